// round 1
// baseline (speedup 1.0000x reference)
#include <cuda_runtime.h>

#define Nv   200000
#define Kk   27
#define Mm   100000
#define Bb   4
#define EPSf 1e-5f

// ---------------- scratch (device globals — no runtime allocation) ----------
__device__ float g_x1[(size_t)Nv * 64];   // conv1 out / normalized
__device__ float g_x2[(size_t)Nv * 64];   // conv2 accum / normalized
__device__ float g_sum1[Bb * 64], g_sq1[Bb * 64];
__device__ float g_sum2[Bb * 64], g_sq2[Bb * 64];
__device__ float g_sum3[Bb * 256], g_sq3[Bb * 256];
__device__ int   g_cnt[Bb];

// ---------------- zero scratch ----------------------------------------------
__global__ void zero_kernel() {
    long long i = (long long)blockIdx.x * blockDim.x + threadIdx.x;
    long long stride = (long long)gridDim.x * blockDim.x;
    const long long total4 = (long long)Nv * 16;   // N*64 floats as float4
    float4* p = reinterpret_cast<float4*>(g_x2);
    float4 z = make_float4(0.f, 0.f, 0.f, 0.f);
    for (long long j = i; j < total4; j += stride) p[j] = z;
    if (i < Bb * 64)  { g_sum1[i] = 0.f; g_sq1[i] = 0.f; g_sum2[i] = 0.f; g_sq2[i] = 0.f; }
    if (i < Bb * 256) { g_sum3[i] = 0.f; g_sq3[i] = 0.f; }
    if (i < Bb) g_cnt[i] = 0;
}

// ---------------- per-batch counts ------------------------------------------
__global__ void count_kernel(const int* __restrict__ batch_idx) {
    __shared__ int s[Bb];
    if (threadIdx.x < Bb) s[threadIdx.x] = 0;
    __syncthreads();
    int i = blockIdx.x * blockDim.x + threadIdx.x;
    int stride = gridDim.x * blockDim.x;
    for (int j = i; j < Nv; j += stride) atomicAdd(&s[batch_idx[j]], 1);
    __syncthreads();
    if (threadIdx.x < Bb) atomicAdd(&g_cnt[threadIdx.x], s[threadIdx.x]);
}

// ---------------- conv1: x1 = feats[N,256] @ W1[256,64] ---------------------
// block: 128 rows x 64 cols, k in chunks of 64; 256 thr, 8x4 micro-tile
__global__ void __launch_bounds__(256) conv1_kernel(const float* __restrict__ feats,
                                                    const float* __restrict__ W1) {
    __shared__ float As[128 * 64];   // 32 KB
    __shared__ float Ws[64 * 64];    // 16 KB
    int t = threadIdx.x;
    int row0 = blockIdx.x * 128;
    int ty = t >> 4;   // 0..15 -> rows ty*8..ty*8+7
    int tx = t & 15;   // cols tx*4
    float acc[8][4];
#pragma unroll
    for (int i = 0; i < 8; i++)
#pragma unroll
        for (int j = 0; j < 4; j++) acc[i][j] = 0.f;

    for (int k0 = 0; k0 < 256; k0 += 64) {
        __syncthreads();
#pragma unroll
        for (int e = t; e < 128 * 64; e += 256) {
            int r = e >> 6, c = e & 63;
            int row = row0 + r;
            As[e] = (row < Nv) ? feats[row * 256 + k0 + c] : 0.f;
        }
#pragma unroll
        for (int e = t; e < 64 * 64; e += 256) {
            Ws[e] = W1[(k0 + (e >> 6)) * 64 + (e & 63)];
        }
        __syncthreads();
#pragma unroll 16
        for (int c = 0; c < 64; c++) {
            float4 w = *(const float4*)&Ws[c * 64 + tx * 4];
#pragma unroll
            for (int i = 0; i < 8; i++) {
                float a = As[(ty * 8 + i) * 64 + c];
                acc[i][0] += a * w.x; acc[i][1] += a * w.y;
                acc[i][2] += a * w.z; acc[i][3] += a * w.w;
            }
        }
    }
#pragma unroll
    for (int i = 0; i < 8; i++) {
        int row = row0 + ty * 8 + i;
        if (row < Nv) {
            float4 v = make_float4(acc[i][0], acc[i][1], acc[i][2], acc[i][3]);
            *(float4*)&g_x1[(size_t)row * 64 + tx * 4] = v;
        }
    }
}

// ---------------- stats: per (batch, channel) sum / sumsq -------------------
// exploits sorted batch_idx: per-thread running sums, smem flush on change
template <int C>
__global__ void __launch_bounds__(256) stats_kernel(const float* __restrict__ x,
                                                    const int* __restrict__ batch_idx,
                                                    float* __restrict__ sumArr,
                                                    float* __restrict__ sqArr,
                                                    int rowsPerBlock) {
    __shared__ float s_sum[Bb * C];
    __shared__ float s_sq[Bb * C];
    int t = threadIdx.x;
    for (int i = t; i < Bb * C; i += 256) { s_sum[i] = 0.f; s_sq[i] = 0.f; }
    __syncthreads();
    constexpr int G = 256 / C;   // row groups per block
    int col = t % C, rg = t / C;
    int r0 = blockIdx.x * rowsPerBlock;
    int r1 = min(r0 + rowsPerBlock, Nv);
    int cb = -1;
    float s = 0.f, q = 0.f;
    for (int r = r0 + rg; r < r1; r += G) {
        int b = batch_idx[r];
        if (b != cb) {
            if (cb >= 0) { atomicAdd(&s_sum[cb * C + col], s); atomicAdd(&s_sq[cb * C + col], q); }
            cb = b; s = 0.f; q = 0.f;
        }
        float v = x[(size_t)r * C + col];
        s += v; q += v * v;
    }
    if (cb >= 0) { atomicAdd(&s_sum[cb * C + col], s); atomicAdd(&s_sq[cb * C + col], q); }
    __syncthreads();
    for (int i = t; i < Bb * C; i += 256) {
        if (s_sum[i] != 0.f) atomicAdd(&sumArr[i], s_sum[i]);
        if (s_sq[i]  != 0.f) atomicAdd(&sqArr[i],  s_sq[i]);
    }
}

// ---------------- finalize stats: sum->mean, sq->rsqrt(var+eps) -------------
__global__ void finalize_kernel(float* sumArr, float* sqArr, int C) {
    int i = blockIdx.x * blockDim.x + threadIdx.x;
    if (i < Bb * C) {
        float cnt = (float)g_cnt[i / C];
        float mean = sumArr[i] / cnt;
        float var = sqArr[i] / cnt - mean * mean;
        sumArr[i] = mean;
        sqArr[i] = rsqrtf(fmaxf(var, 0.f) + EPSf);
    }
}

// ---------------- normalize (+relu), in place --------------------------------
template <int C>
__global__ void norm_relu_kernel(float* __restrict__ x,
                                 const int* __restrict__ batch_idx,
                                 const float* __restrict__ mean,
                                 const float* __restrict__ inv) {
    const int C4 = C / 4;
    long long total = (long long)Nv * C4;
    long long i = (long long)blockIdx.x * blockDim.x + threadIdx.x;
    long long stride = (long long)gridDim.x * blockDim.x;
    for (; i < total; i += stride) {
        int row = (int)(i / C4);
        int cg = (int)(i % C4);
        int b = batch_idx[row];
        float4 v = ((float4*)x)[i];
        float4 m = ((const float4*)mean)[b * C4 + cg];
        float4 sv = ((const float4*)inv)[b * C4 + cg];
        v.x = fmaxf((v.x - m.x) * sv.x, 0.f);
        v.y = fmaxf((v.y - m.y) * sv.y, 0.f);
        v.z = fmaxf((v.z - m.z) * sv.z, 0.f);
        v.w = fmaxf((v.w - m.w) * sv.w, 0.f);
        ((float4*)x)[i] = v;
    }
}

// ---------------- conv2: gather-GEMM-scatter over 27 offsets ----------------
// grid (ceil(M/64), 27); block 256; 64 pairs x 64 out-cols; 4x4 micro-tile
__global__ void __launch_bounds__(256) conv2_kernel(const int* __restrict__ in_idx,
                                                    const int* __restrict__ out_idx,
                                                    const float* __restrict__ W2) {
    __shared__ float Ws[64 * 64];   // 16 KB
    __shared__ float Xs[64 * 64];   // 16 KB
    __shared__ int s_in[64];
    __shared__ int s_out[64];
    int t = threadIdx.x;
    int k = blockIdx.y;
    int base = blockIdx.x * 64;

    const float* W2k = W2 + (size_t)k * 4096;
#pragma unroll
    for (int e = t; e < 4096; e += 256) Ws[e] = W2k[e];

    if (t < 64) {
        int p = base + t;
        s_in[t]  = (p < Mm) ? in_idx[(size_t)k * Mm + p] : -1;
        s_out[t] = (p < Mm) ? out_idx[(size_t)k * Mm + p] : -1;
    }
    __syncthreads();

#pragma unroll
    for (int e = t; e < 64 * 64; e += 256) {
        int r = e >> 6, c = e & 63;
        int src = s_in[r];
        Xs[e] = (src >= 0) ? g_x1[(size_t)src * 64 + c] : 0.f;
    }
    __syncthreads();

    int ty = t >> 4;   // rows ty*4..ty*4+3
    int tx = t & 15;   // cols tx*4
    float acc[4][4];
#pragma unroll
    for (int i = 0; i < 4; i++)
#pragma unroll
        for (int j = 0; j < 4; j++) acc[i][j] = 0.f;

#pragma unroll 16
    for (int c = 0; c < 64; c++) {
        float4 w = *(const float4*)&Ws[c * 64 + tx * 4];
#pragma unroll
        for (int i = 0; i < 4; i++) {
            float a = Xs[(ty * 4 + i) * 64 + c];
            acc[i][0] += a * w.x; acc[i][1] += a * w.y;
            acc[i][2] += a * w.z; acc[i][3] += a * w.w;
        }
    }

#pragma unroll
    for (int i = 0; i < 4; i++) {
        int dst = s_out[ty * 4 + i];
        if (dst >= 0) {
            float* p = &g_x2[(size_t)dst * 64 + tx * 4];
            atomicAdd(p + 0, acc[i][0]);
            atomicAdd(p + 1, acc[i][1]);
            atomicAdd(p + 2, acc[i][2]);
            atomicAdd(p + 3, acc[i][3]);
        }
    }
}

// ---------------- conv3: y = x2n[N,64] @ W3[64,256] -> d_out ----------------
// grid (ceil(N/64), 2 col-halves); block 256; 4x8 micro-tile
__global__ void __launch_bounds__(256) conv3_kernel(const float* __restrict__ W3,
                                                    float* __restrict__ y) {
    __shared__ float Xs[64 * 64];    // 16 KB
    __shared__ float Ws[64 * 128];   // 32 KB
    int t = threadIdx.x;
    int row0 = blockIdx.x * 64;
    int col0 = blockIdx.y * 128;

#pragma unroll
    for (int e = t; e < 64 * 64; e += 256) {
        int r = e >> 6, c = e & 63;
        int row = row0 + r;
        Xs[e] = (row < Nv) ? g_x2[(size_t)row * 64 + c] : 0.f;
    }
#pragma unroll
    for (int e = t; e < 64 * 128; e += 256) {
        int c = e >> 7, d = e & 127;
        Ws[e] = W3[c * 256 + col0 + d];
    }
    __syncthreads();

    int ty = t >> 4;   // rows ty*4
    int tx = t & 15;   // cols tx*8
    float acc[4][8];
#pragma unroll
    for (int i = 0; i < 4; i++)
#pragma unroll
        for (int j = 0; j < 8; j++) acc[i][j] = 0.f;

#pragma unroll 16
    for (int c = 0; c < 64; c++) {
        float4 w0 = *(const float4*)&Ws[c * 128 + tx * 8];
        float4 w1 = *(const float4*)&Ws[c * 128 + tx * 8 + 4];
#pragma unroll
        for (int i = 0; i < 4; i++) {
            float a = Xs[(ty * 4 + i) * 64 + c];
            acc[i][0] += a * w0.x; acc[i][1] += a * w0.y;
            acc[i][2] += a * w0.z; acc[i][3] += a * w0.w;
            acc[i][4] += a * w1.x; acc[i][5] += a * w1.y;
            acc[i][6] += a * w1.z; acc[i][7] += a * w1.w;
        }
    }

#pragma unroll
    for (int i = 0; i < 4; i++) {
        int row = row0 + ty * 4 + i;
        if (row < Nv) {
            float4 v0 = make_float4(acc[i][0], acc[i][1], acc[i][2], acc[i][3]);
            float4 v1 = make_float4(acc[i][4], acc[i][5], acc[i][6], acc[i][7]);
            *(float4*)&y[(size_t)row * 256 + col0 + tx * 8]     = v0;
            *(float4*)&y[(size_t)row * 256 + col0 + tx * 8 + 4] = v1;
        }
    }
}

// ---------------- final: normalize3 + residual + relu, in place -------------
__global__ void final_kernel(float* __restrict__ y,
                             const float* __restrict__ feats,
                             const int* __restrict__ batch_idx,
                             const float* __restrict__ mean,
                             const float* __restrict__ inv) {
    const int C4 = 64;   // 256/4
    long long total = (long long)Nv * C4;
    long long i = (long long)blockIdx.x * blockDim.x + threadIdx.x;
    long long stride = (long long)gridDim.x * blockDim.x;
    for (; i < total; i += stride) {
        int row = (int)(i / C4);
        int cg = (int)(i % C4);
        int b = batch_idx[row];
        float4 v = ((float4*)y)[i];
        float4 f = ((const float4*)feats)[i];
        float4 m = ((const float4*)mean)[b * C4 + cg];
        float4 sv = ((const float4*)inv)[b * C4 + cg];
        v.x = fmaxf((v.x - m.x) * sv.x + f.x, 0.f);
        v.y = fmaxf((v.y - m.y) * sv.y + f.y, 0.f);
        v.z = fmaxf((v.z - m.z) * sv.z + f.z, 0.f);
        v.w = fmaxf((v.w - m.w) * sv.w + f.w, 0.f);
        ((float4*)y)[i] = v;
    }
}

// ---------------- launch -----------------------------------------------------
extern "C" void kernel_launch(void* const* d_in, const int* in_sizes, int n_in,
                              void* d_out, int out_size) {
    const float* feats     = (const float*)d_in[0];
    const float* W1        = (const float*)d_in[1];
    const float* W2        = (const float*)d_in[2];
    const float* W3        = (const float*)d_in[3];
    const int*   in_idx    = (const int*)d_in[4];
    const int*   out_idx   = (const int*)d_in[5];
    const int*   batch_idx = (const int*)d_in[6];
    float* out = (float*)d_out;

    float *p_x1, *p_x2, *p_sum1, *p_sq1, *p_sum2, *p_sq2, *p_sum3, *p_sq3;
    cudaGetSymbolAddress((void**)&p_x1, g_x1);
    cudaGetSymbolAddress((void**)&p_x2, g_x2);
    cudaGetSymbolAddress((void**)&p_sum1, g_sum1);
    cudaGetSymbolAddress((void**)&p_sq1, g_sq1);
    cudaGetSymbolAddress((void**)&p_sum2, g_sum2);
    cudaGetSymbolAddress((void**)&p_sq2, g_sq2);
    cudaGetSymbolAddress((void**)&p_sum3, g_sum3);
    cudaGetSymbolAddress((void**)&p_sq3, g_sq3);

    zero_kernel<<<2048, 256>>>();
    count_kernel<<<296, 256>>>(batch_idx);

    // conv1 + IN + relu
    conv1_kernel<<<(Nv + 127) / 128, 256>>>(feats, W1);
    stats_kernel<64><<<(Nv + 511) / 512, 256>>>(p_x1, batch_idx, p_sum1, p_sq1, 512);
    finalize_kernel<<<1, 256>>>(p_sum1, p_sq1, 64);
    norm_relu_kernel<64><<<12544, 256>>>(p_x1, batch_idx, p_sum1, p_sq1);

    // conv2 (sparse 3x3x3) + IN + relu
    dim3 g2((Mm + 63) / 64, Kk);
    conv2_kernel<<<g2, 256>>>(in_idx, out_idx, W2);
    stats_kernel<64><<<(Nv + 511) / 512, 256>>>(p_x2, batch_idx, p_sum2, p_sq2, 512);
    finalize_kernel<<<1, 256>>>(p_sum2, p_sq2, 64);
    norm_relu_kernel<64><<<12544, 256>>>(p_x2, batch_idx, p_sum2, p_sq2);

    // conv3 + IN + residual + relu
    dim3 g3((Nv + 63) / 64, 2);
    conv3_kernel<<<g3, 256>>>(W3, out);
    stats_kernel<256><<<(Nv + 255) / 256, 256>>>(out, batch_idx, p_sum3, p_sq3, 256);
    finalize_kernel<<<4, 256>>>(p_sum3, p_sq3, 256);
    final_kernel<<<16384, 256>>>(out, feats, batch_idx, p_sum3, p_sq3);
}

// round 2
// speedup vs baseline: 1.0659x; 1.0659x over previous
#include <cuda_runtime.h>

#define Nv   200000
#define Kk   27
#define Mm   100000
#define Bb   4
#define EPSf 1e-5f

// ---------------- scratch (device globals — no runtime allocation) ----------
__device__ float g_x1[(size_t)Nv * 64];   // conv1 out (raw, pre-norm)
__device__ float g_x2[(size_t)Nv * 64];   // conv2 accum (raw, pre-norm)
__device__ float g_sum1[Bb * 64], g_sq1[Bb * 64];
__device__ float g_sum2[Bb * 64], g_sq2[Bb * 64];
__device__ float g_sum3[Bb * 256], g_sq3[Bb * 256];
__device__ int   g_cnt[Bb];

// ---------------- f32x2 packed helpers --------------------------------------
__device__ __forceinline__ void fma2(unsigned long long& d, unsigned long long a,
                                     unsigned long long b) {
    asm("fma.rn.f32x2 %0, %1, %2, %0;" : "+l"(d) : "l"(a), "l"(b));
}
__device__ __forceinline__ unsigned long long dup2(float a) {
    unsigned long long r;
    asm("mov.b64 %0, {%1, %1};" : "=l"(r) : "f"(a));
    return r;
}
__device__ __forceinline__ float2 unpack2(unsigned long long v) {
    float2 r;
    asm("mov.b64 {%0, %1}, %2;" : "=f"(r.x), "=f"(r.y) : "l"(v));
    return r;
}
__device__ __forceinline__ void red_v4(float* p, float a, float b, float c, float d) {
    asm volatile("red.global.add.v4.f32 [%0], {%1,%2,%3,%4};"
                 :: "l"(p), "f"(a), "f"(b), "f"(c), "f"(d) : "memory");
}

// ---------------- zero scratch ----------------------------------------------
__global__ void zero_kernel() {
    long long i = (long long)blockIdx.x * blockDim.x + threadIdx.x;
    long long stride = (long long)gridDim.x * blockDim.x;
    const long long total4 = (long long)Nv * 16;
    float4* p = reinterpret_cast<float4*>(g_x2);
    float4 z = make_float4(0.f, 0.f, 0.f, 0.f);
    for (long long j = i; j < total4; j += stride) p[j] = z;
    if (i < Bb * 64)  { g_sum1[i] = 0.f; g_sq1[i] = 0.f; g_sum2[i] = 0.f; g_sq2[i] = 0.f; }
    if (i < Bb * 256) { g_sum3[i] = 0.f; g_sq3[i] = 0.f; }
    if (i < Bb) g_cnt[i] = 0;
}

// ---------------- per-batch counts ------------------------------------------
__global__ void count_kernel(const int* __restrict__ batch_idx) {
    __shared__ int s[Bb];
    if (threadIdx.x < Bb) s[threadIdx.x] = 0;
    __syncthreads();
    int i = blockIdx.x * blockDim.x + threadIdx.x;
    int stride = gridDim.x * blockDim.x;
    for (int j = i; j < Nv; j += stride) atomicAdd(&s[batch_idx[j]], 1);
    __syncthreads();
    if (threadIdx.x < Bb) atomicAdd(&g_cnt[threadIdx.x], s[threadIdx.x]);
}

// ---------------- conv1: x1 = feats[N,256] @ W1[256,64], fused stats1 -------
// tile 128 rows x 64 cols, 4 k-chunks of 64; 256 thr; micro 4x8 via f32x2
__global__ void __launch_bounds__(256) conv1_kernel(const float* __restrict__ feats,
                                                    const float* __restrict__ W1,
                                                    const int* __restrict__ batch_idx,
                                                    float* __restrict__ gsum,
                                                    float* __restrict__ gsq) {
    extern __shared__ __align__(16) float smem[];
    float* As = smem;               // 128 x 68 = 8704 floats
    float* Ws = smem + 8704;        // 64 x 64 = 4096 floats
    int*   s_b = (int*)&smem[12800];

    int t = threadIdx.x;
    int row0 = blockIdx.x * 128;
    if (t < 128) {
        int r = row0 + t;
        s_b[t] = (r < Nv) ? batch_idx[r] : -1;
    }

    int ty = t >> 3;   // 0..31 -> rows ty*4..
    int tx = t & 7;    // cols tx*8..
    unsigned long long acc[4][4];
#pragma unroll
    for (int i = 0; i < 4; i++)
#pragma unroll
        for (int j = 0; j < 4; j++) acc[i][j] = 0ull;

    for (int k0 = 0; k0 < 256; k0 += 64) {
        __syncthreads();
#pragma unroll
        for (int e4 = t; e4 < 128 * 16; e4 += 256) {
            int r = e4 >> 4, cg = e4 & 15;
            int row = row0 + r;
            float4 v = make_float4(0.f, 0.f, 0.f, 0.f);
            if (row < Nv) v = *(const float4*)&feats[(size_t)row * 256 + k0 + cg * 4];
            *(float4*)&As[r * 68 + cg * 4] = v;
        }
#pragma unroll
        for (int e4 = t; e4 < 1024; e4 += 256)
            ((float4*)Ws)[e4] = ((const float4*)(W1 + (size_t)k0 * 64))[e4];
        __syncthreads();

#pragma unroll 2
        for (int c0 = 0; c0 < 64; c0 += 4) {
            float4 av[4];
#pragma unroll
            for (int i = 0; i < 4; i++) av[i] = *(const float4*)&As[(ty * 4 + i) * 68 + c0];
#pragma unroll
            for (int cc = 0; cc < 4; cc++) {
                const ulonglong2 wA = *(const ulonglong2*)&Ws[(c0 + cc) * 64 + tx * 8];
                const ulonglong2 wB = *(const ulonglong2*)&Ws[(c0 + cc) * 64 + tx * 8 + 4];
#pragma unroll
                for (int i = 0; i < 4; i++) {
                    float a = (cc == 0) ? av[i].x : (cc == 1) ? av[i].y : (cc == 2) ? av[i].z : av[i].w;
                    unsigned long long aa = dup2(a);
                    fma2(acc[i][0], aa, wA.x);
                    fma2(acc[i][1], aa, wA.y);
                    fma2(acc[i][2], aa, wB.x);
                    fma2(acc[i][3], aa, wB.y);
                }
            }
        }
    }

    // store raw x1
#pragma unroll
    for (int i = 0; i < 4; i++) {
        int row = row0 + ty * 4 + i;
        if (row < Nv) {
            *(ulonglong2*)&g_x1[(size_t)row * 64 + tx * 8]     = make_ulonglong2(acc[i][0], acc[i][1]);
            *(ulonglong2*)&g_x1[(size_t)row * 64 + tx * 8 + 4] = make_ulonglong2(acc[i][2], acc[i][3]);
        }
    }

    // fused stats1
    __syncthreads();   // done with As -> reuse as reduction buffer
    int b0 = s_b[0];
    bool fast = (s_b[127] == b0);
    float* red = As;   // sum [0,2048), sq [2048,4096)
    if (fast) {
        float ss[8], qq[8];
#pragma unroll
        for (int j = 0; j < 8; j++) { ss[j] = 0.f; qq[j] = 0.f; }
#pragma unroll
        for (int i = 0; i < 4; i++)
#pragma unroll
            for (int jp = 0; jp < 4; jp++) {
                float2 p = unpack2(acc[i][jp]);
                ss[2 * jp] += p.x;     qq[2 * jp] += p.x * p.x;
                ss[2 * jp + 1] += p.y; qq[2 * jp + 1] += p.y * p.y;
            }
        *(float4*)&red[ty * 64 + tx * 8]          = make_float4(ss[0], ss[1], ss[2], ss[3]);
        *(float4*)&red[ty * 64 + tx * 8 + 4]      = make_float4(ss[4], ss[5], ss[6], ss[7]);
        *(float4*)&red[2048 + ty * 64 + tx * 8]     = make_float4(qq[0], qq[1], qq[2], qq[3]);
        *(float4*)&red[2048 + ty * 64 + tx * 8 + 4] = make_float4(qq[4], qq[5], qq[6], qq[7]);
        __syncthreads();
        if (t < 64) {
            float s = 0.f;
#pragma unroll
            for (int u = 0; u < 32; u++) s += red[u * 64 + t];
            atomicAdd(&gsum[b0 * 64 + t], s);
        } else if (t < 128) {
            int c = t - 64;
            float s = 0.f;
#pragma unroll
            for (int u = 0; u < 32; u++) s += red[2048 + u * 64 + c];
            atomicAdd(&gsq[b0 * 64 + c], s);
        }
    } else {
#pragma unroll
        for (int i = 0; i < 4; i++) {
            int r = row0 + ty * 4 + i;
            if (r < Nv) {
                int b = s_b[ty * 4 + i];
#pragma unroll
                for (int jp = 0; jp < 4; jp++) {
                    float2 p = unpack2(acc[i][jp]);
                    atomicAdd(&gsum[b * 64 + tx * 8 + 2 * jp], p.x);
                    atomicAdd(&gsum[b * 64 + tx * 8 + 2 * jp + 1], p.y);
                    atomicAdd(&gsq[b * 64 + tx * 8 + 2 * jp], p.x * p.x);
                    atomicAdd(&gsq[b * 64 + tx * 8 + 2 * jp + 1], p.y * p.y);
                }
            }
        }
    }
}

// ---------------- finalize stats: sum->mean, sq->rsqrt(var+eps) -------------
__global__ void finalize_kernel(float* sumArr, float* sqArr, int C) {
    int i = blockIdx.x * blockDim.x + threadIdx.x;
    if (i < Bb * C) {
        float cnt = (float)g_cnt[i / C];
        float mean = sumArr[i] / cnt;
        float var = sqArr[i] / cnt - mean * mean;
        sumArr[i] = mean;
        sqArr[i] = rsqrtf(fmaxf(var, 0.f) + EPSf);
    }
}

// ---------------- conv2: gather(norm1+relu) -> GEMM -> red.v4 scatter -------
// grid (ceil(M/128), 27); 256 thr; tile 128 pairs x 64 cols; micro 4x8 f32x2
__global__ void __launch_bounds__(256) conv2_kernel(const int* __restrict__ in_idx,
                                                    const int* __restrict__ out_idx,
                                                    const float* __restrict__ W2,
                                                    const int* __restrict__ batch_idx,
                                                    const float* __restrict__ mean1,
                                                    const float* __restrict__ inv1) {
    extern __shared__ __align__(16) float smem[];
    float* Xs   = smem;                 // 128 x 68
    float* Ws   = smem + 8704;          // 64 x 64
    float* sm_m = smem + 12800;         // 256
    float* sm_i = smem + 13056;         // 256
    int*   s_in  = (int*)&smem[13312];  // 128
    int*   s_out = (int*)&smem[13440];  // 128
    int*   s_b   = (int*)&smem[13568];  // 128

    int t = threadIdx.x;
    int k = blockIdx.y;
    int base = blockIdx.x * 128;

    if (t < 128) {
        int p = base + t;
        int src = (p < Mm) ? in_idx[(size_t)k * Mm + p] : -1;
        s_in[t]  = src;
        s_out[t] = (p < Mm) ? out_idx[(size_t)k * Mm + p] : -1;
        s_b[t]   = (src >= 0) ? batch_idx[src] : 0;
    }
    if (t < 256) { sm_m[t] = mean1[t]; sm_i[t] = inv1[t]; }
    const float* W2k = W2 + (size_t)k * 4096;
#pragma unroll
    for (int e4 = t; e4 < 1024; e4 += 256)
        ((float4*)Ws)[e4] = ((const float4*)W2k)[e4];
    __syncthreads();

    // gather + norm1 + relu
#pragma unroll
    for (int e = t; e < 128 * 16; e += 256) {
        int r = e >> 4, cg = e & 15;
        int src = s_in[r];
        float4 v = make_float4(0.f, 0.f, 0.f, 0.f);
        if (src >= 0) {
            float4 x = *(const float4*)&g_x1[(size_t)src * 64 + cg * 4];
            int b = s_b[r];
            float4 m = *(const float4*)&sm_m[b * 64 + cg * 4];
            float4 iv = *(const float4*)&sm_i[b * 64 + cg * 4];
            v.x = fmaxf((x.x - m.x) * iv.x, 0.f);
            v.y = fmaxf((x.y - m.y) * iv.y, 0.f);
            v.z = fmaxf((x.z - m.z) * iv.z, 0.f);
            v.w = fmaxf((x.w - m.w) * iv.w, 0.f);
        }
        *(float4*)&Xs[r * 68 + cg * 4] = v;
    }
    __syncthreads();

    int ty = t >> 3;
    int tx = t & 7;
    unsigned long long acc[4][4];
#pragma unroll
    for (int i = 0; i < 4; i++)
#pragma unroll
        for (int j = 0; j < 4; j++) acc[i][j] = 0ull;

#pragma unroll 2
    for (int c0 = 0; c0 < 64; c0 += 4) {
        float4 av[4];
#pragma unroll
        for (int i = 0; i < 4; i++) av[i] = *(const float4*)&Xs[(ty * 4 + i) * 68 + c0];
#pragma unroll
        for (int cc = 0; cc < 4; cc++) {
            const ulonglong2 wA = *(const ulonglong2*)&Ws[(c0 + cc) * 64 + tx * 8];
            const ulonglong2 wB = *(const ulonglong2*)&Ws[(c0 + cc) * 64 + tx * 8 + 4];
#pragma unroll
            for (int i = 0; i < 4; i++) {
                float a = (cc == 0) ? av[i].x : (cc == 1) ? av[i].y : (cc == 2) ? av[i].z : av[i].w;
                unsigned long long aa = dup2(a);
                fma2(acc[i][0], aa, wA.x);
                fma2(acc[i][1], aa, wA.y);
                fma2(acc[i][2], aa, wB.x);
                fma2(acc[i][3], aa, wB.y);
            }
        }
    }

    // scatter via vectorized reductions
#pragma unroll
    for (int i = 0; i < 4; i++) {
        int dst = s_out[ty * 4 + i];
        if (dst >= 0) {
            float2 p0 = unpack2(acc[i][0]);
            float2 p1 = unpack2(acc[i][1]);
            float2 p2 = unpack2(acc[i][2]);
            float2 p3 = unpack2(acc[i][3]);
            float* ptr = &g_x2[(size_t)dst * 64 + tx * 8];
            red_v4(ptr,     p0.x, p0.y, p1.x, p1.y);
            red_v4(ptr + 4, p2.x, p2.y, p3.x, p3.y);
        }
    }
}

// ---------------- stats2: per (batch, channel) sum/sumsq over x2 ------------
__global__ void __launch_bounds__(256) stats2_kernel(const float* __restrict__ x,
                                                     const int* __restrict__ batch_idx,
                                                     float* __restrict__ gsum,
                                                     float* __restrict__ gsq) {
    __shared__ float sm[2048];  // fast: [rg][64] sum + sq; slow: [b][64] sum + sq
    int t = threadIdx.x;
    int r0 = blockIdx.x * 128;
    int r1 = min(r0 + 128, Nv);
    int cg = t & 15, rg = t >> 4;
    int b0 = batch_idx[r0], b1 = batch_idx[r1 - 1];

    if (b0 == b1) {
        float4 s = make_float4(0.f, 0.f, 0.f, 0.f);
        float4 q = make_float4(0.f, 0.f, 0.f, 0.f);
#pragma unroll 4
        for (int r = r0 + rg; r < r1; r += 16) {
            float4 v = *(const float4*)&x[(size_t)r * 64 + cg * 4];
            s.x += v.x; s.y += v.y; s.z += v.z; s.w += v.w;
            q.x += v.x * v.x; q.y += v.y * v.y; q.z += v.z * v.z; q.w += v.w * v.w;
        }
        *(float4*)&sm[rg * 64 + cg * 4]        = s;
        *(float4*)&sm[1024 + rg * 64 + cg * 4] = q;
        __syncthreads();
        if (t < 64) {
            float v = 0.f;
#pragma unroll
            for (int u = 0; u < 16; u++) v += sm[u * 64 + t];
            atomicAdd(&gsum[b0 * 64 + t], v);
        } else if (t < 128) {
            int c = t - 64;
            float v = 0.f;
#pragma unroll
            for (int u = 0; u < 16; u++) v += sm[1024 + u * 64 + c];
            atomicAdd(&gsq[b0 * 64 + c], v);
        }
    } else {
        for (int i = t; i < 512; i += 256) sm[i] = 0.f;
        __syncthreads();
        for (int r = r0 + rg; r < r1; r += 16) {
            int b = batch_idx[r];
            float4 v = *(const float4*)&x[(size_t)r * 64 + cg * 4];
            atomicAdd(&sm[b * 64 + cg * 4], v.x);
            atomicAdd(&sm[b * 64 + cg * 4 + 1], v.y);
            atomicAdd(&sm[b * 64 + cg * 4 + 2], v.z);
            atomicAdd(&sm[b * 64 + cg * 4 + 3], v.w);
            atomicAdd(&sm[256 + b * 64 + cg * 4], v.x * v.x);
            atomicAdd(&sm[256 + b * 64 + cg * 4 + 1], v.y * v.y);
            atomicAdd(&sm[256 + b * 64 + cg * 4 + 2], v.z * v.z);
            atomicAdd(&sm[256 + b * 64 + cg * 4 + 3], v.w * v.w);
        }
        __syncthreads();
        if (t < 256) {
            if (sm[t] != 0.f)       atomicAdd(&gsum[t], sm[t]);
            if (sm[256 + t] != 0.f) atomicAdd(&gsq[t], sm[256 + t]);
        }
    }
}

// ---------------- conv3: gather(norm2+relu) -> GEMM -> out, fused stats3 ----
// grid (ceil(N/128), 2); 256 thr; tile 128 rows x 128 cols; micro 4x16 f32x2
__global__ void __launch_bounds__(256) conv3_kernel(const float* __restrict__ W3,
                                                    float* __restrict__ out,
                                                    const int* __restrict__ batch_idx,
                                                    const float* __restrict__ mean2,
                                                    const float* __restrict__ inv2,
                                                    float* __restrict__ gsum,
                                                    float* __restrict__ gsq) {
    extern __shared__ __align__(16) float smem[];
    float* Xs   = smem;                 // 128 x 68 = 8704
    float* Ws   = smem + 8704;          // 64 x 128 = 8192
    float* sm_m = smem + 16896;         // 256
    float* sm_i = smem + 17152;         // 256
    int*   s_b  = (int*)&smem[17408];   // 128

    int t = threadIdx.x;
    int row0 = blockIdx.x * 128;
    int col0 = blockIdx.y * 128;

    if (t < 128) {
        int r = row0 + t;
        s_b[t] = (r < Nv) ? batch_idx[r] : -1;
    }
    if (t < 256) { sm_m[t] = mean2[t]; sm_i[t] = inv2[t]; }
#pragma unroll
    for (int e4 = t; e4 < 2048; e4 += 256) {
        int c = e4 >> 5, d4 = e4 & 31;
        ((float4*)Ws)[e4] = *(const float4*)&W3[c * 256 + col0 + d4 * 4];
    }
    __syncthreads();

    // gather + norm2 + relu
#pragma unroll
    for (int e = t; e < 128 * 16; e += 256) {
        int r = e >> 4, cg = e & 15;
        int row = row0 + r;
        float4 v = make_float4(0.f, 0.f, 0.f, 0.f);
        if (row < Nv) {
            float4 x = *(const float4*)&g_x2[(size_t)row * 64 + cg * 4];
            int b = s_b[r];
            float4 m = *(const float4*)&sm_m[b * 64 + cg * 4];
            float4 iv = *(const float4*)&sm_i[b * 64 + cg * 4];
            v.x = fmaxf((x.x - m.x) * iv.x, 0.f);
            v.y = fmaxf((x.y - m.y) * iv.y, 0.f);
            v.z = fmaxf((x.z - m.z) * iv.z, 0.f);
            v.w = fmaxf((x.w - m.w) * iv.w, 0.f);
        }
        *(float4*)&Xs[r * 68 + cg * 4] = v;
    }
    __syncthreads();

    int ty = t >> 3;   // 0..31 rows*4
    int tx = t & 7;    // cols tx*16
    unsigned long long acc[4][8];
#pragma unroll
    for (int i = 0; i < 4; i++)
#pragma unroll
        for (int j = 0; j < 8; j++) acc[i][j] = 0ull;

#pragma unroll 2
    for (int c0 = 0; c0 < 64; c0 += 4) {
        float4 av[4];
#pragma unroll
        for (int i = 0; i < 4; i++) av[i] = *(const float4*)&Xs[(ty * 4 + i) * 68 + c0];
#pragma unroll
        for (int cc = 0; cc < 4; cc++) {
            const float* wrow = &Ws[(c0 + cc) * 128 + tx * 16];
            const ulonglong2 w0 = *(const ulonglong2*)(wrow);
            const ulonglong2 w1 = *(const ulonglong2*)(wrow + 4);
            const ulonglong2 w2 = *(const ulonglong2*)(wrow + 8);
            const ulonglong2 w3 = *(const ulonglong2*)(wrow + 12);
#pragma unroll
            for (int i = 0; i < 4; i++) {
                float a = (cc == 0) ? av[i].x : (cc == 1) ? av[i].y : (cc == 2) ? av[i].z : av[i].w;
                unsigned long long aa = dup2(a);
                fma2(acc[i][0], aa, w0.x); fma2(acc[i][1], aa, w0.y);
                fma2(acc[i][2], aa, w1.x); fma2(acc[i][3], aa, w1.y);
                fma2(acc[i][4], aa, w2.x); fma2(acc[i][5], aa, w2.y);
                fma2(acc[i][6], aa, w3.x); fma2(acc[i][7], aa, w3.y);
            }
        }
    }

    __syncthreads();   // done with Ws -> reuse as reduction buffer
    int b0 = s_b[0];
    bool fast = (s_b[127] == b0);
    float* red = Ws;   // sum [0,4096), sq [4096,8192)

    float ss[16], qq[16];
#pragma unroll
    for (int j = 0; j < 16; j++) { ss[j] = 0.f; qq[j] = 0.f; }

#pragma unroll
    for (int i = 0; i < 4; i++) {
        float v[16];
#pragma unroll
        for (int jp = 0; jp < 8; jp++) {
            float2 p = unpack2(acc[i][jp]);
            v[2 * jp] = p.x; v[2 * jp + 1] = p.y;
        }
        int row = row0 + ty * 4 + i;
        if (row < Nv) {
            float* o = &out[(size_t)row * 256 + col0 + tx * 16];
            *(float4*)(o)      = make_float4(v[0], v[1], v[2], v[3]);
            *(float4*)(o + 4)  = make_float4(v[4], v[5], v[6], v[7]);
            *(float4*)(o + 8)  = make_float4(v[8], v[9], v[10], v[11]);
            *(float4*)(o + 12) = make_float4(v[12], v[13], v[14], v[15]);
        }
        if (fast) {
#pragma unroll
            for (int j = 0; j < 16; j++) { ss[j] += v[j]; qq[j] += v[j] * v[j]; }
        } else if (row < Nv) {
            int b = s_b[ty * 4 + i];
#pragma unroll
            for (int j = 0; j < 16; j++) {
                atomicAdd(&gsum[b * 256 + col0 + tx * 16 + j], v[j]);
                atomicAdd(&gsq[b * 256 + col0 + tx * 16 + j], v[j] * v[j]);
            }
        }
    }

    if (fast) {
#pragma unroll
        for (int u = 0; u < 4; u++) {
            *(float4*)&red[ty * 128 + tx * 16 + u * 4] =
                make_float4(ss[u * 4], ss[u * 4 + 1], ss[u * 4 + 2], ss[u * 4 + 3]);
            *(float4*)&red[4096 + ty * 128 + tx * 16 + u * 4] =
                make_float4(qq[u * 4], qq[u * 4 + 1], qq[u * 4 + 2], qq[u * 4 + 3]);
        }
        __syncthreads();
        if (t < 128) {
            float s = 0.f;
#pragma unroll
            for (int u = 0; u < 32; u++) s += red[u * 128 + t];
            atomicAdd(&gsum[b0 * 256 + col0 + t], s);
        } else {
            int c = t - 128;
            float s = 0.f;
#pragma unroll
            for (int u = 0; u < 32; u++) s += red[4096 + u * 128 + c];
            atomicAdd(&gsq[b0 * 256 + col0 + c], s);
        }
    }
}

// ---------------- final: normalize3 + residual + relu, in place -------------
__global__ void final_kernel(float* __restrict__ y,
                             const float* __restrict__ feats,
                             const int* __restrict__ batch_idx,
                             const float* __restrict__ mean,
                             const float* __restrict__ inv) {
    const int C4 = 64;
    long long total = (long long)Nv * C4;
    long long i = (long long)blockIdx.x * blockDim.x + threadIdx.x;
    long long stride = (long long)gridDim.x * blockDim.x;
    for (; i < total; i += stride) {
        int row = (int)(i / C4);
        int cg = (int)(i % C4);
        int b = batch_idx[row];
        float4 v = ((float4*)y)[i];
        float4 f = ((const float4*)feats)[i];
        float4 m = ((const float4*)mean)[b * C4 + cg];
        float4 sv = ((const float4*)inv)[b * C4 + cg];
        v.x = fmaxf((v.x - m.x) * sv.x + f.x, 0.f);
        v.y = fmaxf((v.y - m.y) * sv.y + f.y, 0.f);
        v.z = fmaxf((v.z - m.z) * sv.z + f.z, 0.f);
        v.w = fmaxf((v.w - m.w) * sv.w + f.w, 0.f);
        ((float4*)y)[i] = v;
    }
}

// ---------------- launch -----------------------------------------------------
extern "C" void kernel_launch(void* const* d_in, const int* in_sizes, int n_in,
                              void* d_out, int out_size) {
    const float* feats     = (const float*)d_in[0];
    const float* W1        = (const float*)d_in[1];
    const float* W2        = (const float*)d_in[2];
    const float* W3        = (const float*)d_in[3];
    const int*   in_idx    = (const int*)d_in[4];
    const int*   out_idx   = (const int*)d_in[5];
    const int*   batch_idx = (const int*)d_in[6];
    float* out = (float*)d_out;

    float *p_x2, *p_sum1, *p_sq1, *p_sum2, *p_sq2, *p_sum3, *p_sq3;
    cudaGetSymbolAddress((void**)&p_x2, g_x2);
    cudaGetSymbolAddress((void**)&p_sum1, g_sum1);
    cudaGetSymbolAddress((void**)&p_sq1, g_sq1);
    cudaGetSymbolAddress((void**)&p_sum2, g_sum2);
    cudaGetSymbolAddress((void**)&p_sq2, g_sq2);
    cudaGetSymbolAddress((void**)&p_sum3, g_sum3);
    cudaGetSymbolAddress((void**)&p_sq3, g_sq3);

    const int smem1 = 51712;
    const int smem2 = 54784;
    const int smem3 = 70144;
    cudaFuncSetAttribute(conv1_kernel, cudaFuncAttributeMaxDynamicSharedMemorySize, smem1);
    cudaFuncSetAttribute(conv2_kernel, cudaFuncAttributeMaxDynamicSharedMemorySize, smem2);
    cudaFuncSetAttribute(conv3_kernel, cudaFuncAttributeMaxDynamicSharedMemorySize, smem3);

    zero_kernel<<<2048, 256>>>();
    count_kernel<<<391, 256>>>(batch_idx);

    // conv1 + fused stats1
    conv1_kernel<<<(Nv + 127) / 128, 256, smem1>>>(feats, W1, batch_idx, p_sum1, p_sq1);
    finalize_kernel<<<1, 256>>>(p_sum1, p_sq1, 64);

    // conv2 (norm1+relu fused in gather) + red.v4 scatter
    dim3 g2((Mm + 127) / 128, Kk);
    conv2_kernel<<<g2, 256, smem2>>>(in_idx, out_idx, W2, batch_idx, p_sum1, p_sq1);
    stats2_kernel<<<(Nv + 127) / 128, 256>>>(p_x2, batch_idx, p_sum2, p_sq2);
    finalize_kernel<<<1, 256>>>(p_sum2, p_sq2, 64);

    // conv3 (norm2+relu fused in gather) + fused stats3
    dim3 g3((Nv + 127) / 128, 2);
    conv3_kernel<<<g3, 256, smem3>>>(W3, out, batch_idx, p_sum2, p_sq2, p_sum3, p_sq3);
    finalize_kernel<<<4, 256>>>(p_sum3, p_sq3, 256);

    // normalize3 + residual + relu
    final_kernel<<<16384, 256>>>(out, feats, batch_idx, p_sum3, p_sq3);
}

// round 4
// speedup vs baseline: 1.2445x; 1.1676x over previous
#include <cuda_runtime.h>
#include <cuda_bf16.h>
#include <cstdint>

#define Nv   200000
#define Kk   27
#define Mm   100000
#define Bb   4
#define EPSf 1e-5f

// ---------------- scratch (device globals — no runtime allocation) ----------
__device__ float g_x1[(size_t)Nv * 64];          // conv1 out (raw, pre-norm)
__device__ float g_x2[(size_t)Nv * 64];          // conv2 accum (raw, pre-norm)
__device__ __nv_bfloat16 g_x1h[(size_t)Nv * 64]; // normalized x1, bf16 hi
__device__ __nv_bfloat16 g_x1l[(size_t)Nv * 64]; // normalized x1, bf16 lo
__device__ float g_sum1[Bb * 64], g_sq1[Bb * 64];
__device__ float g_sum2[Bb * 64], g_sq2[Bb * 64];
__device__ float g_sum3[Bb * 256], g_sq3[Bb * 256];
__device__ int   g_cnt[Bb];

// ---------------- f32x2 packed helpers (conv1/conv3 SIMT path) --------------
__device__ __forceinline__ void fma2(unsigned long long& d, unsigned long long a,
                                     unsigned long long b) {
    asm("fma.rn.f32x2 %0, %1, %2, %0;" : "+l"(d) : "l"(a), "l"(b));
}
__device__ __forceinline__ unsigned long long dup2(float a) {
    unsigned long long r;
    asm("mov.b64 %0, {%1, %1};" : "=l"(r) : "f"(a));
    return r;
}
__device__ __forceinline__ float2 unpack2(unsigned long long v) {
    float2 r;
    asm("mov.b64 {%0, %1}, %2;" : "=f"(r.x), "=f"(r.y) : "l"(v));
    return r;
}
__device__ __forceinline__ void red_v4(float* p, float a, float b, float c, float d) {
    asm volatile("red.global.add.v4.f32 [%0], {%1,%2,%3,%4};"
                 :: "l"(p), "f"(a), "f"(b), "f"(c), "f"(d) : "memory");
}

// ---------------- mma.sync / ldmatrix helpers --------------------------------
__device__ __forceinline__ uint32_t smem_u32(const void* p) {
    uint32_t a;
    asm("{ .reg .u64 t; cvta.to.shared.u64 t, %1; cvt.u32.u64 %0, t; }"
        : "=r"(a) : "l"(p));
    return a;
}
__device__ __forceinline__ void ldsm_x4(uint32_t* r, uint32_t addr) {
    asm volatile("ldmatrix.sync.aligned.m8n8.x4.shared.b16 {%0,%1,%2,%3}, [%4];"
        : "=r"(r[0]), "=r"(r[1]), "=r"(r[2]), "=r"(r[3]) : "r"(addr));
}
__device__ __forceinline__ void mma_bf16(float* c, const uint32_t* a,
                                         uint32_t b0, uint32_t b1) {
    asm volatile("mma.sync.aligned.m16n8k16.row.col.f32.bf16.bf16.f32 "
        "{%0,%1,%2,%3}, {%4,%5,%6,%7}, {%8,%9}, {%0,%1,%2,%3};"
        : "+f"(c[0]), "+f"(c[1]), "+f"(c[2]), "+f"(c[3])
        : "r"(a[0]), "r"(a[1]), "r"(a[2]), "r"(a[3]), "r"(b0), "r"(b1));
}

// ---------------- zero scratch ----------------------------------------------
__global__ void zero_kernel() {
    long long i = (long long)blockIdx.x * blockDim.x + threadIdx.x;
    long long stride = (long long)gridDim.x * blockDim.x;
    const long long total4 = (long long)Nv * 16;
    float4* p = reinterpret_cast<float4*>(g_x2);
    float4 z = make_float4(0.f, 0.f, 0.f, 0.f);
    for (long long j = i; j < total4; j += stride) p[j] = z;
    if (i < Bb * 64)  { g_sum1[i] = 0.f; g_sq1[i] = 0.f; g_sum2[i] = 0.f; g_sq2[i] = 0.f; }
    if (i < Bb * 256) { g_sum3[i] = 0.f; g_sq3[i] = 0.f; }
    if (i < Bb) g_cnt[i] = 0;
}

// ---------------- per-batch counts ------------------------------------------
__global__ void count_kernel(const int* __restrict__ batch_idx) {
    __shared__ int s[Bb];
    if (threadIdx.x < Bb) s[threadIdx.x] = 0;
    __syncthreads();
    int i = blockIdx.x * blockDim.x + threadIdx.x;
    int stride = gridDim.x * blockDim.x;
    for (int j = i; j < Nv; j += stride) atomicAdd(&s[batch_idx[j]], 1);
    __syncthreads();
    if (threadIdx.x < Bb) atomicAdd(&g_cnt[threadIdx.x], s[threadIdx.x]);
}

// ---------------- conv1: x1 = feats[N,256] @ W1[256,64], fused stats1 -------
__global__ void __launch_bounds__(256) conv1_kernel(const float* __restrict__ feats,
                                                    const float* __restrict__ W1,
                                                    const int* __restrict__ batch_idx,
                                                    float* __restrict__ gsum,
                                                    float* __restrict__ gsq) {
    extern __shared__ __align__(16) float smem[];
    float* As = smem;               // 128 x 68
    float* Ws = smem + 8704;        // 64 x 64
    int*   s_b = (int*)&smem[12800];

    int t = threadIdx.x;
    int row0 = blockIdx.x * 128;
    if (t < 128) {
        int r = row0 + t;
        s_b[t] = (r < Nv) ? batch_idx[r] : -1;
    }

    int ty = t >> 3;
    int tx = t & 7;
    unsigned long long acc[4][4];
#pragma unroll
    for (int i = 0; i < 4; i++)
#pragma unroll
        for (int j = 0; j < 4; j++) acc[i][j] = 0ull;

    for (int k0 = 0; k0 < 256; k0 += 64) {
        __syncthreads();
#pragma unroll
        for (int e4 = t; e4 < 128 * 16; e4 += 256) {
            int r = e4 >> 4, cg = e4 & 15;
            int row = row0 + r;
            float4 v = make_float4(0.f, 0.f, 0.f, 0.f);
            if (row < Nv) v = *(const float4*)&feats[(size_t)row * 256 + k0 + cg * 4];
            *(float4*)&As[r * 68 + cg * 4] = v;
        }
#pragma unroll
        for (int e4 = t; e4 < 1024; e4 += 256)
            ((float4*)Ws)[e4] = ((const float4*)(W1 + (size_t)k0 * 64))[e4];
        __syncthreads();

#pragma unroll 2
        for (int c0 = 0; c0 < 64; c0 += 4) {
            float4 av[4];
#pragma unroll
            for (int i = 0; i < 4; i++) av[i] = *(const float4*)&As[(ty * 4 + i) * 68 + c0];
#pragma unroll
            for (int cc = 0; cc < 4; cc++) {
                const ulonglong2 wA = *(const ulonglong2*)&Ws[(c0 + cc) * 64 + tx * 8];
                const ulonglong2 wB = *(const ulonglong2*)&Ws[(c0 + cc) * 64 + tx * 8 + 4];
#pragma unroll
                for (int i = 0; i < 4; i++) {
                    float a = (cc == 0) ? av[i].x : (cc == 1) ? av[i].y : (cc == 2) ? av[i].z : av[i].w;
                    unsigned long long aa = dup2(a);
                    fma2(acc[i][0], aa, wA.x);
                    fma2(acc[i][1], aa, wA.y);
                    fma2(acc[i][2], aa, wB.x);
                    fma2(acc[i][3], aa, wB.y);
                }
            }
        }
    }

#pragma unroll
    for (int i = 0; i < 4; i++) {
        int row = row0 + ty * 4 + i;
        if (row < Nv) {
            *(ulonglong2*)&g_x1[(size_t)row * 64 + tx * 8]     = make_ulonglong2(acc[i][0], acc[i][1]);
            *(ulonglong2*)&g_x1[(size_t)row * 64 + tx * 8 + 4] = make_ulonglong2(acc[i][2], acc[i][3]);
        }
    }

    __syncthreads();
    int b0 = s_b[0];
    bool fast = (s_b[127] == b0);
    float* red = As;
    if (fast) {
        float ss[8], qq[8];
#pragma unroll
        for (int j = 0; j < 8; j++) { ss[j] = 0.f; qq[j] = 0.f; }
#pragma unroll
        for (int i = 0; i < 4; i++)
#pragma unroll
            for (int jp = 0; jp < 4; jp++) {
                float2 p = unpack2(acc[i][jp]);
                ss[2 * jp] += p.x;     qq[2 * jp] += p.x * p.x;
                ss[2 * jp + 1] += p.y; qq[2 * jp + 1] += p.y * p.y;
            }
        *(float4*)&red[ty * 64 + tx * 8]          = make_float4(ss[0], ss[1], ss[2], ss[3]);
        *(float4*)&red[ty * 64 + tx * 8 + 4]      = make_float4(ss[4], ss[5], ss[6], ss[7]);
        *(float4*)&red[2048 + ty * 64 + tx * 8]     = make_float4(qq[0], qq[1], qq[2], qq[3]);
        *(float4*)&red[2048 + ty * 64 + tx * 8 + 4] = make_float4(qq[4], qq[5], qq[6], qq[7]);
        __syncthreads();
        if (t < 64) {
            float s = 0.f;
#pragma unroll
            for (int u = 0; u < 32; u++) s += red[u * 64 + t];
            atomicAdd(&gsum[b0 * 64 + t], s);
        } else if (t < 128) {
            int c = t - 64;
            float s = 0.f;
#pragma unroll
            for (int u = 0; u < 32; u++) s += red[2048 + u * 64 + c];
            atomicAdd(&gsq[b0 * 64 + c], s);
        }
    } else {
#pragma unroll
        for (int i = 0; i < 4; i++) {
            int r = row0 + ty * 4 + i;
            if (r < Nv) {
                int b = s_b[ty * 4 + i];
#pragma unroll
                for (int jp = 0; jp < 4; jp++) {
                    float2 p = unpack2(acc[i][jp]);
                    atomicAdd(&gsum[b * 64 + tx * 8 + 2 * jp], p.x);
                    atomicAdd(&gsum[b * 64 + tx * 8 + 2 * jp + 1], p.y);
                    atomicAdd(&gsq[b * 64 + tx * 8 + 2 * jp], p.x * p.x);
                    atomicAdd(&gsq[b * 64 + tx * 8 + 2 * jp + 1], p.y * p.y);
                }
            }
        }
    }
}

// ---------------- finalize stats ---------------------------------------------
__global__ void finalize_kernel(float* sumArr, float* sqArr, int C) {
    int i = blockIdx.x * blockDim.x + threadIdx.x;
    if (i < Bb * C) {
        float cnt = (float)g_cnt[i / C];
        float mean = sumArr[i] / cnt;
        float var = sqArr[i] / cnt - mean * mean;
        sumArr[i] = mean;
        sqArr[i] = rsqrtf(fmaxf(var, 0.f) + EPSf);
    }
}

// ---------------- norm1 + relu + bf16 hi/lo split -----------------------------
__global__ void __launch_bounds__(256) norm_split_kernel(const int* __restrict__ batch_idx,
                                                         const float* __restrict__ mean,
                                                         const float* __restrict__ inv) {
    long long total = (long long)Nv * 16;
    long long i = (long long)blockIdx.x * blockDim.x + threadIdx.x;
    long long stride = (long long)gridDim.x * blockDim.x;
    for (; i < total; i += stride) {
        int row = (int)(i >> 4);
        int cg = (int)(i & 15);
        int b = batch_idx[row];
        float4 v = ((const float4*)g_x1)[i];
        float4 m = ((const float4*)mean)[b * 16 + cg];
        float4 s = ((const float4*)inv)[b * 16 + cg];
        float a0 = fmaxf((v.x - m.x) * s.x, 0.f);
        float a1 = fmaxf((v.y - m.y) * s.y, 0.f);
        float a2 = fmaxf((v.z - m.z) * s.z, 0.f);
        float a3 = fmaxf((v.w - m.w) * s.w, 0.f);
        __nv_bfloat16 h0 = __float2bfloat16(a0), h1 = __float2bfloat16(a1);
        __nv_bfloat16 h2 = __float2bfloat16(a2), h3 = __float2bfloat16(a3);
        __nv_bfloat16 l0 = __float2bfloat16(a0 - __bfloat162float(h0));
        __nv_bfloat16 l1 = __float2bfloat16(a1 - __bfloat162float(h1));
        __nv_bfloat16 l2 = __float2bfloat16(a2 - __bfloat162float(h2));
        __nv_bfloat16 l3 = __float2bfloat16(a3 - __bfloat162float(h3));
        __nv_bfloat162* ph = (__nv_bfloat162*)&g_x1h[(size_t)row * 64 + cg * 4];
        __nv_bfloat162* pl = (__nv_bfloat162*)&g_x1l[(size_t)row * 64 + cg * 4];
        ph[0] = __nv_bfloat162(h0, h1);
        ph[1] = __nv_bfloat162(h2, h3);
        pl[0] = __nv_bfloat162(l0, l1);
        pl[1] = __nv_bfloat162(l2, l3);
    }
}

// ---------------- conv2: mma.sync bf16 3-term gather-GEMM-scatter ------------
// grid (782, 27); 256 thr (8 warps, 4x2); tile M=128, N=64, K=64
// smem: Ah[128][72] Al[128][72] Wh[64][72] Wl[64][72] bf16; C overlay f32[128][68]
__global__ void __launch_bounds__(256) conv2_mma_kernel(const int* __restrict__ in_idx,
                                                        const int* __restrict__ out_idx,
                                                        const float* __restrict__ W2) {
    extern __shared__ __align__(16) char sm2[];
    __nv_bfloat16* Ah = (__nv_bfloat16*)sm2;             // 18432 B
    __nv_bfloat16* Al = (__nv_bfloat16*)(sm2 + 18432);   // 18432 B
    __nv_bfloat16* Wh = (__nv_bfloat16*)(sm2 + 36864);   // 9216 B
    __nv_bfloat16* Wl = (__nv_bfloat16*)(sm2 + 46080);   // 9216 B
    float* Cs = (float*)sm2;                             // 128*68*4 = 34816 B (overlay)
    __shared__ int s_in[128], s_out[128];

    int t = threadIdx.x;
    int k = blockIdx.y;
    int m0 = blockIdx.x * 128;

    if (t < 128) {
        int p = m0 + t;
        bool v = (p < Mm);
        s_in[t]  = v ? in_idx[(size_t)k * Mm + p] : -1;
        s_out[t] = v ? out_idx[(size_t)k * Mm + p] : -1;
    }

    // W2[k][c][d] -> B[n=d][k=c] hi/lo, padded LDB=72
    const float* Wk = W2 + (size_t)k * 4096;
#pragma unroll
    for (int e = t; e < 4096; e += 256) {
        int c = e >> 6, d = e & 63;
        float w = Wk[e];
        __nv_bfloat16 h = __float2bfloat16(w);
        __nv_bfloat16 l = __float2bfloat16(w - __bfloat162float(h));
        Wh[d * 72 + c] = h;
        Wl[d * 72 + c] = l;
    }
    __syncthreads();

    // gather bf16 hi/lo rows (128 rows x 64 bf16 = 8 x 16B each)
#pragma unroll
    for (int e = t; e < 1024; e += 256) {
        int r = e >> 3, q = e & 7;
        int src = s_in[r];
        uint4 vh = make_uint4(0u, 0u, 0u, 0u);
        uint4 vl = vh;
        if (src >= 0) {
            vh = ((const uint4*)(g_x1h + (size_t)src * 64))[q];
            vl = ((const uint4*)(g_x1l + (size_t)src * 64))[q];
        }
        *(uint4*)&Ah[r * 72 + q * 8] = vh;
        *(uint4*)&Al[r * 72 + q * 8] = vl;
    }
    __syncthreads();

    int wid = t >> 5, lane = t & 31;
    int mb = (wid >> 1) * 32;    // warp row: 32 m-rows
    int nb = (wid & 1) * 32;     // warp col: 32 n-cols

    float acc[2][4][4];
#pragma unroll
    for (int i = 0; i < 2; i++)
#pragma unroll
        for (int j = 0; j < 4; j++)
#pragma unroll
            for (int q = 0; q < 4; q++) acc[i][j][q] = 0.f;

    // ldmatrix per-lane source rows
    int a_row = lane & 15;                  // + quadrant k-offset
    int a_koff = (lane >> 4) << 3;
    int b_n = (lane & 7) + ((lane >> 4) << 3);   // n within 16-wide pair
    int b_koff = ((lane >> 3) & 1) << 3;

#pragma unroll
    for (int term = 0; term < 3; term++) {
        const __nv_bfloat16* A = (term == 1) ? Al : Ah;
        const __nv_bfloat16* W = (term == 2) ? Wl : Wh;
#pragma unroll
        for (int ks = 0; ks < 4; ks++) {
            int k0 = ks * 16;
            uint32_t af0[4], af1[4], bf0[4], bf1[4];
            ldsm_x4(af0, smem_u32(&A[(mb + a_row) * 72 + k0 + a_koff]));
            ldsm_x4(af1, smem_u32(&A[(mb + 16 + a_row) * 72 + k0 + a_koff]));
            ldsm_x4(bf0, smem_u32(&W[(nb + b_n) * 72 + k0 + b_koff]));
            ldsm_x4(bf1, smem_u32(&W[(nb + 16 + b_n) * 72 + k0 + b_koff]));
            mma_bf16(acc[0][0], af0, bf0[0], bf0[1]);
            mma_bf16(acc[0][1], af0, bf0[2], bf0[3]);
            mma_bf16(acc[0][2], af0, bf1[0], bf1[1]);
            mma_bf16(acc[0][3], af0, bf1[2], bf1[3]);
            mma_bf16(acc[1][0], af1, bf0[0], bf0[1]);
            mma_bf16(acc[1][1], af1, bf0[2], bf0[3]);
            mma_bf16(acc[1][2], af1, bf1[0], bf1[1]);
            mma_bf16(acc[1][3], af1, bf1[2], bf1[3]);
        }
    }

    __syncthreads();   // all warps done reading A/W smem -> safe to overlay C

    int g = lane >> 2, tg = lane & 3;
#pragma unroll
    for (int mi = 0; mi < 2; mi++) {
        int row = mb + mi * 16 + g;
#pragma unroll
        for (int nj = 0; nj < 4; nj++) {
            int col = nb + nj * 8 + tg * 2;
            *(float2*)&Cs[row * 68 + col]       = make_float2(acc[mi][nj][0], acc[mi][nj][1]);
            *(float2*)&Cs[(row + 8) * 68 + col] = make_float2(acc[mi][nj][2], acc[mi][nj][3]);
        }
    }
    __syncthreads();

    // scatter: thread handles half a row (32 floats = 8 red.v4)
    {
        int r = t >> 1, h = (t & 1) * 32;
        int dst = s_out[r];
        if (dst >= 0) {
            float* p = g_x2 + (size_t)dst * 64 + h;
            const float* c = &Cs[r * 68 + h];
#pragma unroll
            for (int j = 0; j < 8; j++)
                red_v4(p + j * 4, c[j * 4], c[j * 4 + 1], c[j * 4 + 2], c[j * 4 + 3]);
        }
    }
}

// ---------------- stats2: per (batch, channel) sum/sumsq over x2 ------------
__global__ void __launch_bounds__(256) stats2_kernel(const float* __restrict__ x,
                                                     const int* __restrict__ batch_idx,
                                                     float* __restrict__ gsum,
                                                     float* __restrict__ gsq) {
    __shared__ float sm[2048];
    int t = threadIdx.x;
    int r0 = blockIdx.x * 128;
    int r1 = min(r0 + 128, Nv);
    int cg = t & 15, rg = t >> 4;
    int b0 = batch_idx[r0], b1 = batch_idx[r1 - 1];

    if (b0 == b1) {
        float4 s = make_float4(0.f, 0.f, 0.f, 0.f);
        float4 q = make_float4(0.f, 0.f, 0.f, 0.f);
#pragma unroll 4
        for (int r = r0 + rg; r < r1; r += 16) {
            float4 v = *(const float4*)&x[(size_t)r * 64 + cg * 4];
            s.x += v.x; s.y += v.y; s.z += v.z; s.w += v.w;
            q.x += v.x * v.x; q.y += v.y * v.y; q.z += v.z * v.z; q.w += v.w * v.w;
        }
        *(float4*)&sm[rg * 64 + cg * 4]        = s;
        *(float4*)&sm[1024 + rg * 64 + cg * 4] = q;
        __syncthreads();
        if (t < 64) {
            float v = 0.f;
#pragma unroll
            for (int u = 0; u < 16; u++) v += sm[u * 64 + t];
            atomicAdd(&gsum[b0 * 64 + t], v);
        } else if (t < 128) {
            int c = t - 64;
            float v = 0.f;
#pragma unroll
            for (int u = 0; u < 16; u++) v += sm[1024 + u * 64 + c];
            atomicAdd(&gsq[b0 * 64 + c], v);
        }
    } else {
        for (int i = t; i < 512; i += 256) sm[i] = 0.f;
        __syncthreads();
        for (int r = r0 + rg; r < r1; r += 16) {
            int b = batch_idx[r];
            float4 v = *(const float4*)&x[(size_t)r * 64 + cg * 4];
            atomicAdd(&sm[b * 64 + cg * 4], v.x);
            atomicAdd(&sm[b * 64 + cg * 4 + 1], v.y);
            atomicAdd(&sm[b * 64 + cg * 4 + 2], v.z);
            atomicAdd(&sm[b * 64 + cg * 4 + 3], v.w);
            atomicAdd(&sm[256 + b * 64 + cg * 4], v.x * v.x);
            atomicAdd(&sm[256 + b * 64 + cg * 4 + 1], v.y * v.y);
            atomicAdd(&sm[256 + b * 64 + cg * 4 + 2], v.z * v.z);
            atomicAdd(&sm[256 + b * 64 + cg * 4 + 3], v.w * v.w);
        }
        __syncthreads();
        if (t < 256) {
            if (sm[t] != 0.f)       atomicAdd(&gsum[t], sm[t]);
            if (sm[256 + t] != 0.f) atomicAdd(&gsq[t], sm[256 + t]);
        }
    }
}

// ---------------- conv3: gather(norm2+relu) -> GEMM -> out, fused stats3 ----
__global__ void __launch_bounds__(256) conv3_kernel(const float* __restrict__ W3,
                                                    float* __restrict__ out,
                                                    const int* __restrict__ batch_idx,
                                                    const float* __restrict__ mean2,
                                                    const float* __restrict__ inv2,
                                                    float* __restrict__ gsum,
                                                    float* __restrict__ gsq) {
    extern __shared__ __align__(16) float smem[];
    float* Xs   = smem;                 // 128 x 68
    float* Ws   = smem + 8704;          // 64 x 128
    float* sm_m = smem + 16896;
    float* sm_i = smem + 17152;
    int*   s_b  = (int*)&smem[17408];

    int t = threadIdx.x;
    int row0 = blockIdx.x * 128;
    int col0 = blockIdx.y * 128;

    if (t < 128) {
        int r = row0 + t;
        s_b[t] = (r < Nv) ? batch_idx[r] : -1;
    }
    if (t < 256) { sm_m[t] = mean2[t]; sm_i[t] = inv2[t]; }
#pragma unroll
    for (int e4 = t; e4 < 2048; e4 += 256) {
        int c = e4 >> 5, d4 = e4 & 31;
        ((float4*)Ws)[e4] = *(const float4*)&W3[c * 256 + col0 + d4 * 4];
    }
    __syncthreads();

#pragma unroll
    for (int e = t; e < 128 * 16; e += 256) {
        int r = e >> 4, cg = e & 15;
        int row = row0 + r;
        float4 v = make_float4(0.f, 0.f, 0.f, 0.f);
        if (row < Nv) {
            float4 x = *(const float4*)&g_x2[(size_t)row * 64 + cg * 4];
            int b = s_b[r];
            float4 m = *(const float4*)&sm_m[b * 64 + cg * 4];
            float4 iv = *(const float4*)&sm_i[b * 64 + cg * 4];
            v.x = fmaxf((x.x - m.x) * iv.x, 0.f);
            v.y = fmaxf((x.y - m.y) * iv.y, 0.f);
            v.z = fmaxf((x.z - m.z) * iv.z, 0.f);
            v.w = fmaxf((x.w - m.w) * iv.w, 0.f);
        }
        *(float4*)&Xs[r * 68 + cg * 4] = v;
    }
    __syncthreads();

    int ty = t >> 3;
    int tx = t & 7;
    unsigned long long acc[4][8];
#pragma unroll
    for (int i = 0; i < 4; i++)
#pragma unroll
        for (int j = 0; j < 8; j++) acc[i][j] = 0ull;

#pragma unroll 2
    for (int c0 = 0; c0 < 64; c0 += 4) {
        float4 av[4];
#pragma unroll
        for (int i = 0; i < 4; i++) av[i] = *(const float4*)&Xs[(ty * 4 + i) * 68 + c0];
#pragma unroll
        for (int cc = 0; cc < 4; cc++) {
            const float* wrow = &Ws[(c0 + cc) * 128 + tx * 16];
            const ulonglong2 w0 = *(const ulonglong2*)(wrow);
            const ulonglong2 w1 = *(const ulonglong2*)(wrow + 4);
            const ulonglong2 w2 = *(const ulonglong2*)(wrow + 8);
            const ulonglong2 w3 = *(const ulonglong2*)(wrow + 12);
#pragma unroll
            for (int i = 0; i < 4; i++) {
                float a = (cc == 0) ? av[i].x : (cc == 1) ? av[i].y : (cc == 2) ? av[i].z : av[i].w;
                unsigned long long aa = dup2(a);
                fma2(acc[i][0], aa, w0.x); fma2(acc[i][1], aa, w0.y);
                fma2(acc[i][2], aa, w1.x); fma2(acc[i][3], aa, w1.y);
                fma2(acc[i][4], aa, w2.x); fma2(acc[i][5], aa, w2.y);
                fma2(acc[i][6], aa, w3.x); fma2(acc[i][7], aa, w3.y);
            }
        }
    }

    __syncthreads();
    int b0 = s_b[0];
    bool fast = (s_b[127] == b0);
    float* red = Ws;

    float ss[16], qq[16];
#pragma unroll
    for (int j = 0; j < 16; j++) { ss[j] = 0.f; qq[j] = 0.f; }

#pragma unroll
    for (int i = 0; i < 4; i++) {
        float v[16];
#pragma unroll
        for (int jp = 0; jp < 8; jp++) {
            float2 p = unpack2(acc[i][jp]);
            v[2 * jp] = p.x; v[2 * jp + 1] = p.y;
        }
        int row = row0 + ty * 4 + i;
        if (row < Nv) {
            float* o = &out[(size_t)row * 256 + col0 + tx * 16];
            *(float4*)(o)      = make_float4(v[0], v[1], v[2], v[3]);
            *(float4*)(o + 4)  = make_float4(v[4], v[5], v[6], v[7]);
            *(float4*)(o + 8)  = make_float4(v[8], v[9], v[10], v[11]);
            *(float4*)(o + 12) = make_float4(v[12], v[13], v[14], v[15]);
        }
        if (fast) {
#pragma unroll
            for (int j = 0; j < 16; j++) { ss[j] += v[j]; qq[j] += v[j] * v[j]; }
        } else if (row < Nv) {
            int b = s_b[ty * 4 + i];
#pragma unroll
            for (int j = 0; j < 16; j++) {
                atomicAdd(&gsum[b * 256 + col0 + tx * 16 + j], v[j]);
                atomicAdd(&gsq[b * 256 + col0 + tx * 16 + j], v[j] * v[j]);
            }
        }
    }

    if (fast) {
#pragma unroll
        for (int u = 0; u < 4; u++) {
            *(float4*)&red[ty * 128 + tx * 16 + u * 4] =
                make_float4(ss[u * 4], ss[u * 4 + 1], ss[u * 4 + 2], ss[u * 4 + 3]);
            *(float4*)&red[4096 + ty * 128 + tx * 16 + u * 4] =
                make_float4(qq[u * 4], qq[u * 4 + 1], qq[u * 4 + 2], qq[u * 4 + 3]);
        }
        __syncthreads();
        if (t < 128) {
            float s = 0.f;
#pragma unroll
            for (int u = 0; u < 32; u++) s += red[u * 128 + t];
            atomicAdd(&gsum[b0 * 256 + col0 + t], s);
        } else {
            int c = t - 128;
            float s = 0.f;
#pragma unroll
            for (int u = 0; u < 32; u++) s += red[4096 + u * 128 + c];
            atomicAdd(&gsq[b0 * 256 + col0 + c], s);
        }
    }
}

// ---------------- final: normalize3 + residual + relu ------------------------
__global__ void final_kernel(float* __restrict__ y,
                             const float* __restrict__ feats,
                             const int* __restrict__ batch_idx,
                             const float* __restrict__ mean,
                             const float* __restrict__ inv) {
    const int C4 = 64;
    long long total = (long long)Nv * C4;
    long long i = (long long)blockIdx.x * blockDim.x + threadIdx.x;
    long long stride = (long long)gridDim.x * blockDim.x;
    for (; i < total; i += stride) {
        int row = (int)(i / C4);
        int cg = (int)(i % C4);
        int b = batch_idx[row];
        float4 v = ((float4*)y)[i];
        float4 f = ((const float4*)feats)[i];
        float4 m = ((const float4*)mean)[b * C4 + cg];
        float4 sv = ((const float4*)inv)[b * C4 + cg];
        v.x = fmaxf((v.x - m.x) * sv.x + f.x, 0.f);
        v.y = fmaxf((v.y - m.y) * sv.y + f.y, 0.f);
        v.z = fmaxf((v.z - m.z) * sv.z + f.z, 0.f);
        v.w = fmaxf((v.w - m.w) * sv.w + f.w, 0.f);
        ((float4*)y)[i] = v;
    }
}

// ---------------- launch -----------------------------------------------------
extern "C" void kernel_launch(void* const* d_in, const int* in_sizes, int n_in,
                              void* d_out, int out_size) {
    const float* feats     = (const float*)d_in[0];
    const float* W1        = (const float*)d_in[1];
    const float* W2        = (const float*)d_in[2];
    const float* W3        = (const float*)d_in[3];
    const int*   in_idx    = (const int*)d_in[4];
    const int*   out_idx   = (const int*)d_in[5];
    const int*   batch_idx = (const int*)d_in[6];
    float* out = (float*)d_out;

    float *p_x2, *p_sum1, *p_sq1, *p_sum2, *p_sq2, *p_sum3, *p_sq3;
    cudaGetSymbolAddress((void**)&p_x2, g_x2);
    cudaGetSymbolAddress((void**)&p_sum1, g_sum1);
    cudaGetSymbolAddress((void**)&p_sq1, g_sq1);
    cudaGetSymbolAddress((void**)&p_sum2, g_sum2);
    cudaGetSymbolAddress((void**)&p_sq2, g_sq2);
    cudaGetSymbolAddress((void**)&p_sum3, g_sum3);
    cudaGetSymbolAddress((void**)&p_sq3, g_sq3);

    const int smem1 = 51712;
    const int smem2 = 55296;
    const int smem3 = 70144;
    cudaFuncSetAttribute(conv1_kernel, cudaFuncAttributeMaxDynamicSharedMemorySize, smem1);
    cudaFuncSetAttribute(conv2_mma_kernel, cudaFuncAttributeMaxDynamicSharedMemorySize, smem2);
    cudaFuncSetAttribute(conv3_kernel, cudaFuncAttributeMaxDynamicSharedMemorySize, smem3);

    zero_kernel<<<2048, 256>>>();
    count_kernel<<<391, 256>>>(batch_idx);

    // conv1 + fused stats1
    conv1_kernel<<<(Nv + 127) / 128, 256, smem1>>>(feats, W1, batch_idx, p_sum1, p_sq1);
    finalize_kernel<<<1, 256>>>(p_sum1, p_sq1, 64);

    // norm1 + relu + bf16 hi/lo split
    norm_split_kernel<<<4096, 256>>>(batch_idx, p_sum1, p_sq1);

    // conv2: tensor-core mma.sync (bf16 3-term split)
    dim3 g2((Mm + 127) / 128, Kk);
    conv2_mma_kernel<<<g2, 256, smem2>>>(in_idx, out_idx, W2);
    stats2_kernel<<<(Nv + 127) / 128, 256>>>(p_x2, batch_idx, p_sum2, p_sq2);
    finalize_kernel<<<1, 256>>>(p_sum2, p_sq2, 64);

    // conv3 (norm2+relu fused in gather) + fused stats3
    dim3 g3((Nv + 127) / 128, 2);
    conv3_kernel<<<g3, 256, smem3>>>(W3, out, batch_idx, p_sum2, p_sq2, p_sum3, p_sq3);
    finalize_kernel<<<4, 256>>>(p_sum3, p_sq3, 256);

    final_kernel<<<16384, 256>>>(out, feats, batch_idx, p_sum3, p_sq3);
}

// round 5
// speedup vs baseline: 1.6668x; 1.3393x over previous
#include <cuda_runtime.h>
#include <cuda_bf16.h>
#include <cstdint>

#define Nv   200000
#define Kk   27
#define Mm   100000
#define Bb   4
#define EPSf 1e-5f

// ---------------- scratch (device globals — no runtime allocation) ----------
__device__ float g_x1[(size_t)Nv * 64];          // conv1 out (raw, pre-norm)
__device__ float g_x2[(size_t)Nv * 64];          // conv2 accum (raw, pre-norm)
__device__ __nv_bfloat16 g_x1h[(size_t)Nv * 64]; // normalized x1, bf16 hi
__device__ __nv_bfloat16 g_x1l[(size_t)Nv * 64]; // normalized x1, bf16 lo
__device__ __nv_bfloat16 g_W1h[64 * 256],  g_W1l[64 * 256];    // [d][c] col-major
__device__ __nv_bfloat16 g_W2h[Kk * 4096], g_W2l[Kk * 4096];   // [k][d][c]
__device__ __nv_bfloat16 g_W3h[256 * 64],  g_W3l[256 * 64];    // [n][c]
__device__ float g_sum1[Bb * 64], g_sq1[Bb * 64];
__device__ float g_sum2[Bb * 64], g_sq2[Bb * 64];
__device__ float g_sum3[Bb * 256], g_sq3[Bb * 256];
__device__ int   g_cnt[Bb];

// ---------------- helpers -----------------------------------------------------
__device__ __forceinline__ void red_v4(float* p, float a, float b, float c, float d) {
    asm volatile("red.global.add.v4.f32 [%0], {%1,%2,%3,%4};"
                 :: "l"(p), "f"(a), "f"(b), "f"(c), "f"(d) : "memory");
}
__device__ __forceinline__ uint32_t smem_u32(const void* p) {
    uint32_t a;
    asm("{ .reg .u64 t; cvta.to.shared.u64 t, %1; cvt.u32.u64 %0, t; }"
        : "=r"(a) : "l"(p));
    return a;
}
__device__ __forceinline__ void ldsm_x4(uint32_t* r, uint32_t addr) {
    asm volatile("ldmatrix.sync.aligned.m8n8.x4.shared.b16 {%0,%1,%2,%3}, [%4];"
        : "=r"(r[0]), "=r"(r[1]), "=r"(r[2]), "=r"(r[3]) : "r"(addr));
}
__device__ __forceinline__ void mma_bf16(float* c, const uint32_t* a,
                                         uint32_t b0, uint32_t b1) {
    asm volatile("mma.sync.aligned.m16n8k16.row.col.f32.bf16.bf16.f32 "
        "{%0,%1,%2,%3}, {%4,%5,%6,%7}, {%8,%9}, {%0,%1,%2,%3};"
        : "+f"(c[0]), "+f"(c[1]), "+f"(c[2]), "+f"(c[3])
        : "r"(a[0]), "r"(a[1]), "r"(a[2]), "r"(a[3]), "r"(b0), "r"(b1));
}
__device__ __forceinline__ void split_bf(float a, __nv_bfloat16& h, __nv_bfloat16& l) {
    h = __float2bfloat16(a);
    l = __float2bfloat16(a - __bfloat162float(h));
}

// ---------------- zero scratch ----------------------------------------------
__global__ void zero_kernel() {
    long long i = (long long)blockIdx.x * blockDim.x + threadIdx.x;
    long long stride = (long long)gridDim.x * blockDim.x;
    const long long total4 = (long long)Nv * 16;
    float4* p = reinterpret_cast<float4*>(g_x2);
    float4 z = make_float4(0.f, 0.f, 0.f, 0.f);
    for (long long j = i; j < total4; j += stride) p[j] = z;
    if (i < Bb * 64)  { g_sum1[i] = 0.f; g_sq1[i] = 0.f; g_sum2[i] = 0.f; g_sq2[i] = 0.f; }
    if (i < Bb * 256) { g_sum3[i] = 0.f; g_sq3[i] = 0.f; }
    if (i < Bb) g_cnt[i] = 0;
}

// ---------------- per-batch counts ------------------------------------------
__global__ void count_kernel(const int* __restrict__ batch_idx) {
    __shared__ int s[Bb];
    if (threadIdx.x < Bb) s[threadIdx.x] = 0;
    __syncthreads();
    int i = blockIdx.x * blockDim.x + threadIdx.x;
    int stride = gridDim.x * blockDim.x;
    for (int j = i; j < Nv; j += stride) atomicAdd(&s[batch_idx[j]], 1);
    __syncthreads();
    if (threadIdx.x < Bb) atomicAdd(&g_cnt[threadIdx.x], s[threadIdx.x]);
}

// ---------------- weight pre-split (col-major bf16 hi/lo) --------------------
__global__ void wsplit_kernel(const float* __restrict__ W1,
                              const float* __restrict__ W2,
                              const float* __restrict__ W3) {
    int i = blockIdx.x * blockDim.x + threadIdx.x;
    if (i < 16384) {                       // W1: [d=64][c=256] <- W1[c*64+d]
        int d = i >> 8, c = i & 255;
        __nv_bfloat16 h, l;
        split_bf(W1[c * 64 + d], h, l);
        g_W1h[i] = h; g_W1l[i] = l;
    } else if (i < 16384 + Kk * 4096) {    // W2: [k][d=64][c=64] <- W2[k][c][d]
        int j = i - 16384;
        int kk = j >> 12, r = j & 4095;
        int d = r >> 6, c = r & 63;
        __nv_bfloat16 h, l;
        split_bf(W2[kk * 4096 + c * 64 + d], h, l);
        g_W2h[j] = h; g_W2l[j] = l;
    } else if (i < 16384 + Kk * 4096 + 16384) {  // W3: [n=256][c=64] <- W3[c*256+n]
        int j = i - 16384 - Kk * 4096;
        int n = j >> 6, c = j & 63;
        __nv_bfloat16 h, l;
        split_bf(W3[c * 256 + n], h, l);
        g_W3h[j] = h; g_W3l[j] = l;
    }
}

// ---------------- conv1: mma.sync, x1 = feats @ W1, fused stats1 --------------
// grid 1563; 256 thr (8 warps 4x2); tile M=128, N=64, K=256 (4 chunks)
__global__ void __launch_bounds__(256) conv1_mma_kernel(const float* __restrict__ feats,
                                                        const int* __restrict__ batch_idx,
                                                        float* __restrict__ gsum,
                                                        float* __restrict__ gsq) {
    extern __shared__ __align__(16) char sm1[];
    __nv_bfloat16* Ah = (__nv_bfloat16*)sm1;             // 128x72 = 18432 B
    __nv_bfloat16* Al = (__nv_bfloat16*)(sm1 + 18432);   // 18432 B
    __nv_bfloat16* Wh = (__nv_bfloat16*)(sm1 + 36864);   // 64x72 = 9216 B
    __nv_bfloat16* Wl = (__nv_bfloat16*)(sm1 + 46080);   // 9216 B -> 55296
    float* Cs = (float*)sm1;                             // overlay 128x68 f32
    __shared__ int s_b[128];
    __shared__ float sred[256], qred[256];

    int t = threadIdx.x;
    int row0 = blockIdx.x * 128;
    if (t < 128) {
        int r = row0 + t;
        s_b[t] = (r < Nv) ? batch_idx[r] : -1;
    }

    int wid = t >> 5, lane = t & 31;
    int mb = (wid >> 1) * 32;
    int nb = (wid & 1) * 32;
    int a_row = lane & 15;
    int a_koff = (lane >> 4) << 3;
    int b_n = (lane & 7) + ((lane >> 4) << 3);
    int b_koff = ((lane >> 3) & 1) << 3;

    float acc[2][4][4];
#pragma unroll
    for (int i = 0; i < 2; i++)
#pragma unroll
        for (int j = 0; j < 4; j++)
#pragma unroll
            for (int q = 0; q < 4; q++) acc[i][j][q] = 0.f;

    for (int k0 = 0; k0 < 256; k0 += 64) {
        __syncthreads();
        // A chunk: load fp32, split bf16 hi/lo
#pragma unroll
        for (int e4 = t; e4 < 2048; e4 += 256) {
            int r = e4 >> 4, cg = e4 & 15;
            int row = row0 + r;
            float4 v = make_float4(0.f, 0.f, 0.f, 0.f);
            if (row < Nv) v = *(const float4*)&feats[(size_t)row * 256 + k0 + cg * 4];
            __nv_bfloat16 h0, h1, h2, h3, l0, l1, l2, l3;
            split_bf(v.x, h0, l0); split_bf(v.y, h1, l1);
            split_bf(v.z, h2, l2); split_bf(v.w, h3, l3);
            __nv_bfloat162* ph = (__nv_bfloat162*)&Ah[r * 72 + cg * 4];
            __nv_bfloat162* pl = (__nv_bfloat162*)&Al[r * 72 + cg * 4];
            ph[0] = __nv_bfloat162(h0, h1); ph[1] = __nv_bfloat162(h2, h3);
            pl[0] = __nv_bfloat162(l0, l1); pl[1] = __nv_bfloat162(l2, l3);
        }
        // W chunk from pre-split
#pragma unroll
        for (int e4 = t; e4 < 512; e4 += 256) {
            int d = e4 >> 3, q = e4 & 7;
            *(uint4*)&Wh[d * 72 + q * 8] = *(const uint4*)&g_W1h[d * 256 + k0 + q * 8];
            *(uint4*)&Wl[d * 72 + q * 8] = *(const uint4*)&g_W1l[d * 256 + k0 + q * 8];
        }
        __syncthreads();

#pragma unroll
        for (int term = 0; term < 3; term++) {
            const __nv_bfloat16* A = (term == 1) ? Al : Ah;
            const __nv_bfloat16* W = (term == 2) ? Wl : Wh;
#pragma unroll
            for (int ks = 0; ks < 4; ks++) {
                int kc = ks * 16;
                uint32_t af0[4], af1[4], bf0[4], bf1[4];
                ldsm_x4(af0, smem_u32(&A[(mb + a_row) * 72 + kc + a_koff]));
                ldsm_x4(af1, smem_u32(&A[(mb + 16 + a_row) * 72 + kc + a_koff]));
                ldsm_x4(bf0, smem_u32(&W[(nb + b_n) * 72 + kc + b_koff]));
                ldsm_x4(bf1, smem_u32(&W[(nb + 16 + b_n) * 72 + kc + b_koff]));
                mma_bf16(acc[0][0], af0, bf0[0], bf0[1]);
                mma_bf16(acc[0][1], af0, bf0[2], bf0[3]);
                mma_bf16(acc[0][2], af0, bf1[0], bf1[1]);
                mma_bf16(acc[0][3], af0, bf1[2], bf1[3]);
                mma_bf16(acc[1][0], af1, bf0[0], bf0[1]);
                mma_bf16(acc[1][1], af1, bf0[2], bf0[3]);
                mma_bf16(acc[1][2], af1, bf1[0], bf1[1]);
                mma_bf16(acc[1][3], af1, bf1[2], bf1[3]);
            }
        }
    }

    __syncthreads();
    // stage C
    int g = lane >> 2, tg = lane & 3;
#pragma unroll
    for (int mi = 0; mi < 2; mi++) {
        int row = mb + mi * 16 + g;
#pragma unroll
        for (int nj = 0; nj < 4; nj++) {
            int col = nb + nj * 8 + tg * 2;
            *(float2*)&Cs[row * 68 + col]       = make_float2(acc[mi][nj][0], acc[mi][nj][1]);
            *(float2*)&Cs[(row + 8) * 68 + col] = make_float2(acc[mi][nj][2], acc[mi][nj][3]);
        }
    }
    __syncthreads();

    // write raw x1
#pragma unroll
    for (int e4 = t; e4 < 2048; e4 += 256) {
        int r = e4 >> 4, cg = e4 & 15;
        int row = row0 + r;
        if (row < Nv)
            *(float4*)&g_x1[(size_t)row * 64 + cg * 4] = *(const float4*)&Cs[r * 68 + cg * 4];
    }

    // fused stats1 (rows beyond Nv are zero in Cs -> contribute nothing)
    int b0 = s_b[0];
    bool fast = (s_b[127] == b0) || (row0 + 127 >= Nv && b0 == s_b[(Nv - 1) - row0 < 0 ? 0 : (Nv - 1) - row0]);
    if (s_b[127] == b0) fast = true; else if (row0 + 127 >= Nv) {
        // tail block: check up to last valid row
        int lastr = Nv - 1 - row0;
        fast = (lastr >= 0 && s_b[lastr] == b0);
    } else fast = false;

    if (fast) {
        int col = t & 63, rg = t >> 6;
        float s = 0.f, q = 0.f;
#pragma unroll 8
        for (int r = rg * 32; r < rg * 32 + 32; r++) {
            float v = Cs[r * 68 + col];
            s += v; q += v * v;
        }
        sred[rg * 64 + col] = s;
        qred[rg * 64 + col] = q;
        __syncthreads();
        if (t < 64) {
            float v = sred[t] + sred[64 + t] + sred[128 + t] + sred[192 + t];
            atomicAdd(&gsum[b0 * 64 + t], v);
        } else if (t < 128) {
            int c = t - 64;
            float v = qred[c] + qred[64 + c] + qred[128 + c] + qred[192 + c];
            atomicAdd(&gsq[b0 * 64 + c], v);
        }
    } else {
        for (int e = t; e < 8192; e += 256) {
            int r = e >> 6, c = e & 63;
            if (row0 + r < Nv) {
                float v = Cs[r * 68 + c];
                int b = s_b[r];
                atomicAdd(&gsum[b * 64 + c], v);
                atomicAdd(&gsq[b * 64 + c], v * v);
            }
        }
    }
}

// ---------------- finalize stats ---------------------------------------------
__global__ void finalize_kernel(float* sumArr, float* sqArr, int C) {
    int i = blockIdx.x * blockDim.x + threadIdx.x;
    if (i < Bb * C) {
        float cnt = (float)g_cnt[i / C];
        float mean = sumArr[i] / cnt;
        float var = sqArr[i] / cnt - mean * mean;
        sumArr[i] = mean;
        sqArr[i] = rsqrtf(fmaxf(var, 0.f) + EPSf);
    }
}

// ---------------- norm1 + relu + bf16 hi/lo split -----------------------------
__global__ void __launch_bounds__(256) norm_split_kernel(const int* __restrict__ batch_idx,
                                                         const float* __restrict__ mean,
                                                         const float* __restrict__ inv) {
    long long total = (long long)Nv * 16;
    long long i = (long long)blockIdx.x * blockDim.x + threadIdx.x;
    long long stride = (long long)gridDim.x * blockDim.x;
    for (; i < total; i += stride) {
        int row = (int)(i >> 4);
        int cg = (int)(i & 15);
        int b = batch_idx[row];
        float4 v = ((const float4*)g_x1)[i];
        float4 m = ((const float4*)mean)[b * 16 + cg];
        float4 s = ((const float4*)inv)[b * 16 + cg];
        float a0 = fmaxf((v.x - m.x) * s.x, 0.f);
        float a1 = fmaxf((v.y - m.y) * s.y, 0.f);
        float a2 = fmaxf((v.z - m.z) * s.z, 0.f);
        float a3 = fmaxf((v.w - m.w) * s.w, 0.f);
        __nv_bfloat16 h0, h1, h2, h3, l0, l1, l2, l3;
        split_bf(a0, h0, l0); split_bf(a1, h1, l1);
        split_bf(a2, h2, l2); split_bf(a3, h3, l3);
        __nv_bfloat162* ph = (__nv_bfloat162*)&g_x1h[(size_t)row * 64 + cg * 4];
        __nv_bfloat162* pl = (__nv_bfloat162*)&g_x1l[(size_t)row * 64 + cg * 4];
        ph[0] = __nv_bfloat162(h0, h1);
        ph[1] = __nv_bfloat162(h2, h3);
        pl[0] = __nv_bfloat162(l0, l1);
        pl[1] = __nv_bfloat162(l2, l3);
    }
}

// ---------------- conv2: mma.sync bf16 3-term gather-GEMM-scatter ------------
__global__ void __launch_bounds__(256) conv2_mma_kernel(const int* __restrict__ in_idx,
                                                        const int* __restrict__ out_idx) {
    extern __shared__ __align__(16) char sm2[];
    __nv_bfloat16* Ah = (__nv_bfloat16*)sm2;             // 18432 B
    __nv_bfloat16* Al = (__nv_bfloat16*)(sm2 + 18432);
    __nv_bfloat16* Wh = (__nv_bfloat16*)(sm2 + 36864);   // 9216 B
    __nv_bfloat16* Wl = (__nv_bfloat16*)(sm2 + 46080);
    float* Cs = (float*)sm2;
    __shared__ int s_in[128], s_out[128];

    int t = threadIdx.x;
    int k = blockIdx.y;
    int m0 = blockIdx.x * 128;

    if (t < 128) {
        int p = m0 + t;
        bool v = (p < Mm);
        s_in[t]  = v ? in_idx[(size_t)k * Mm + p] : -1;
        s_out[t] = v ? out_idx[(size_t)k * Mm + p] : -1;
    }

    // pre-split W2 slice: [d][c] bf16, pad to 72
    const __nv_bfloat16* Wkh = g_W2h + (size_t)k * 4096;
    const __nv_bfloat16* Wkl = g_W2l + (size_t)k * 4096;
#pragma unroll
    for (int e4 = t; e4 < 512; e4 += 256) {
        int d = e4 >> 3, q = e4 & 7;
        *(uint4*)&Wh[d * 72 + q * 8] = *(const uint4*)&Wkh[d * 64 + q * 8];
        *(uint4*)&Wl[d * 72 + q * 8] = *(const uint4*)&Wkl[d * 64 + q * 8];
    }
    __syncthreads();

#pragma unroll
    for (int e = t; e < 1024; e += 256) {
        int r = e >> 3, q = e & 7;
        int src = s_in[r];
        uint4 vh = make_uint4(0u, 0u, 0u, 0u);
        uint4 vl = vh;
        if (src >= 0) {
            vh = ((const uint4*)(g_x1h + (size_t)src * 64))[q];
            vl = ((const uint4*)(g_x1l + (size_t)src * 64))[q];
        }
        *(uint4*)&Ah[r * 72 + q * 8] = vh;
        *(uint4*)&Al[r * 72 + q * 8] = vl;
    }
    __syncthreads();

    int wid = t >> 5, lane = t & 31;
    int mb = (wid >> 1) * 32;
    int nb = (wid & 1) * 32;

    float acc[2][4][4];
#pragma unroll
    for (int i = 0; i < 2; i++)
#pragma unroll
        for (int j = 0; j < 4; j++)
#pragma unroll
            for (int q = 0; q < 4; q++) acc[i][j][q] = 0.f;

    int a_row = lane & 15;
    int a_koff = (lane >> 4) << 3;
    int b_n = (lane & 7) + ((lane >> 4) << 3);
    int b_koff = ((lane >> 3) & 1) << 3;

#pragma unroll
    for (int term = 0; term < 3; term++) {
        const __nv_bfloat16* A = (term == 1) ? Al : Ah;
        const __nv_bfloat16* W = (term == 2) ? Wl : Wh;
#pragma unroll
        for (int ks = 0; ks < 4; ks++) {
            int k0 = ks * 16;
            uint32_t af0[4], af1[4], bf0[4], bf1[4];
            ldsm_x4(af0, smem_u32(&A[(mb + a_row) * 72 + k0 + a_koff]));
            ldsm_x4(af1, smem_u32(&A[(mb + 16 + a_row) * 72 + k0 + a_koff]));
            ldsm_x4(bf0, smem_u32(&W[(nb + b_n) * 72 + k0 + b_koff]));
            ldsm_x4(bf1, smem_u32(&W[(nb + 16 + b_n) * 72 + k0 + b_koff]));
            mma_bf16(acc[0][0], af0, bf0[0], bf0[1]);
            mma_bf16(acc[0][1], af0, bf0[2], bf0[3]);
            mma_bf16(acc[0][2], af0, bf1[0], bf1[1]);
            mma_bf16(acc[0][3], af0, bf1[2], bf1[3]);
            mma_bf16(acc[1][0], af1, bf0[0], bf0[1]);
            mma_bf16(acc[1][1], af1, bf0[2], bf0[3]);
            mma_bf16(acc[1][2], af1, bf1[0], bf1[1]);
            mma_bf16(acc[1][3], af1, bf1[2], bf1[3]);
        }
    }

    __syncthreads();

    int g = lane >> 2, tg = lane & 3;
#pragma unroll
    for (int mi = 0; mi < 2; mi++) {
        int row = mb + mi * 16 + g;
#pragma unroll
        for (int nj = 0; nj < 4; nj++) {
            int col = nb + nj * 8 + tg * 2;
            *(float2*)&Cs[row * 68 + col]       = make_float2(acc[mi][nj][0], acc[mi][nj][1]);
            *(float2*)&Cs[(row + 8) * 68 + col] = make_float2(acc[mi][nj][2], acc[mi][nj][3]);
        }
    }
    __syncthreads();

    {
        int r = t >> 1, h = (t & 1) * 32;
        int dst = s_out[r];
        if (dst >= 0) {
            float* p = g_x2 + (size_t)dst * 64 + h;
            const float* c = &Cs[r * 68 + h];
#pragma unroll
            for (int j = 0; j < 8; j++)
                red_v4(p + j * 4, c[j * 4], c[j * 4 + 1], c[j * 4 + 2], c[j * 4 + 3]);
        }
    }
}

// ---------------- stats2 ------------------------------------------------------
__global__ void __launch_bounds__(256) stats2_kernel(const float* __restrict__ x,
                                                     const int* __restrict__ batch_idx,
                                                     float* __restrict__ gsum,
                                                     float* __restrict__ gsq) {
    __shared__ float sm[2048];
    int t = threadIdx.x;
    int r0 = blockIdx.x * 128;
    int r1 = min(r0 + 128, Nv);
    int cg = t & 15, rg = t >> 4;
    int b0 = batch_idx[r0], b1 = batch_idx[r1 - 1];

    if (b0 == b1) {
        float4 s = make_float4(0.f, 0.f, 0.f, 0.f);
        float4 q = make_float4(0.f, 0.f, 0.f, 0.f);
#pragma unroll 4
        for (int r = r0 + rg; r < r1; r += 16) {
            float4 v = *(const float4*)&x[(size_t)r * 64 + cg * 4];
            s.x += v.x; s.y += v.y; s.z += v.z; s.w += v.w;
            q.x += v.x * v.x; q.y += v.y * v.y; q.z += v.z * v.z; q.w += v.w * v.w;
        }
        *(float4*)&sm[rg * 64 + cg * 4]        = s;
        *(float4*)&sm[1024 + rg * 64 + cg * 4] = q;
        __syncthreads();
        if (t < 64) {
            float v = 0.f;
#pragma unroll
            for (int u = 0; u < 16; u++) v += sm[u * 64 + t];
            atomicAdd(&gsum[b0 * 64 + t], v);
        } else if (t < 128) {
            int c = t - 64;
            float v = 0.f;
#pragma unroll
            for (int u = 0; u < 16; u++) v += sm[1024 + u * 64 + c];
            atomicAdd(&gsq[b0 * 64 + c], v);
        }
    } else {
        for (int i = t; i < 512; i += 256) sm[i] = 0.f;
        __syncthreads();
        for (int r = r0 + rg; r < r1; r += 16) {
            int b = batch_idx[r];
            float4 v = *(const float4*)&x[(size_t)r * 64 + cg * 4];
            atomicAdd(&sm[b * 64 + cg * 4], v.x);
            atomicAdd(&sm[b * 64 + cg * 4 + 1], v.y);
            atomicAdd(&sm[b * 64 + cg * 4 + 2], v.z);
            atomicAdd(&sm[b * 64 + cg * 4 + 3], v.w);
            atomicAdd(&sm[256 + b * 64 + cg * 4], v.x * v.x);
            atomicAdd(&sm[256 + b * 64 + cg * 4 + 1], v.y * v.y);
            atomicAdd(&sm[256 + b * 64 + cg * 4 + 2], v.z * v.z);
            atomicAdd(&sm[256 + b * 64 + cg * 4 + 3], v.w * v.w);
        }
        __syncthreads();
        if (t < 256) {
            if (sm[t] != 0.f)       atomicAdd(&gsum[t], sm[t]);
            if (sm[256 + t] != 0.f) atomicAdd(&gsq[t], sm[256 + t]);
        }
    }
}

// ---------------- conv3: mma.sync, gather(norm2+relu) -> GEMM -> out + stats3 -
// grid (1563, 2); 256 thr (8 warps: 4 m x 2 n, warp tile 32x64); C block 128x128
__global__ void __launch_bounds__(256) conv3_mma_kernel(float* __restrict__ out,
                                                        const int* __restrict__ batch_idx,
                                                        const float* __restrict__ mean2,
                                                        const float* __restrict__ inv2,
                                                        float* __restrict__ gsum,
                                                        float* __restrict__ gsq) {
    extern __shared__ __align__(16) char sm3[];
    __nv_bfloat16* Ah = (__nv_bfloat16*)sm3;             // 128x72 = 18432
    __nv_bfloat16* Al = (__nv_bfloat16*)(sm3 + 18432);
    __nv_bfloat16* Wh = (__nv_bfloat16*)(sm3 + 36864);   // 128x72 = 18432
    __nv_bfloat16* Wl = (__nv_bfloat16*)(sm3 + 55296);   // -> 73728
    float* Cs = (float*)sm3;                             // overlay 128x132 = 67584 B
    __shared__ int s_b[128];
    __shared__ float sm_m[256], sm_i[256];
    __shared__ float sred[256], qred[256];

    int t = threadIdx.x;
    int row0 = blockIdx.x * 128;
    int col0 = blockIdx.y * 128;

    if (t < 128) {
        int r = row0 + t;
        s_b[t] = (r < Nv) ? batch_idx[r] : -1;
    }
    if (t < 256) { sm_m[t] = mean2[t]; sm_i[t] = inv2[t]; }
    __syncthreads();

    // gather + norm2 + relu + split
#pragma unroll
    for (int e4 = t; e4 < 2048; e4 += 256) {
        int r = e4 >> 4, cg = e4 & 15;
        int row = row0 + r;
        float4 v = make_float4(0.f, 0.f, 0.f, 0.f);
        if (row < Nv) {
            float4 x = *(const float4*)&g_x2[(size_t)row * 64 + cg * 4];
            int b = s_b[r];
            float4 m = *(const float4*)&sm_m[b * 64 + cg * 4];
            float4 iv = *(const float4*)&sm_i[b * 64 + cg * 4];
            v.x = fmaxf((x.x - m.x) * iv.x, 0.f);
            v.y = fmaxf((x.y - m.y) * iv.y, 0.f);
            v.z = fmaxf((x.z - m.z) * iv.z, 0.f);
            v.w = fmaxf((x.w - m.w) * iv.w, 0.f);
        }
        __nv_bfloat16 h0, h1, h2, h3, l0, l1, l2, l3;
        split_bf(v.x, h0, l0); split_bf(v.y, h1, l1);
        split_bf(v.z, h2, l2); split_bf(v.w, h3, l3);
        __nv_bfloat162* ph = (__nv_bfloat162*)&Ah[r * 72 + cg * 4];
        __nv_bfloat162* pl = (__nv_bfloat162*)&Al[r * 72 + cg * 4];
        ph[0] = __nv_bfloat162(h0, h1); ph[1] = __nv_bfloat162(h2, h3);
        pl[0] = __nv_bfloat162(l0, l1); pl[1] = __nv_bfloat162(l2, l3);
    }
    // W3 slice [col0..col0+127][64] pre-split
#pragma unroll
    for (int e4 = t; e4 < 1024; e4 += 256) {
        int n = e4 >> 3, q = e4 & 7;
        *(uint4*)&Wh[n * 72 + q * 8] = *(const uint4*)&g_W3h[(col0 + n) * 64 + q * 8];
        *(uint4*)&Wl[n * 72 + q * 8] = *(const uint4*)&g_W3l[(col0 + n) * 64 + q * 8];
    }
    __syncthreads();

    int wid = t >> 5, lane = t & 31;
    int mb = (wid >> 1) * 32;   // 4 m warps
    int nb = (wid & 1) * 64;    // 2 n warps, 64 cols each

    float acc[2][8][4];
#pragma unroll
    for (int i = 0; i < 2; i++)
#pragma unroll
        for (int j = 0; j < 8; j++)
#pragma unroll
            for (int q = 0; q < 4; q++) acc[i][j][q] = 0.f;

    int a_row = lane & 15;
    int a_koff = (lane >> 4) << 3;
    int b_n = (lane & 7) + ((lane >> 4) << 3);
    int b_koff = ((lane >> 3) & 1) << 3;

#pragma unroll
    for (int term = 0; term < 3; term++) {
        const __nv_bfloat16* A = (term == 1) ? Al : Ah;
        const __nv_bfloat16* W = (term == 2) ? Wl : Wh;
#pragma unroll
        for (int ks = 0; ks < 4; ks++) {
            int k0 = ks * 16;
            uint32_t af0[4], af1[4], bfr[4][4];
            ldsm_x4(af0, smem_u32(&A[(mb + a_row) * 72 + k0 + a_koff]));
            ldsm_x4(af1, smem_u32(&A[(mb + 16 + a_row) * 72 + k0 + a_koff]));
#pragma unroll
            for (int gb = 0; gb < 4; gb++)
                ldsm_x4(bfr[gb], smem_u32(&W[(nb + gb * 16 + b_n) * 72 + k0 + b_koff]));
#pragma unroll
            for (int nj = 0; nj < 8; nj++) {
                uint32_t bb0 = bfr[nj >> 1][(nj & 1) * 2];
                uint32_t bb1 = bfr[nj >> 1][(nj & 1) * 2 + 1];
                mma_bf16(acc[0][nj], af0, bb0, bb1);
                mma_bf16(acc[1][nj], af1, bb0, bb1);
            }
        }
    }

    __syncthreads();
    // stage C (LDC = 132)
    int g = lane >> 2, tg = lane & 3;
#pragma unroll
    for (int mi = 0; mi < 2; mi++) {
        int row = mb + mi * 16 + g;
#pragma unroll
        for (int nj = 0; nj < 8; nj++) {
            int col = nb + nj * 8 + tg * 2;
            *(float2*)&Cs[row * 132 + col]       = make_float2(acc[mi][nj][0], acc[mi][nj][1]);
            *(float2*)&Cs[(row + 8) * 132 + col] = make_float2(acc[mi][nj][2], acc[mi][nj][3]);
        }
    }
    __syncthreads();

    // write out
#pragma unroll
    for (int e4 = t; e4 < 4096; e4 += 256) {
        int r = e4 >> 5, c4 = e4 & 31;
        int row = row0 + r;
        if (row < Nv)
            *(float4*)&out[(size_t)row * 256 + col0 + c4 * 4] = *(const float4*)&Cs[r * 132 + c4 * 4];
    }

    // fused stats3
    int b0 = s_b[0];
    bool fast;
    if (s_b[127] == b0) fast = true;
    else if (row0 + 127 >= Nv) {
        int lastr = Nv - 1 - row0;
        fast = (lastr >= 0 && s_b[lastr] == b0);
    } else fast = false;

    if (fast) {
        int col = t & 127, rg = t >> 7;
        float s = 0.f, q = 0.f;
#pragma unroll 8
        for (int r = rg * 64; r < rg * 64 + 64; r++) {
            float v = Cs[r * 132 + col];
            s += v; q += v * v;
        }
        sred[rg * 128 + col] = s;
        qred[rg * 128 + col] = q;
        __syncthreads();
        if (t < 128) {
            atomicAdd(&gsum[b0 * 256 + col0 + t], sred[t] + sred[128 + t]);
        } else {
            int c = t - 128;
            atomicAdd(&gsq[b0 * 256 + col0 + c], qred[c] + qred[128 + c]);
        }
    } else {
        for (int e = t; e < 16384; e += 256) {
            int r = e >> 7, c = e & 127;
            if (row0 + r < Nv) {
                float v = Cs[r * 132 + c];
                int b = s_b[r];
                atomicAdd(&gsum[b * 256 + col0 + c], v);
                atomicAdd(&gsq[b * 256 + col0 + c], v * v);
            }
        }
    }
}

// ---------------- final: normalize3 + residual + relu ------------------------
__global__ void final_kernel(float* __restrict__ y,
                             const float* __restrict__ feats,
                             const int* __restrict__ batch_idx,
                             const float* __restrict__ mean,
                             const float* __restrict__ inv) {
    const int C4 = 64;
    long long total = (long long)Nv * C4;
    long long i = (long long)blockIdx.x * blockDim.x + threadIdx.x;
    long long stride = (long long)gridDim.x * blockDim.x;
    for (; i < total; i += stride) {
        int row = (int)(i / C4);
        int cg = (int)(i % C4);
        int b = batch_idx[row];
        float4 v = ((float4*)y)[i];
        float4 f = ((const float4*)feats)[i];
        float4 m = ((const float4*)mean)[b * C4 + cg];
        float4 sv = ((const float4*)inv)[b * C4 + cg];
        v.x = fmaxf((v.x - m.x) * sv.x + f.x, 0.f);
        v.y = fmaxf((v.y - m.y) * sv.y + f.y, 0.f);
        v.z = fmaxf((v.z - m.z) * sv.z + f.z, 0.f);
        v.w = fmaxf((v.w - m.w) * sv.w + f.w, 0.f);
        ((float4*)y)[i] = v;
    }
}

// ---------------- launch -----------------------------------------------------
extern "C" void kernel_launch(void* const* d_in, const int* in_sizes, int n_in,
                              void* d_out, int out_size) {
    const float* feats     = (const float*)d_in[0];
    const float* W1        = (const float*)d_in[1];
    const float* W2        = (const float*)d_in[2];
    const float* W3        = (const float*)d_in[3];
    const int*   in_idx    = (const int*)d_in[4];
    const int*   out_idx   = (const int*)d_in[5];
    const int*   batch_idx = (const int*)d_in[6];
    float* out = (float*)d_out;

    float *p_x2, *p_sum1, *p_sq1, *p_sum2, *p_sq2, *p_sum3, *p_sq3;
    cudaGetSymbolAddress((void**)&p_x2, g_x2);
    cudaGetSymbolAddress((void**)&p_sum1, g_sum1);
    cudaGetSymbolAddress((void**)&p_sq1, g_sq1);
    cudaGetSymbolAddress((void**)&p_sum2, g_sum2);
    cudaGetSymbolAddress((void**)&p_sq2, g_sq2);
    cudaGetSymbolAddress((void**)&p_sum3, g_sum3);
    cudaGetSymbolAddress((void**)&p_sq3, g_sq3);

    const int smem1 = 55296;
    const int smem2 = 55296;
    const int smem3 = 73728;
    cudaFuncSetAttribute(conv1_mma_kernel, cudaFuncAttributeMaxDynamicSharedMemorySize, smem1);
    cudaFuncSetAttribute(conv2_mma_kernel, cudaFuncAttributeMaxDynamicSharedMemorySize, smem2);
    cudaFuncSetAttribute(conv3_mma_kernel, cudaFuncAttributeMaxDynamicSharedMemorySize, smem3);

    zero_kernel<<<2048, 256>>>();
    count_kernel<<<391, 256>>>(batch_idx);
    wsplit_kernel<<<(16384 + Kk * 4096 + 16384 + 255) / 256, 256>>>(W1, W2, W3);

    // conv1 (tensor) + fused stats1
    conv1_mma_kernel<<<(Nv + 127) / 128, 256, smem1>>>(feats, batch_idx, p_sum1, p_sq1);
    finalize_kernel<<<1, 256>>>(p_sum1, p_sq1, 64);

    // norm1 + relu + bf16 hi/lo split
    norm_split_kernel<<<4096, 256>>>(batch_idx, p_sum1, p_sq1);

    // conv2 (tensor) + scatter
    dim3 g2((Mm + 127) / 128, Kk);
    conv2_mma_kernel<<<g2, 256, smem2>>>(in_idx, out_idx);
    stats2_kernel<<<(Nv + 127) / 128, 256>>>(p_x2, batch_idx, p_sum2, p_sq2);
    finalize_kernel<<<1, 256>>>(p_sum2, p_sq2, 64);

    // conv3 (tensor, norm2+relu fused) + fused stats3
    dim3 g3((Nv + 127) / 128, 2);
    conv3_mma_kernel<<<g3, 256, smem3>>>(out, batch_idx, p_sum2, p_sq2, p_sum3, p_sq3);
    finalize_kernel<<<4, 256>>>(p_sum3, p_sq3, 256);

    final_kernel<<<16384, 256>>>(out, feats, batch_idx, p_sum3, p_sq3);
}

// round 6
// speedup vs baseline: 1.7768x; 1.0660x over previous
#include <cuda_runtime.h>
#include <cuda_bf16.h>
#include <cstdint>

#define Nv   200000
#define Kk   27
#define Mm   100000
#define Bb   4
#define EPSf 1e-5f

// ---------------- scratch (device globals — no runtime allocation) ----------
__device__ float g_x1[(size_t)Nv * 64];          // conv1 out (raw, pre-norm)
__device__ float g_x2[(size_t)Nv * 64];          // conv2 accum (raw, pre-norm)
__device__ __nv_bfloat16 g_x1h[(size_t)Nv * 64]; // normalized x1, bf16 hi
__device__ __nv_bfloat16 g_x1l[(size_t)Nv * 64]; // normalized x1, bf16 lo
__device__ __nv_bfloat16 g_W1h[64 * 256],  g_W1l[64 * 256];    // [d][c] col-major
__device__ __nv_bfloat16 g_W2h[Kk * 4096], g_W2l[Kk * 4096];   // [k][d][c]
__device__ __nv_bfloat16 g_W3h[256 * 64],  g_W3l[256 * 64];    // [n][c]
__device__ float g_sum1[Bb * 64], g_sq1[Bb * 64];
__device__ float g_sum2[Bb * 64], g_sq2[Bb * 64];
__device__ float g_sum3[Bb * 256], g_sq3[Bb * 256];
__device__ int   g_cnt[Bb];

// ---------------- helpers -----------------------------------------------------
__device__ __forceinline__ void red_v4(float* p, float a, float b, float c, float d) {
    asm volatile("red.global.add.v4.f32 [%0], {%1,%2,%3,%4};"
                 :: "l"(p), "f"(a), "f"(b), "f"(c), "f"(d) : "memory");
}
__device__ __forceinline__ uint32_t smem_u32(const void* p) {
    uint32_t a;
    asm("{ .reg .u64 t; cvta.to.shared.u64 t, %1; cvt.u32.u64 %0, t; }"
        : "=r"(a) : "l"(p));
    return a;
}
__device__ __forceinline__ void ldsm_x4(uint32_t* r, uint32_t addr) {
    asm volatile("ldmatrix.sync.aligned.m8n8.x4.shared.b16 {%0,%1,%2,%3}, [%4];"
        : "=r"(r[0]), "=r"(r[1]), "=r"(r[2]), "=r"(r[3]) : "r"(addr));
}
__device__ __forceinline__ void mma_bf16(float* c, const uint32_t* a,
                                         uint32_t b0, uint32_t b1) {
    asm volatile("mma.sync.aligned.m16n8k16.row.col.f32.bf16.bf16.f32 "
        "{%0,%1,%2,%3}, {%4,%5,%6,%7}, {%8,%9}, {%0,%1,%2,%3};"
        : "+f"(c[0]), "+f"(c[1]), "+f"(c[2]), "+f"(c[3])
        : "r"(a[0]), "r"(a[1]), "r"(a[2]), "r"(a[3]), "r"(b0), "r"(b1));
}
__device__ __forceinline__ void split_bf(float a, __nv_bfloat16& h, __nv_bfloat16& l) {
    h = __float2bfloat16(a);
    l = __float2bfloat16(a - __bfloat162float(h));
}

// ---------------- zero scratch ----------------------------------------------
__global__ void zero_kernel() {
    long long i = (long long)blockIdx.x * blockDim.x + threadIdx.x;
    long long stride = (long long)gridDim.x * blockDim.x;
    const long long total4 = (long long)Nv * 16;
    float4* p = reinterpret_cast<float4*>(g_x2);
    float4 z = make_float4(0.f, 0.f, 0.f, 0.f);
    for (long long j = i; j < total4; j += stride) p[j] = z;
    if (i < Bb * 64)  { g_sum1[i] = 0.f; g_sq1[i] = 0.f; g_sum2[i] = 0.f; g_sq2[i] = 0.f; }
    if (i < Bb * 256) { g_sum3[i] = 0.f; g_sq3[i] = 0.f; }
    if (i < Bb) g_cnt[i] = 0;
}

// ---------------- per-batch counts ------------------------------------------
__global__ void count_kernel(const int* __restrict__ batch_idx) {
    __shared__ int s[Bb];
    if (threadIdx.x < Bb) s[threadIdx.x] = 0;
    __syncthreads();
    int i = blockIdx.x * blockDim.x + threadIdx.x;
    int stride = gridDim.x * blockDim.x;
    for (int j = i; j < Nv; j += stride) atomicAdd(&s[batch_idx[j]], 1);
    __syncthreads();
    if (threadIdx.x < Bb) atomicAdd(&g_cnt[threadIdx.x], s[threadIdx.x]);
}

// ---------------- weight pre-split (col-major bf16 hi/lo) --------------------
__global__ void wsplit_kernel(const float* __restrict__ W1,
                              const float* __restrict__ W2,
                              const float* __restrict__ W3) {
    int i = blockIdx.x * blockDim.x + threadIdx.x;
    if (i < 16384) {                       // W1: [d=64][c=256] <- W1[c*64+d]
        int d = i >> 8, c = i & 255;
        __nv_bfloat16 h, l;
        split_bf(W1[c * 64 + d], h, l);
        g_W1h[i] = h; g_W1l[i] = l;
    } else if (i < 16384 + Kk * 4096) {    // W2: [k][d=64][c=64] <- W2[k][c][d]
        int j = i - 16384;
        int kk = j >> 12, r = j & 4095;
        int d = r >> 6, c = r & 63;
        __nv_bfloat16 h, l;
        split_bf(W2[kk * 4096 + c * 64 + d], h, l);
        g_W2h[j] = h; g_W2l[j] = l;
    } else if (i < 16384 + Kk * 4096 + 16384) {  // W3: [n=256][c=64] <- W3[c*256+n]
        int j = i - 16384 - Kk * 4096;
        int n = j >> 6, c = j & 63;
        __nv_bfloat16 h, l;
        split_bf(W3[c * 256 + n], h, l);
        g_W3h[j] = h; g_W3l[j] = l;
    }
}

// ---------------- conv1: mma.sync, x1 = feats @ W1, fused stats1 --------------
// grid 1563; 256 thr (8 warps 4x2); tile M=128, N=64, K=256 (4 chunks)
__global__ void __launch_bounds__(256, 2) conv1_mma_kernel(const float* __restrict__ feats,
                                                           const int* __restrict__ batch_idx,
                                                           float* __restrict__ gsum,
                                                           float* __restrict__ gsq) {
    extern __shared__ __align__(16) char sm1[];
    __nv_bfloat16* Ah = (__nv_bfloat16*)sm1;             // 128x72 = 18432 B
    __nv_bfloat16* Al = (__nv_bfloat16*)(sm1 + 18432);   // 18432 B
    __nv_bfloat16* Wh = (__nv_bfloat16*)(sm1 + 36864);   // 64x72 = 9216 B
    __nv_bfloat16* Wl = (__nv_bfloat16*)(sm1 + 46080);   // 9216 B -> 55296
    float* Cs = (float*)sm1;                             // overlay 128x68 f32
    __shared__ int s_b[128];
    __shared__ float sred[256], qred[256];

    int t = threadIdx.x;
    int row0 = blockIdx.x * 128;
    if (t < 128) {
        int r = row0 + t;
        s_b[t] = (r < Nv) ? batch_idx[r] : -1;
    }

    int wid = t >> 5, lane = t & 31;
    int mb = (wid >> 1) * 32;
    int nb = (wid & 1) * 32;
    int a_row = lane & 15;
    int a_koff = (lane >> 4) << 3;
    int b_n = (lane & 7) + ((lane >> 4) << 3);
    int b_koff = ((lane >> 3) & 1) << 3;

    float acc[2][4][4];
#pragma unroll
    for (int i = 0; i < 2; i++)
#pragma unroll
        for (int j = 0; j < 4; j++)
#pragma unroll
            for (int q = 0; q < 4; q++) acc[i][j][q] = 0.f;

    for (int k0 = 0; k0 < 256; k0 += 64) {
        __syncthreads();
        // A chunk: load fp32, split bf16 hi/lo
#pragma unroll
        for (int e4 = t; e4 < 2048; e4 += 256) {
            int r = e4 >> 4, cg = e4 & 15;
            int row = row0 + r;
            float4 v = make_float4(0.f, 0.f, 0.f, 0.f);
            if (row < Nv) v = *(const float4*)&feats[(size_t)row * 256 + k0 + cg * 4];
            __nv_bfloat16 h0, h1, h2, h3, l0, l1, l2, l3;
            split_bf(v.x, h0, l0); split_bf(v.y, h1, l1);
            split_bf(v.z, h2, l2); split_bf(v.w, h3, l3);
            __nv_bfloat162* ph = (__nv_bfloat162*)&Ah[r * 72 + cg * 4];
            __nv_bfloat162* pl = (__nv_bfloat162*)&Al[r * 72 + cg * 4];
            ph[0] = __nv_bfloat162(h0, h1); ph[1] = __nv_bfloat162(h2, h3);
            pl[0] = __nv_bfloat162(l0, l1); pl[1] = __nv_bfloat162(l2, l3);
        }
        // W chunk from pre-split
#pragma unroll
        for (int e4 = t; e4 < 512; e4 += 256) {
            int d = e4 >> 3, q = e4 & 7;
            *(uint4*)&Wh[d * 72 + q * 8] = *(const uint4*)&g_W1h[d * 256 + k0 + q * 8];
            *(uint4*)&Wl[d * 72 + q * 8] = *(const uint4*)&g_W1l[d * 256 + k0 + q * 8];
        }
        __syncthreads();

#pragma unroll
        for (int term = 0; term < 3; term++) {
            const __nv_bfloat16* A = (term == 1) ? Al : Ah;
            const __nv_bfloat16* W = (term == 2) ? Wl : Wh;
#pragma unroll
            for (int ks = 0; ks < 4; ks++) {
                int kc = ks * 16;
                uint32_t af0[4], af1[4], bf0[4], bf1[4];
                ldsm_x4(af0, smem_u32(&A[(mb + a_row) * 72 + kc + a_koff]));
                ldsm_x4(af1, smem_u32(&A[(mb + 16 + a_row) * 72 + kc + a_koff]));
                ldsm_x4(bf0, smem_u32(&W[(nb + b_n) * 72 + kc + b_koff]));
                ldsm_x4(bf1, smem_u32(&W[(nb + 16 + b_n) * 72 + kc + b_koff]));
                mma_bf16(acc[0][0], af0, bf0[0], bf0[1]);
                mma_bf16(acc[0][1], af0, bf0[2], bf0[3]);
                mma_bf16(acc[0][2], af0, bf1[0], bf1[1]);
                mma_bf16(acc[0][3], af0, bf1[2], bf1[3]);
                mma_bf16(acc[1][0], af1, bf0[0], bf0[1]);
                mma_bf16(acc[1][1], af1, bf0[2], bf0[3]);
                mma_bf16(acc[1][2], af1, bf1[0], bf1[1]);
                mma_bf16(acc[1][3], af1, bf1[2], bf1[3]);
            }
        }
    }

    __syncthreads();
    // stage C
    int g = lane >> 2, tg = lane & 3;
#pragma unroll
    for (int mi = 0; mi < 2; mi++) {
        int row = mb + mi * 16 + g;
#pragma unroll
        for (int nj = 0; nj < 4; nj++) {
            int col = nb + nj * 8 + tg * 2;
            *(float2*)&Cs[row * 68 + col]       = make_float2(acc[mi][nj][0], acc[mi][nj][1]);
            *(float2*)&Cs[(row + 8) * 68 + col] = make_float2(acc[mi][nj][2], acc[mi][nj][3]);
        }
    }
    __syncthreads();

    // write raw x1
#pragma unroll
    for (int e4 = t; e4 < 2048; e4 += 256) {
        int r = e4 >> 4, cg = e4 & 15;
        int row = row0 + r;
        if (row < Nv)
            *(float4*)&g_x1[(size_t)row * 64 + cg * 4] = *(const float4*)&Cs[r * 68 + cg * 4];
    }

    // fused stats1 (rows beyond Nv are zero in Cs -> contribute nothing)
    int b0 = s_b[0];
    bool fast;
    if (s_b[127] == b0) fast = true;
    else if (row0 + 127 >= Nv) {
        int lastr = Nv - 1 - row0;
        fast = (lastr >= 0 && s_b[lastr] == b0);
    } else fast = false;

    if (fast) {
        int col = t & 63, rg = t >> 6;
        float s = 0.f, q = 0.f;
#pragma unroll 8
        for (int r = rg * 32; r < rg * 32 + 32; r++) {
            float v = Cs[r * 68 + col];
            s += v; q += v * v;
        }
        sred[rg * 64 + col] = s;
        qred[rg * 64 + col] = q;
        __syncthreads();
        if (t < 64) {
            float v = sred[t] + sred[64 + t] + sred[128 + t] + sred[192 + t];
            atomicAdd(&gsum[b0 * 64 + t], v);
        } else if (t < 128) {
            int c = t - 64;
            float v = qred[c] + qred[64 + c] + qred[128 + c] + qred[192 + c];
            atomicAdd(&gsq[b0 * 64 + c], v);
        }
    } else {
        for (int e = t; e < 8192; e += 256) {
            int r = e >> 6, c = e & 63;
            if (row0 + r < Nv) {
                float v = Cs[r * 68 + c];
                int b = s_b[r];
                atomicAdd(&gsum[b * 64 + c], v);
                atomicAdd(&gsq[b * 64 + c], v * v);
            }
        }
    }
}

// ---------------- finalize stats ---------------------------------------------
__global__ void finalize_kernel(float* sumArr, float* sqArr, int C) {
    int i = blockIdx.x * blockDim.x + threadIdx.x;
    if (i < Bb * C) {
        float cnt = (float)g_cnt[i / C];
        float mean = sumArr[i] / cnt;
        float var = sqArr[i] / cnt - mean * mean;
        sumArr[i] = mean;
        sqArr[i] = rsqrtf(fmaxf(var, 0.f) + EPSf);
    }
}

// ---------------- norm1 + relu + bf16 hi/lo split -----------------------------
__global__ void __launch_bounds__(256) norm_split_kernel(const int* __restrict__ batch_idx,
                                                         const float* __restrict__ mean,
                                                         const float* __restrict__ inv) {
    long long total = (long long)Nv * 16;
    long long i = (long long)blockIdx.x * blockDim.x + threadIdx.x;
    long long stride = (long long)gridDim.x * blockDim.x;
    for (; i < total; i += stride) {
        int row = (int)(i >> 4);
        int cg = (int)(i & 15);
        int b = batch_idx[row];
        float4 v = ((const float4*)g_x1)[i];
        float4 m = ((const float4*)mean)[b * 16 + cg];
        float4 s = ((const float4*)inv)[b * 16 + cg];
        float a0 = fmaxf((v.x - m.x) * s.x, 0.f);
        float a1 = fmaxf((v.y - m.y) * s.y, 0.f);
        float a2 = fmaxf((v.z - m.z) * s.z, 0.f);
        float a3 = fmaxf((v.w - m.w) * s.w, 0.f);
        __nv_bfloat16 h0, h1, h2, h3, l0, l1, l2, l3;
        split_bf(a0, h0, l0); split_bf(a1, h1, l1);
        split_bf(a2, h2, l2); split_bf(a3, h3, l3);
        __nv_bfloat162* ph = (__nv_bfloat162*)&g_x1h[(size_t)row * 64 + cg * 4];
        __nv_bfloat162* pl = (__nv_bfloat162*)&g_x1l[(size_t)row * 64 + cg * 4];
        ph[0] = __nv_bfloat162(h0, h1);
        ph[1] = __nv_bfloat162(h2, h3);
        pl[0] = __nv_bfloat162(l0, l1);
        pl[1] = __nv_bfloat162(l2, l3);
    }
}

// ---------------- conv2: mma.sync bf16 3-term gather-GEMM-scatter ------------
__global__ void __launch_bounds__(256, 2) conv2_mma_kernel(const int* __restrict__ in_idx,
                                                           const int* __restrict__ out_idx) {
    extern __shared__ __align__(16) char sm2[];
    __nv_bfloat16* Ah = (__nv_bfloat16*)sm2;             // 18432 B
    __nv_bfloat16* Al = (__nv_bfloat16*)(sm2 + 18432);
    __nv_bfloat16* Wh = (__nv_bfloat16*)(sm2 + 36864);   // 9216 B
    __nv_bfloat16* Wl = (__nv_bfloat16*)(sm2 + 46080);
    float* Cs = (float*)sm2;
    __shared__ int s_in[128], s_out[128];

    int t = threadIdx.x;
    int k = blockIdx.y;
    int m0 = blockIdx.x * 128;

    if (t < 128) {
        int p = m0 + t;
        bool v = (p < Mm);
        s_in[t]  = v ? in_idx[(size_t)k * Mm + p] : -1;
        s_out[t] = v ? out_idx[(size_t)k * Mm + p] : -1;
    }

    // pre-split W2 slice: [d][c] bf16, pad to 72
    const __nv_bfloat16* Wkh = g_W2h + (size_t)k * 4096;
    const __nv_bfloat16* Wkl = g_W2l + (size_t)k * 4096;
#pragma unroll
    for (int e4 = t; e4 < 512; e4 += 256) {
        int d = e4 >> 3, q = e4 & 7;
        *(uint4*)&Wh[d * 72 + q * 8] = *(const uint4*)&Wkh[d * 64 + q * 8];
        *(uint4*)&Wl[d * 72 + q * 8] = *(const uint4*)&Wkl[d * 64 + q * 8];
    }
    __syncthreads();

#pragma unroll
    for (int e = t; e < 1024; e += 256) {
        int r = e >> 3, q = e & 7;
        int src = s_in[r];
        uint4 vh = make_uint4(0u, 0u, 0u, 0u);
        uint4 vl = vh;
        if (src >= 0) {
            vh = ((const uint4*)(g_x1h + (size_t)src * 64))[q];
            vl = ((const uint4*)(g_x1l + (size_t)src * 64))[q];
        }
        *(uint4*)&Ah[r * 72 + q * 8] = vh;
        *(uint4*)&Al[r * 72 + q * 8] = vl;
    }
    __syncthreads();

    int wid = t >> 5, lane = t & 31;
    int mb = (wid >> 1) * 32;
    int nb = (wid & 1) * 32;

    float acc[2][4][4];
#pragma unroll
    for (int i = 0; i < 2; i++)
#pragma unroll
        for (int j = 0; j < 4; j++)
#pragma unroll
            for (int q = 0; q < 4; q++) acc[i][j][q] = 0.f;

    int a_row = lane & 15;
    int a_koff = (lane >> 4) << 3;
    int b_n = (lane & 7) + ((lane >> 4) << 3);
    int b_koff = ((lane >> 3) & 1) << 3;

#pragma unroll
    for (int term = 0; term < 3; term++) {
        const __nv_bfloat16* A = (term == 1) ? Al : Ah;
        const __nv_bfloat16* W = (term == 2) ? Wl : Wh;
#pragma unroll
        for (int ks = 0; ks < 4; ks++) {
            int k0 = ks * 16;
            uint32_t af0[4], af1[4], bf0[4], bf1[4];
            ldsm_x4(af0, smem_u32(&A[(mb + a_row) * 72 + k0 + a_koff]));
            ldsm_x4(af1, smem_u32(&A[(mb + 16 + a_row) * 72 + k0 + a_koff]));
            ldsm_x4(bf0, smem_u32(&W[(nb + b_n) * 72 + k0 + b_koff]));
            ldsm_x4(bf1, smem_u32(&W[(nb + 16 + b_n) * 72 + k0 + b_koff]));
            mma_bf16(acc[0][0], af0, bf0[0], bf0[1]);
            mma_bf16(acc[0][1], af0, bf0[2], bf0[3]);
            mma_bf16(acc[0][2], af0, bf1[0], bf1[1]);
            mma_bf16(acc[0][3], af0, bf1[2], bf1[3]);
            mma_bf16(acc[1][0], af1, bf0[0], bf0[1]);
            mma_bf16(acc[1][1], af1, bf0[2], bf0[3]);
            mma_bf16(acc[1][2], af1, bf1[0], bf1[1]);
            mma_bf16(acc[1][3], af1, bf1[2], bf1[3]);
        }
    }

    __syncthreads();

    int g = lane >> 2, tg = lane & 3;
#pragma unroll
    for (int mi = 0; mi < 2; mi++) {
        int row = mb + mi * 16 + g;
#pragma unroll
        for (int nj = 0; nj < 4; nj++) {
            int col = nb + nj * 8 + tg * 2;
            *(float2*)&Cs[row * 68 + col]       = make_float2(acc[mi][nj][0], acc[mi][nj][1]);
            *(float2*)&Cs[(row + 8) * 68 + col] = make_float2(acc[mi][nj][2], acc[mi][nj][3]);
        }
    }
    __syncthreads();

    {
        int r = t >> 1, h = (t & 1) * 32;
        int dst = s_out[r];
        if (dst >= 0) {
            float* p = g_x2 + (size_t)dst * 64 + h;
            const float* c = &Cs[r * 68 + h];
#pragma unroll
            for (int j = 0; j < 8; j++)
                red_v4(p + j * 4, c[j * 4], c[j * 4 + 1], c[j * 4 + 2], c[j * 4 + 3]);
        }
    }
}

// ---------------- stats2 ------------------------------------------------------
__global__ void __launch_bounds__(256) stats2_kernel(const float* __restrict__ x,
                                                     const int* __restrict__ batch_idx,
                                                     float* __restrict__ gsum,
                                                     float* __restrict__ gsq) {
    __shared__ float sm[2048];
    int t = threadIdx.x;
    int r0 = blockIdx.x * 128;
    int r1 = min(r0 + 128, Nv);
    int cg = t & 15, rg = t >> 4;
    int b0 = batch_idx[r0], b1 = batch_idx[r1 - 1];

    if (b0 == b1) {
        float4 s = make_float4(0.f, 0.f, 0.f, 0.f);
        float4 q = make_float4(0.f, 0.f, 0.f, 0.f);
#pragma unroll 4
        for (int r = r0 + rg; r < r1; r += 16) {
            float4 v = *(const float4*)&x[(size_t)r * 64 + cg * 4];
            s.x += v.x; s.y += v.y; s.z += v.z; s.w += v.w;
            q.x += v.x * v.x; q.y += v.y * v.y; q.z += v.z * v.z; q.w += v.w * v.w;
        }
        *(float4*)&sm[rg * 64 + cg * 4]        = s;
        *(float4*)&sm[1024 + rg * 64 + cg * 4] = q;
        __syncthreads();
        if (t < 64) {
            float v = 0.f;
#pragma unroll
            for (int u = 0; u < 16; u++) v += sm[u * 64 + t];
            atomicAdd(&gsum[b0 * 64 + t], v);
        } else if (t < 128) {
            int c = t - 64;
            float v = 0.f;
#pragma unroll
            for (int u = 0; u < 16; u++) v += sm[1024 + u * 64 + c];
            atomicAdd(&gsq[b0 * 64 + c], v);
        }
    } else {
        for (int i = t; i < 512; i += 256) sm[i] = 0.f;
        __syncthreads();
        for (int r = r0 + rg; r < r1; r += 16) {
            int b = batch_idx[r];
            float4 v = *(const float4*)&x[(size_t)r * 64 + cg * 4];
            atomicAdd(&sm[b * 64 + cg * 4], v.x);
            atomicAdd(&sm[b * 64 + cg * 4 + 1], v.y);
            atomicAdd(&sm[b * 64 + cg * 4 + 2], v.z);
            atomicAdd(&sm[b * 64 + cg * 4 + 3], v.w);
            atomicAdd(&sm[256 + b * 64 + cg * 4], v.x * v.x);
            atomicAdd(&sm[256 + b * 64 + cg * 4 + 1], v.y * v.y);
            atomicAdd(&sm[256 + b * 64 + cg * 4 + 2], v.z * v.z);
            atomicAdd(&sm[256 + b * 64 + cg * 4 + 3], v.w * v.w);
        }
        __syncthreads();
        if (t < 256) {
            if (sm[t] != 0.f)       atomicAdd(&gsum[t], sm[t]);
            if (sm[256 + t] != 0.f) atomicAdd(&gsq[t], sm[256 + t]);
        }
    }
}

// ---------------- conv3: mma.sync, gather(norm2+relu) -> GEMM -> out + stats3 -
// grid (1563, 4); 256 thr (8 warps 4x2); tile M=128, N=64 (col slice), K=64
__global__ void __launch_bounds__(256, 2) conv3_mma_kernel(float* __restrict__ out,
                                                           const int* __restrict__ batch_idx,
                                                           const float* __restrict__ mean2,
                                                           const float* __restrict__ inv2,
                                                           float* __restrict__ gsum,
                                                           float* __restrict__ gsq) {
    extern __shared__ __align__(16) char sm3[];
    __nv_bfloat16* Ah = (__nv_bfloat16*)sm3;             // 128x72 = 18432
    __nv_bfloat16* Al = (__nv_bfloat16*)(sm3 + 18432);
    __nv_bfloat16* Wh = (__nv_bfloat16*)(sm3 + 36864);   // 64x72 = 9216
    __nv_bfloat16* Wl = (__nv_bfloat16*)(sm3 + 46080);   // -> 55296
    float* Cs = (float*)sm3;                             // overlay 128x68 f32
    __shared__ int s_b[128];
    __shared__ float sm_m[256], sm_i[256];
    __shared__ float sred[256], qred[256];

    int t = threadIdx.x;
    int row0 = blockIdx.x * 128;
    int col0 = blockIdx.y * 64;

    if (t < 128) {
        int r = row0 + t;
        s_b[t] = (r < Nv) ? batch_idx[r] : -1;
    }
    if (t < 256) { sm_m[t] = mean2[t]; sm_i[t] = inv2[t]; }
    __syncthreads();

    // gather + norm2 + relu + split (A tile reused across 4 col-slices via L2)
#pragma unroll
    for (int e4 = t; e4 < 2048; e4 += 256) {
        int r = e4 >> 4, cg = e4 & 15;
        int row = row0 + r;
        float4 v = make_float4(0.f, 0.f, 0.f, 0.f);
        if (row < Nv) {
            float4 x = *(const float4*)&g_x2[(size_t)row * 64 + cg * 4];
            int b = s_b[r];
            float4 m = *(const float4*)&sm_m[b * 64 + cg * 4];
            float4 iv = *(const float4*)&sm_i[b * 64 + cg * 4];
            v.x = fmaxf((x.x - m.x) * iv.x, 0.f);
            v.y = fmaxf((x.y - m.y) * iv.y, 0.f);
            v.z = fmaxf((x.z - m.z) * iv.z, 0.f);
            v.w = fmaxf((x.w - m.w) * iv.w, 0.f);
        }
        __nv_bfloat16 h0, h1, h2, h3, l0, l1, l2, l3;
        split_bf(v.x, h0, l0); split_bf(v.y, h1, l1);
        split_bf(v.z, h2, l2); split_bf(v.w, h3, l3);
        __nv_bfloat162* ph = (__nv_bfloat162*)&Ah[r * 72 + cg * 4];
        __nv_bfloat162* pl = (__nv_bfloat162*)&Al[r * 72 + cg * 4];
        ph[0] = __nv_bfloat162(h0, h1); ph[1] = __nv_bfloat162(h2, h3);
        pl[0] = __nv_bfloat162(l0, l1); pl[1] = __nv_bfloat162(l2, l3);
    }
    // W3 slice [col0..col0+63][64] pre-split
#pragma unroll
    for (int e4 = t; e4 < 512; e4 += 256) {
        int n = e4 >> 3, q = e4 & 7;
        *(uint4*)&Wh[n * 72 + q * 8] = *(const uint4*)&g_W3h[(col0 + n) * 64 + q * 8];
        *(uint4*)&Wl[n * 72 + q * 8] = *(const uint4*)&g_W3l[(col0 + n) * 64 + q * 8];
    }
    __syncthreads();

    int wid = t >> 5, lane = t & 31;
    int mb = (wid >> 1) * 32;
    int nb = (wid & 1) * 32;

    float acc[2][4][4];
#pragma unroll
    for (int i = 0; i < 2; i++)
#pragma unroll
        for (int j = 0; j < 4; j++)
#pragma unroll
            for (int q = 0; q < 4; q++) acc[i][j][q] = 0.f;

    int a_row = lane & 15;
    int a_koff = (lane >> 4) << 3;
    int b_n = (lane & 7) + ((lane >> 4) << 3);
    int b_koff = ((lane >> 3) & 1) << 3;

#pragma unroll
    for (int term = 0; term < 3; term++) {
        const __nv_bfloat16* A = (term == 1) ? Al : Ah;
        const __nv_bfloat16* W = (term == 2) ? Wl : Wh;
#pragma unroll
        for (int ks = 0; ks < 4; ks++) {
            int k0 = ks * 16;
            uint32_t af0[4], af1[4], bf0[4], bf1[4];
            ldsm_x4(af0, smem_u32(&A[(mb + a_row) * 72 + k0 + a_koff]));
            ldsm_x4(af1, smem_u32(&A[(mb + 16 + a_row) * 72 + k0 + a_koff]));
            ldsm_x4(bf0, smem_u32(&W[(nb + b_n) * 72 + k0 + b_koff]));
            ldsm_x4(bf1, smem_u32(&W[(nb + 16 + b_n) * 72 + k0 + b_koff]));
            mma_bf16(acc[0][0], af0, bf0[0], bf0[1]);
            mma_bf16(acc[0][1], af0, bf0[2], bf0[3]);
            mma_bf16(acc[0][2], af0, bf1[0], bf1[1]);
            mma_bf16(acc[0][3], af0, bf1[2], bf1[3]);
            mma_bf16(acc[1][0], af1, bf0[0], bf0[1]);
            mma_bf16(acc[1][1], af1, bf0[2], bf0[3]);
            mma_bf16(acc[1][2], af1, bf1[0], bf1[1]);
            mma_bf16(acc[1][3], af1, bf1[2], bf1[3]);
        }
    }

    __syncthreads();
    // stage C (LDC = 68)
    int g = lane >> 2, tg = lane & 3;
#pragma unroll
    for (int mi = 0; mi < 2; mi++) {
        int row = mb + mi * 16 + g;
#pragma unroll
        for (int nj = 0; nj < 4; nj++) {
            int col = nb + nj * 8 + tg * 2;
            *(float2*)&Cs[row * 68 + col]       = make_float2(acc[mi][nj][0], acc[mi][nj][1]);
            *(float2*)&Cs[(row + 8) * 68 + col] = make_float2(acc[mi][nj][2], acc[mi][nj][3]);
        }
    }
    __syncthreads();

    // write out slice
#pragma unroll
    for (int e4 = t; e4 < 2048; e4 += 256) {
        int r = e4 >> 4, cg = e4 & 15;
        int row = row0 + r;
        if (row < Nv)
            *(float4*)&out[(size_t)row * 256 + col0 + cg * 4] = *(const float4*)&Cs[r * 68 + cg * 4];
    }

    // fused stats3 over this 64-col slice
    int b0 = s_b[0];
    bool fast;
    if (s_b[127] == b0) fast = true;
    else if (row0 + 127 >= Nv) {
        int lastr = Nv - 1 - row0;
        fast = (lastr >= 0 && s_b[lastr] == b0);
    } else fast = false;

    if (fast) {
        int col = t & 63, rg = t >> 6;
        float s = 0.f, q = 0.f;
#pragma unroll 8
        for (int r = rg * 32; r < rg * 32 + 32; r++) {
            float v = Cs[r * 68 + col];
            s += v; q += v * v;
        }
        sred[rg * 64 + col] = s;
        qred[rg * 64 + col] = q;
        __syncthreads();
        if (t < 64) {
            float v = sred[t] + sred[64 + t] + sred[128 + t] + sred[192 + t];
            atomicAdd(&gsum[b0 * 256 + col0 + t], v);
        } else if (t < 128) {
            int c = t - 64;
            float v = qred[c] + qred[64 + c] + qred[128 + c] + qred[192 + c];
            atomicAdd(&gsq[b0 * 256 + col0 + c], v);
        }
    } else {
        for (int e = t; e < 8192; e += 256) {
            int r = e >> 6, c = e & 63;
            if (row0 + r < Nv) {
                float v = Cs[r * 68 + c];
                int b = s_b[r];
                atomicAdd(&gsum[b * 256 + col0 + c], v);
                atomicAdd(&gsq[b * 256 + col0 + c], v * v);
            }
        }
    }
}

// ---------------- final: normalize3 + residual + relu ------------------------
__global__ void final_kernel(float* __restrict__ y,
                             const float* __restrict__ feats,
                             const int* __restrict__ batch_idx,
                             const float* __restrict__ mean,
                             const float* __restrict__ inv) {
    const int C4 = 64;
    long long total = (long long)Nv * C4;
    long long i = (long long)blockIdx.x * blockDim.x + threadIdx.x;
    long long stride = (long long)gridDim.x * blockDim.x;
    for (; i < total; i += stride) {
        int row = (int)(i / C4);
        int cg = (int)(i % C4);
        int b = batch_idx[row];
        float4 v = ((float4*)y)[i];
        float4 f = ((const float4*)feats)[i];
        float4 m = ((const float4*)mean)[b * C4 + cg];
        float4 sv = ((const float4*)inv)[b * C4 + cg];
        v.x = fmaxf((v.x - m.x) * sv.x + f.x, 0.f);
        v.y = fmaxf((v.y - m.y) * sv.y + f.y, 0.f);
        v.z = fmaxf((v.z - m.z) * sv.z + f.z, 0.f);
        v.w = fmaxf((v.w - m.w) * sv.w + f.w, 0.f);
        ((float4*)y)[i] = v;
    }
}

// ---------------- launch -----------------------------------------------------
extern "C" void kernel_launch(void* const* d_in, const int* in_sizes, int n_in,
                              void* d_out, int out_size) {
    const float* feats     = (const float*)d_in[0];
    const float* W1        = (const float*)d_in[1];
    const float* W2        = (const float*)d_in[2];
    const float* W3        = (const float*)d_in[3];
    const int*   in_idx    = (const int*)d_in[4];
    const int*   out_idx   = (const int*)d_in[5];
    const int*   batch_idx = (const int*)d_in[6];
    float* out = (float*)d_out;

    float *p_x2, *p_sum1, *p_sq1, *p_sum2, *p_sq2, *p_sum3, *p_sq3;
    cudaGetSymbolAddress((void**)&p_x2, g_x2);
    cudaGetSymbolAddress((void**)&p_sum1, g_sum1);
    cudaGetSymbolAddress((void**)&p_sq1, g_sq1);
    cudaGetSymbolAddress((void**)&p_sum2, g_sum2);
    cudaGetSymbolAddress((void**)&p_sq2, g_sq2);
    cudaGetSymbolAddress((void**)&p_sum3, g_sum3);
    cudaGetSymbolAddress((void**)&p_sq3, g_sq3);

    const int smemA = 55296;
    cudaFuncSetAttribute(conv1_mma_kernel, cudaFuncAttributeMaxDynamicSharedMemorySize, smemA);
    cudaFuncSetAttribute(conv2_mma_kernel, cudaFuncAttributeMaxDynamicSharedMemorySize, smemA);
    cudaFuncSetAttribute(conv3_mma_kernel, cudaFuncAttributeMaxDynamicSharedMemorySize, smemA);

    zero_kernel<<<2048, 256>>>();
    count_kernel<<<391, 256>>>(batch_idx);
    wsplit_kernel<<<(16384 + Kk * 4096 + 16384 + 255) / 256, 256>>>(W1, W2, W3);

    // conv1 (tensor) + fused stats1
    conv1_mma_kernel<<<(Nv + 127) / 128, 256, smemA>>>(feats, batch_idx, p_sum1, p_sq1);
    finalize_kernel<<<1, 256>>>(p_sum1, p_sq1, 64);

    // norm1 + relu + bf16 hi/lo split
    norm_split_kernel<<<4096, 256>>>(batch_idx, p_sum1, p_sq1);

    // conv2 (tensor) + scatter
    dim3 g2((Mm + 127) / 128, Kk);
    conv2_mma_kernel<<<g2, 256, smemA>>>(in_idx, out_idx);
    stats2_kernel<<<(Nv + 127) / 128, 256>>>(p_x2, batch_idx, p_sum2, p_sq2);
    finalize_kernel<<<1, 256>>>(p_sum2, p_sq2, 64);

    // conv3 (tensor, norm2+relu fused) + fused stats3
    dim3 g3((Nv + 127) / 128, 4);
    conv3_mma_kernel<<<g3, 256, smemA>>>(out, batch_idx, p_sum2, p_sq2, p_sum3, p_sq3);
    finalize_kernel<<<4, 256>>>(p_sum3, p_sq3, 256);

    final_kernel<<<16384, 256>>>(out, feats, batch_idx, p_sum3, p_sq3);
}

// round 7
// speedup vs baseline: 1.9587x; 1.1024x over previous
#include <cuda_runtime.h>
#include <cuda_bf16.h>
#include <cstdint>

#define Nv   200000
#define Kk   27
#define Mm   100000
#define Bb   4
#define EPSf 1e-5f
#define C2_TPK 782                 // tiles per k offset (ceil(Mm/128))
#define C2_TILES (Kk * C2_TPK)     // 21114
#define C2_GRID 296                // 2 CTAs/SM * 148

// ---------------- scratch (device globals — no runtime allocation) ----------
__device__ float g_x1[(size_t)Nv * 64];          // conv1 out (raw, pre-norm)
__device__ float g_x2[(size_t)Nv * 64];          // conv2 accum (raw, pre-norm)
__device__ __nv_bfloat16 g_x1h[(size_t)Nv * 64]; // normalized x1, bf16 hi
__device__ __nv_bfloat16 g_x1l[(size_t)Nv * 64]; // normalized x1, bf16 lo
__device__ __nv_bfloat16 g_W1h[64 * 256],  g_W1l[64 * 256];    // [d][c] col-major
__device__ __nv_bfloat16 g_W2h[Kk * 4096], g_W2l[Kk * 4096];   // [k][d][c]
__device__ __nv_bfloat16 g_W3h[256 * 64],  g_W3l[256 * 64];    // [n][c]
__device__ float g_sum1[Bb * 64], g_sq1[Bb * 64];
__device__ float g_sum2[Bb * 64], g_sq2[Bb * 64];
__device__ float g_sum3[Bb * 256], g_sq3[Bb * 256];
__device__ int   g_cnt[Bb];

// ---------------- helpers -----------------------------------------------------
__device__ __forceinline__ void red_v4(float* p, float a, float b, float c, float d) {
    asm volatile("red.global.add.v4.f32 [%0], {%1,%2,%3,%4};"
                 :: "l"(p), "f"(a), "f"(b), "f"(c), "f"(d) : "memory");
}
__device__ __forceinline__ uint32_t smem_u32(const void* p) {
    uint32_t a;
    asm("{ .reg .u64 t; cvta.to.shared.u64 t, %1; cvt.u32.u64 %0, t; }"
        : "=r"(a) : "l"(p));
    return a;
}
__device__ __forceinline__ void ldsm_x4(uint32_t* r, uint32_t addr) {
    asm volatile("ldmatrix.sync.aligned.m8n8.x4.shared.b16 {%0,%1,%2,%3}, [%4];"
        : "=r"(r[0]), "=r"(r[1]), "=r"(r[2]), "=r"(r[3]) : "r"(addr));
}
__device__ __forceinline__ void mma_bf16(float* c, const uint32_t* a,
                                         uint32_t b0, uint32_t b1) {
    asm volatile("mma.sync.aligned.m16n8k16.row.col.f32.bf16.bf16.f32 "
        "{%0,%1,%2,%3}, {%4,%5,%6,%7}, {%8,%9}, {%0,%1,%2,%3};"
        : "+f"(c[0]), "+f"(c[1]), "+f"(c[2]), "+f"(c[3])
        : "r"(a[0]), "r"(a[1]), "r"(a[2]), "r"(a[3]), "r"(b0), "r"(b1));
}
__device__ __forceinline__ void split_bf(float a, __nv_bfloat16& h, __nv_bfloat16& l) {
    h = __float2bfloat16(a);
    l = __float2bfloat16(a - __bfloat162float(h));
}
__device__ __forceinline__ void cp16(uint32_t dst, const void* src, int sz) {
    asm volatile("cp.async.cg.shared.global [%0], [%1], 16, %2;"
                 :: "r"(dst), "l"(src), "r"(sz));
}
#define CP_COMMIT() asm volatile("cp.async.commit_group;" ::: "memory")
#define CP_WAIT0()  asm volatile("cp.async.wait_group 0;" ::: "memory")

// ---------------- zero scratch ----------------------------------------------
__global__ void zero_kernel() {
    long long i = (long long)blockIdx.x * blockDim.x + threadIdx.x;
    long long stride = (long long)gridDim.x * blockDim.x;
    const long long total4 = (long long)Nv * 16;
    float4* p = reinterpret_cast<float4*>(g_x2);
    float4 z = make_float4(0.f, 0.f, 0.f, 0.f);
    for (long long j = i; j < total4; j += stride) p[j] = z;
    if (i < Bb * 64)  { g_sum1[i] = 0.f; g_sq1[i] = 0.f; g_sum2[i] = 0.f; g_sq2[i] = 0.f; }
    if (i < Bb * 256) { g_sum3[i] = 0.f; g_sq3[i] = 0.f; }
    if (i < Bb) g_cnt[i] = 0;
}

// ---------------- per-batch counts ------------------------------------------
__global__ void count_kernel(const int* __restrict__ batch_idx) {
    __shared__ int s[Bb];
    if (threadIdx.x < Bb) s[threadIdx.x] = 0;
    __syncthreads();
    int i = blockIdx.x * blockDim.x + threadIdx.x;
    int stride = gridDim.x * blockDim.x;
    for (int j = i; j < Nv; j += stride) atomicAdd(&s[batch_idx[j]], 1);
    __syncthreads();
    if (threadIdx.x < Bb) atomicAdd(&g_cnt[threadIdx.x], s[threadIdx.x]);
}

// ---------------- weight pre-split (col-major bf16 hi/lo) --------------------
__global__ void wsplit_kernel(const float* __restrict__ W1,
                              const float* __restrict__ W2,
                              const float* __restrict__ W3) {
    int i = blockIdx.x * blockDim.x + threadIdx.x;
    if (i < 16384) {
        int d = i >> 8, c = i & 255;
        __nv_bfloat16 h, l;
        split_bf(W1[c * 64 + d], h, l);
        g_W1h[i] = h; g_W1l[i] = l;
    } else if (i < 16384 + Kk * 4096) {
        int j = i - 16384;
        int kk = j >> 12, r = j & 4095;
        int d = r >> 6, c = r & 63;
        __nv_bfloat16 h, l;
        split_bf(W2[kk * 4096 + c * 64 + d], h, l);
        g_W2h[j] = h; g_W2l[j] = l;
    } else if (i < 16384 + Kk * 4096 + 16384) {
        int j = i - 16384 - Kk * 4096;
        int n = j >> 6, c = j & 63;
        __nv_bfloat16 h, l;
        split_bf(W3[c * 256 + n], h, l);
        g_W3h[j] = h; g_W3l[j] = l;
    }
}

// ---------------- conv1: mma.sync, x1 = feats @ W1, fused stats1 --------------
__global__ void __launch_bounds__(256, 2) conv1_mma_kernel(const float* __restrict__ feats,
                                                           const int* __restrict__ batch_idx,
                                                           float* __restrict__ gsum,
                                                           float* __restrict__ gsq) {
    extern __shared__ __align__(16) char sm1[];
    __nv_bfloat16* Ah = (__nv_bfloat16*)sm1;
    __nv_bfloat16* Al = (__nv_bfloat16*)(sm1 + 18432);
    __nv_bfloat16* Wh = (__nv_bfloat16*)(sm1 + 36864);
    __nv_bfloat16* Wl = (__nv_bfloat16*)(sm1 + 46080);
    float* Cs = (float*)sm1;
    __shared__ int s_b[128];
    __shared__ float sred[256], qred[256];

    int t = threadIdx.x;
    int row0 = blockIdx.x * 128;
    if (t < 128) {
        int r = row0 + t;
        s_b[t] = (r < Nv) ? batch_idx[r] : -1;
    }

    int wid = t >> 5, lane = t & 31;
    int mb = (wid >> 1) * 32;
    int nb = (wid & 1) * 32;
    int a_row = lane & 15;
    int a_koff = (lane >> 4) << 3;
    int b_n = (lane & 7) + ((lane >> 4) << 3);
    int b_koff = ((lane >> 3) & 1) << 3;

    float acc[2][4][4];
#pragma unroll
    for (int i = 0; i < 2; i++)
#pragma unroll
        for (int j = 0; j < 4; j++)
#pragma unroll
            for (int q = 0; q < 4; q++) acc[i][j][q] = 0.f;

    for (int k0 = 0; k0 < 256; k0 += 64) {
        __syncthreads();
#pragma unroll
        for (int e4 = t; e4 < 2048; e4 += 256) {
            int r = e4 >> 4, cg = e4 & 15;
            int row = row0 + r;
            float4 v = make_float4(0.f, 0.f, 0.f, 0.f);
            if (row < Nv) v = *(const float4*)&feats[(size_t)row * 256 + k0 + cg * 4];
            __nv_bfloat16 h0, h1, h2, h3, l0, l1, l2, l3;
            split_bf(v.x, h0, l0); split_bf(v.y, h1, l1);
            split_bf(v.z, h2, l2); split_bf(v.w, h3, l3);
            __nv_bfloat162* ph = (__nv_bfloat162*)&Ah[r * 72 + cg * 4];
            __nv_bfloat162* pl = (__nv_bfloat162*)&Al[r * 72 + cg * 4];
            ph[0] = __nv_bfloat162(h0, h1); ph[1] = __nv_bfloat162(h2, h3);
            pl[0] = __nv_bfloat162(l0, l1); pl[1] = __nv_bfloat162(l2, l3);
        }
#pragma unroll
        for (int e4 = t; e4 < 512; e4 += 256) {
            int d = e4 >> 3, q = e4 & 7;
            *(uint4*)&Wh[d * 72 + q * 8] = *(const uint4*)&g_W1h[d * 256 + k0 + q * 8];
            *(uint4*)&Wl[d * 72 + q * 8] = *(const uint4*)&g_W1l[d * 256 + k0 + q * 8];
        }
        __syncthreads();

#pragma unroll
        for (int term = 0; term < 3; term++) {
            const __nv_bfloat16* A = (term == 1) ? Al : Ah;
            const __nv_bfloat16* W = (term == 2) ? Wl : Wh;
#pragma unroll
            for (int ks = 0; ks < 4; ks++) {
                int kc = ks * 16;
                uint32_t af0[4], af1[4], bf0[4], bf1[4];
                ldsm_x4(af0, smem_u32(&A[(mb + a_row) * 72 + kc + a_koff]));
                ldsm_x4(af1, smem_u32(&A[(mb + 16 + a_row) * 72 + kc + a_koff]));
                ldsm_x4(bf0, smem_u32(&W[(nb + b_n) * 72 + kc + b_koff]));
                ldsm_x4(bf1, smem_u32(&W[(nb + 16 + b_n) * 72 + kc + b_koff]));
                mma_bf16(acc[0][0], af0, bf0[0], bf0[1]);
                mma_bf16(acc[0][1], af0, bf0[2], bf0[3]);
                mma_bf16(acc[0][2], af0, bf1[0], bf1[1]);
                mma_bf16(acc[0][3], af0, bf1[2], bf1[3]);
                mma_bf16(acc[1][0], af1, bf0[0], bf0[1]);
                mma_bf16(acc[1][1], af1, bf0[2], bf0[3]);
                mma_bf16(acc[1][2], af1, bf1[0], bf1[1]);
                mma_bf16(acc[1][3], af1, bf1[2], bf1[3]);
            }
        }
    }

    __syncthreads();
    int g = lane >> 2, tg = lane & 3;
#pragma unroll
    for (int mi = 0; mi < 2; mi++) {
        int row = mb + mi * 16 + g;
#pragma unroll
        for (int nj = 0; nj < 4; nj++) {
            int col = nb + nj * 8 + tg * 2;
            *(float2*)&Cs[row * 68 + col]       = make_float2(acc[mi][nj][0], acc[mi][nj][1]);
            *(float2*)&Cs[(row + 8) * 68 + col] = make_float2(acc[mi][nj][2], acc[mi][nj][3]);
        }
    }
    __syncthreads();

#pragma unroll
    for (int e4 = t; e4 < 2048; e4 += 256) {
        int r = e4 >> 4, cg = e4 & 15;
        int row = row0 + r;
        if (row < Nv)
            *(float4*)&g_x1[(size_t)row * 64 + cg * 4] = *(const float4*)&Cs[r * 68 + cg * 4];
    }

    int b0 = s_b[0];
    bool fast;
    if (s_b[127] == b0) fast = true;
    else if (row0 + 127 >= Nv) {
        int lastr = Nv - 1 - row0;
        fast = (lastr >= 0 && s_b[lastr] == b0);
    } else fast = false;

    if (fast) {
        int col = t & 63, rg = t >> 6;
        float s = 0.f, q = 0.f;
#pragma unroll 8
        for (int r = rg * 32; r < rg * 32 + 32; r++) {
            float v = Cs[r * 68 + col];
            s += v; q += v * v;
        }
        sred[rg * 64 + col] = s;
        qred[rg * 64 + col] = q;
        __syncthreads();
        if (t < 64) {
            float v = sred[t] + sred[64 + t] + sred[128 + t] + sred[192 + t];
            atomicAdd(&gsum[b0 * 64 + t], v);
        } else if (t < 128) {
            int c = t - 64;
            float v = qred[c] + qred[64 + c] + qred[128 + c] + qred[192 + c];
            atomicAdd(&gsq[b0 * 64 + c], v);
        }
    } else {
        for (int e = t; e < 8192; e += 256) {
            int r = e >> 6, c = e & 63;
            if (row0 + r < Nv) {
                float v = Cs[r * 68 + c];
                int b = s_b[r];
                atomicAdd(&gsum[b * 64 + c], v);
                atomicAdd(&gsq[b * 64 + c], v * v);
            }
        }
    }
}

// ---------------- finalize stats ---------------------------------------------
__global__ void finalize_kernel(float* sumArr, float* sqArr, int C) {
    int i = blockIdx.x * blockDim.x + threadIdx.x;
    if (i < Bb * C) {
        float cnt = (float)g_cnt[i / C];
        float mean = sumArr[i] / cnt;
        float var = sqArr[i] / cnt - mean * mean;
        sumArr[i] = mean;
        sqArr[i] = rsqrtf(fmaxf(var, 0.f) + EPSf);
    }
}

// ---------------- norm1 + relu + bf16 hi/lo split -----------------------------
__global__ void __launch_bounds__(256) norm_split_kernel(const int* __restrict__ batch_idx,
                                                         const float* __restrict__ mean,
                                                         const float* __restrict__ inv) {
    long long total = (long long)Nv * 16;
    long long i = (long long)blockIdx.x * blockDim.x + threadIdx.x;
    long long stride = (long long)gridDim.x * blockDim.x;
    for (; i < total; i += stride) {
        int row = (int)(i >> 4);
        int cg = (int)(i & 15);
        int b = batch_idx[row];
        float4 v = ((const float4*)g_x1)[i];
        float4 m = ((const float4*)mean)[b * 16 + cg];
        float4 s = ((const float4*)inv)[b * 16 + cg];
        float a0 = fmaxf((v.x - m.x) * s.x, 0.f);
        float a1 = fmaxf((v.y - m.y) * s.y, 0.f);
        float a2 = fmaxf((v.z - m.z) * s.z, 0.f);
        float a3 = fmaxf((v.w - m.w) * s.w, 0.f);
        __nv_bfloat16 h0, h1, h2, h3, l0, l1, l2, l3;
        split_bf(a0, h0, l0); split_bf(a1, h1, l1);
        split_bf(a2, h2, l2); split_bf(a3, h3, l3);
        __nv_bfloat162* ph = (__nv_bfloat162*)&g_x1h[(size_t)row * 64 + cg * 4];
        __nv_bfloat162* pl = (__nv_bfloat162*)&g_x1l[(size_t)row * 64 + cg * 4];
        ph[0] = __nv_bfloat162(h0, h1);
        ph[1] = __nv_bfloat162(h2, h3);
        pl[0] = __nv_bfloat162(l0, l1);
        pl[1] = __nv_bfloat162(l2, l3);
    }
}

// ---------------- conv2: persistent pipelined mma.sync gather-GEMM-scatter ---
// grid 296 (2/SM); 2-stage cp.async pipeline; per tile M=128 pairs, N=64, K=64
// smem: stage s A at s*36864 (Ah 18432 + Al 18432); W at 73728 (hi+lo 18432)
__global__ void __launch_bounds__(256, 2) conv2_mma_kernel(const int* __restrict__ in_idx,
                                                           const int* __restrict__ out_idx) {
    extern __shared__ __align__(16) char sm2[];
    __nv_bfloat16* Wh = (__nv_bfloat16*)(sm2 + 73728);
    __nv_bfloat16* Wl = (__nv_bfloat16*)(sm2 + 82944);
    __shared__ int s_in[2][128], s_out[2][128];

    int t = threadIdx.x;
    int per = (C2_TILES + C2_GRID - 1) / C2_GRID;   // 72
    int start = blockIdx.x * per;
    int end = min(start + per, C2_TILES);
    if (start >= end) return;

    int wid = t >> 5, lane = t & 31;
    int mb = (wid >> 1) * 32;
    int nb = (wid & 1) * 32;
    int a_row = lane & 15;
    int a_koff = (lane >> 4) << 3;
    int b_n = (lane & 7) + ((lane >> 4) << 3);
    int b_koff = ((lane >> 3) & 1) << 3;

    int cur_k = -1;

    // prologue: indices for first tile -> slot 0, then issue gather -> stage 0
    {
        int k0 = start / C2_TPK;
        int m0 = (start % C2_TPK) * 128;
        if (t < 128) {
            int p = m0 + t;
            bool v = (p < Mm);
            s_in[0][t]  = v ? in_idx[(size_t)k0 * Mm + p] : -1;
            s_out[0][t] = v ? out_idx[(size_t)k0 * Mm + p] : -1;
        }
    }
    __syncthreads();
    {
        char* base = sm2;   // stage 0
#pragma unroll
        for (int e = t; e < 1024; e += 256) {
            int r = e >> 3, q = e & 7;
            int src = s_in[0][r];
            bool v = (src >= 0);
            size_t off = (size_t)(v ? src : 0) * 64 + q * 8;
            int sz = v ? 16 : 0;
            cp16(smem_u32(base + r * 144 + q * 16),         g_x1h + off, sz);
            cp16(smem_u32(base + 18432 + r * 144 + q * 16), g_x1l + off, sz);
        }
        CP_COMMIT();
    }

    for (int i = start; i < end; i++) {
        int s = (i - start) & 1;
        int ns = s ^ 1;
        int k = i / C2_TPK;

        // early LDG of next tile's indices (overlaps with wait)
        int ri = -1, ro = -1;
        bool have_next = (i + 1 < end);
        if (have_next && t < 128) {
            int nk = (i + 1) / C2_TPK;
            int m0 = ((i + 1) % C2_TPK) * 128;
            int p = m0 + t;
            if (p < Mm) {
                ri = in_idx[(size_t)nk * Mm + p];
                ro = out_idx[(size_t)nk * Mm + p];
            }
        }

        CP_WAIT0();
        __syncthreads();   // stage s data ready; prev epilogue finished

        if (have_next && t < 128) { s_in[ns][t] = ri; s_out[ns][t] = ro; }
        bool needW = (k != cur_k);
        if (needW) {
            const __nv_bfloat16* Wkh = g_W2h + (size_t)k * 4096;
            const __nv_bfloat16* Wkl = g_W2l + (size_t)k * 4096;
#pragma unroll
            for (int e4 = t; e4 < 512; e4 += 256) {
                int d = e4 >> 3, q = e4 & 7;
                *(uint4*)&Wh[d * 72 + q * 8] = *(const uint4*)&Wkh[d * 64 + q * 8];
                *(uint4*)&Wl[d * 72 + q * 8] = *(const uint4*)&Wkl[d * 64 + q * 8];
            }
            cur_k = k;
        }
        __syncthreads();   // indices + W visible

        // issue gather for next tile into stage ns (overlaps with MMA below)
        if (have_next) {
            char* base = sm2 + ns * 36864;
#pragma unroll
            for (int e = t; e < 1024; e += 256) {
                int r = e >> 3, q = e & 7;
                int src = s_in[ns][r];
                bool v = (src >= 0);
                size_t off = (size_t)(v ? src : 0) * 64 + q * 8;
                int sz = v ? 16 : 0;
                cp16(smem_u32(base + r * 144 + q * 16),         g_x1h + off, sz);
                cp16(smem_u32(base + 18432 + r * 144 + q * 16), g_x1l + off, sz);
            }
            CP_COMMIT();
        }

        // MMA on stage s
        const __nv_bfloat16* AhS = (const __nv_bfloat16*)(sm2 + s * 36864);
        const __nv_bfloat16* AlS = (const __nv_bfloat16*)(sm2 + s * 36864 + 18432);

        float acc[2][4][4];
#pragma unroll
        for (int ii = 0; ii < 2; ii++)
#pragma unroll
            for (int j = 0; j < 4; j++)
#pragma unroll
                for (int q = 0; q < 4; q++) acc[ii][j][q] = 0.f;

#pragma unroll
        for (int term = 0; term < 3; term++) {
            const __nv_bfloat16* A = (term == 1) ? AlS : AhS;
            const __nv_bfloat16* W = (term == 2) ? Wl : Wh;
#pragma unroll
            for (int ks = 0; ks < 4; ks++) {
                int k0 = ks * 16;
                uint32_t af0[4], af1[4], bf0[4], bf1[4];
                ldsm_x4(af0, smem_u32(&A[(mb + a_row) * 72 + k0 + a_koff]));
                ldsm_x4(af1, smem_u32(&A[(mb + 16 + a_row) * 72 + k0 + a_koff]));
                ldsm_x4(bf0, smem_u32(&W[(nb + b_n) * 72 + k0 + b_koff]));
                ldsm_x4(bf1, smem_u32(&W[(nb + 16 + b_n) * 72 + k0 + b_koff]));
                mma_bf16(acc[0][0], af0, bf0[0], bf0[1]);
                mma_bf16(acc[0][1], af0, bf0[2], bf0[3]);
                mma_bf16(acc[0][2], af0, bf1[0], bf1[1]);
                mma_bf16(acc[0][3], af0, bf1[2], bf1[3]);
                mma_bf16(acc[1][0], af1, bf0[0], bf0[1]);
                mma_bf16(acc[1][1], af1, bf0[2], bf0[3]);
                mma_bf16(acc[1][2], af1, bf1[0], bf1[1]);
                mma_bf16(acc[1][3], af1, bf1[2], bf1[3]);
            }
        }

        __syncthreads();   // all warps done reading stage s -> overlay C

        float* Cs = (float*)(sm2 + s * 36864);   // 128*68*4 = 34816 <= 36864
        int g = lane >> 2, tg = lane & 3;
#pragma unroll
        for (int mi = 0; mi < 2; mi++) {
            int row = mb + mi * 16 + g;
#pragma unroll
            for (int nj = 0; nj < 4; nj++) {
                int col = nb + nj * 8 + tg * 2;
                *(float2*)&Cs[row * 68 + col]       = make_float2(acc[mi][nj][0], acc[mi][nj][1]);
                *(float2*)&Cs[(row + 8) * 68 + col] = make_float2(acc[mi][nj][2], acc[mi][nj][3]);
            }
        }
        __syncthreads();

        // scatter: thread handles half a row (32 floats = 8 red.v4)
        {
            int r = t >> 1, h = (t & 1) * 32;
            int dst = s_out[s][r];
            if (dst >= 0) {
                float* p = g_x2 + (size_t)dst * 64 + h;
                const float* c = &Cs[r * 68 + h];
#pragma unroll
                for (int j = 0; j < 8; j++)
                    red_v4(p + j * 4, c[j * 4], c[j * 4 + 1], c[j * 4 + 2], c[j * 4 + 3]);
            }
        }
        // next iteration's first __syncthreads protects Cs from stage-reuse
    }
}

// ---------------- stats2 ------------------------------------------------------
__global__ void __launch_bounds__(256) stats2_kernel(const float* __restrict__ x,
                                                     const int* __restrict__ batch_idx,
                                                     float* __restrict__ gsum,
                                                     float* __restrict__ gsq) {
    __shared__ float sm[2048];
    int t = threadIdx.x;
    int r0 = blockIdx.x * 128;
    int r1 = min(r0 + 128, Nv);
    int cg = t & 15, rg = t >> 4;
    int b0 = batch_idx[r0], b1 = batch_idx[r1 - 1];

    if (b0 == b1) {
        float4 s = make_float4(0.f, 0.f, 0.f, 0.f);
        float4 q = make_float4(0.f, 0.f, 0.f, 0.f);
#pragma unroll 4
        for (int r = r0 + rg; r < r1; r += 16) {
            float4 v = *(const float4*)&x[(size_t)r * 64 + cg * 4];
            s.x += v.x; s.y += v.y; s.z += v.z; s.w += v.w;
            q.x += v.x * v.x; q.y += v.y * v.y; q.z += v.z * v.z; q.w += v.w * v.w;
        }
        *(float4*)&sm[rg * 64 + cg * 4]        = s;
        *(float4*)&sm[1024 + rg * 64 + cg * 4] = q;
        __syncthreads();
        if (t < 64) {
            float v = 0.f;
#pragma unroll
            for (int u = 0; u < 16; u++) v += sm[u * 64 + t];
            atomicAdd(&gsum[b0 * 64 + t], v);
        } else if (t < 128) {
            int c = t - 64;
            float v = 0.f;
#pragma unroll
            for (int u = 0; u < 16; u++) v += sm[1024 + u * 64 + c];
            atomicAdd(&gsq[b0 * 64 + c], v);
        }
    } else {
        for (int i = t; i < 512; i += 256) sm[i] = 0.f;
        __syncthreads();
        for (int r = r0 + rg; r < r1; r += 16) {
            int b = batch_idx[r];
            float4 v = *(const float4*)&x[(size_t)r * 64 + cg * 4];
            atomicAdd(&sm[b * 64 + cg * 4], v.x);
            atomicAdd(&sm[b * 64 + cg * 4 + 1], v.y);
            atomicAdd(&sm[b * 64 + cg * 4 + 2], v.z);
            atomicAdd(&sm[b * 64 + cg * 4 + 3], v.w);
            atomicAdd(&sm[256 + b * 64 + cg * 4], v.x * v.x);
            atomicAdd(&sm[256 + b * 64 + cg * 4 + 1], v.y * v.y);
            atomicAdd(&sm[256 + b * 64 + cg * 4 + 2], v.z * v.z);
            atomicAdd(&sm[256 + b * 64 + cg * 4 + 3], v.w * v.w);
        }
        __syncthreads();
        if (t < 256) {
            if (sm[t] != 0.f)       atomicAdd(&gsum[t], sm[t]);
            if (sm[256 + t] != 0.f) atomicAdd(&gsq[t], sm[256 + t]);
        }
    }
}

// ---------------- conv3: mma.sync, gather(norm2+relu) -> GEMM -> out + stats3 -
__global__ void __launch_bounds__(256, 2) conv3_mma_kernel(float* __restrict__ out,
                                                           const int* __restrict__ batch_idx,
                                                           const float* __restrict__ mean2,
                                                           const float* __restrict__ inv2,
                                                           float* __restrict__ gsum,
                                                           float* __restrict__ gsq) {
    extern __shared__ __align__(16) char sm3[];
    __nv_bfloat16* Ah = (__nv_bfloat16*)sm3;
    __nv_bfloat16* Al = (__nv_bfloat16*)(sm3 + 18432);
    __nv_bfloat16* Wh = (__nv_bfloat16*)(sm3 + 36864);
    __nv_bfloat16* Wl = (__nv_bfloat16*)(sm3 + 46080);
    float* Cs = (float*)sm3;
    __shared__ int s_b[128];
    __shared__ float sm_m[256], sm_i[256];
    __shared__ float sred[256], qred[256];

    int t = threadIdx.x;
    int row0 = blockIdx.x * 128;
    int col0 = blockIdx.y * 64;

    if (t < 128) {
        int r = row0 + t;
        s_b[t] = (r < Nv) ? batch_idx[r] : -1;
    }
    if (t < 256) { sm_m[t] = mean2[t]; sm_i[t] = inv2[t]; }
    __syncthreads();

#pragma unroll
    for (int e4 = t; e4 < 2048; e4 += 256) {
        int r = e4 >> 4, cg = e4 & 15;
        int row = row0 + r;
        float4 v = make_float4(0.f, 0.f, 0.f, 0.f);
        if (row < Nv) {
            float4 x = *(const float4*)&g_x2[(size_t)row * 64 + cg * 4];
            int b = s_b[r];
            float4 m = *(const float4*)&sm_m[b * 64 + cg * 4];
            float4 iv = *(const float4*)&sm_i[b * 64 + cg * 4];
            v.x = fmaxf((x.x - m.x) * iv.x, 0.f);
            v.y = fmaxf((x.y - m.y) * iv.y, 0.f);
            v.z = fmaxf((x.z - m.z) * iv.z, 0.f);
            v.w = fmaxf((x.w - m.w) * iv.w, 0.f);
        }
        __nv_bfloat16 h0, h1, h2, h3, l0, l1, l2, l3;
        split_bf(v.x, h0, l0); split_bf(v.y, h1, l1);
        split_bf(v.z, h2, l2); split_bf(v.w, h3, l3);
        __nv_bfloat162* ph = (__nv_bfloat162*)&Ah[r * 72 + cg * 4];
        __nv_bfloat162* pl = (__nv_bfloat162*)&Al[r * 72 + cg * 4];
        ph[0] = __nv_bfloat162(h0, h1); ph[1] = __nv_bfloat162(h2, h3);
        pl[0] = __nv_bfloat162(l0, l1); pl[1] = __nv_bfloat162(l2, l3);
    }
#pragma unroll
    for (int e4 = t; e4 < 512; e4 += 256) {
        int n = e4 >> 3, q = e4 & 7;
        *(uint4*)&Wh[n * 72 + q * 8] = *(const uint4*)&g_W3h[(col0 + n) * 64 + q * 8];
        *(uint4*)&Wl[n * 72 + q * 8] = *(const uint4*)&g_W3l[(col0 + n) * 64 + q * 8];
    }
    __syncthreads();

    int wid = t >> 5, lane = t & 31;
    int mb = (wid >> 1) * 32;
    int nb = (wid & 1) * 32;

    float acc[2][4][4];
#pragma unroll
    for (int i = 0; i < 2; i++)
#pragma unroll
        for (int j = 0; j < 4; j++)
#pragma unroll
            for (int q = 0; q < 4; q++) acc[i][j][q] = 0.f;

    int a_row = lane & 15;
    int a_koff = (lane >> 4) << 3;
    int b_n = (lane & 7) + ((lane >> 4) << 3);
    int b_koff = ((lane >> 3) & 1) << 3;

#pragma unroll
    for (int term = 0; term < 3; term++) {
        const __nv_bfloat16* A = (term == 1) ? Al : Ah;
        const __nv_bfloat16* W = (term == 2) ? Wl : Wh;
#pragma unroll
        for (int ks = 0; ks < 4; ks++) {
            int k0 = ks * 16;
            uint32_t af0[4], af1[4], bf0[4], bf1[4];
            ldsm_x4(af0, smem_u32(&A[(mb + a_row) * 72 + k0 + a_koff]));
            ldsm_x4(af1, smem_u32(&A[(mb + 16 + a_row) * 72 + k0 + a_koff]));
            ldsm_x4(bf0, smem_u32(&W[(nb + b_n) * 72 + k0 + b_koff]));
            ldsm_x4(bf1, smem_u32(&W[(nb + 16 + b_n) * 72 + k0 + b_koff]));
            mma_bf16(acc[0][0], af0, bf0[0], bf0[1]);
            mma_bf16(acc[0][1], af0, bf0[2], bf0[3]);
            mma_bf16(acc[0][2], af0, bf1[0], bf1[1]);
            mma_bf16(acc[0][3], af0, bf1[2], bf1[3]);
            mma_bf16(acc[1][0], af1, bf0[0], bf0[1]);
            mma_bf16(acc[1][1], af1, bf0[2], bf0[3]);
            mma_bf16(acc[1][2], af1, bf1[0], bf1[1]);
            mma_bf16(acc[1][3], af1, bf1[2], bf1[3]);
        }
    }

    __syncthreads();
    int g = lane >> 2, tg = lane & 3;
#pragma unroll
    for (int mi = 0; mi < 2; mi++) {
        int row = mb + mi * 16 + g;
#pragma unroll
        for (int nj = 0; nj < 4; nj++) {
            int col = nb + nj * 8 + tg * 2;
            *(float2*)&Cs[row * 68 + col]       = make_float2(acc[mi][nj][0], acc[mi][nj][1]);
            *(float2*)&Cs[(row + 8) * 68 + col] = make_float2(acc[mi][nj][2], acc[mi][nj][3]);
        }
    }
    __syncthreads();

#pragma unroll
    for (int e4 = t; e4 < 2048; e4 += 256) {
        int r = e4 >> 4, cg = e4 & 15;
        int row = row0 + r;
        if (row < Nv)
            *(float4*)&out[(size_t)row * 256 + col0 + cg * 4] = *(const float4*)&Cs[r * 68 + cg * 4];
    }

    int b0 = s_b[0];
    bool fast;
    if (s_b[127] == b0) fast = true;
    else if (row0 + 127 >= Nv) {
        int lastr = Nv - 1 - row0;
        fast = (lastr >= 0 && s_b[lastr] == b0);
    } else fast = false;

    if (fast) {
        int col = t & 63, rg = t >> 6;
        float s = 0.f, q = 0.f;
#pragma unroll 8
        for (int r = rg * 32; r < rg * 32 + 32; r++) {
            float v = Cs[r * 68 + col];
            s += v; q += v * v;
        }
        sred[rg * 64 + col] = s;
        qred[rg * 64 + col] = q;
        __syncthreads();
        if (t < 64) {
            float v = sred[t] + sred[64 + t] + sred[128 + t] + sred[192 + t];
            atomicAdd(&gsum[b0 * 256 + col0 + t], v);
        } else if (t < 128) {
            int c = t - 64;
            float v = qred[c] + qred[64 + c] + qred[128 + c] + qred[192 + c];
            atomicAdd(&gsq[b0 * 256 + col0 + c], v);
        }
    } else {
        for (int e = t; e < 8192; e += 256) {
            int r = e >> 6, c = e & 63;
            if (row0 + r < Nv) {
                float v = Cs[r * 68 + c];
                int b = s_b[r];
                atomicAdd(&gsum[b * 256 + col0 + c], v);
                atomicAdd(&gsq[b * 256 + col0 + c], v * v);
            }
        }
    }
}

// ---------------- final: normalize3 + residual + relu ------------------------
__global__ void final_kernel(float* __restrict__ y,
                             const float* __restrict__ feats,
                             const int* __restrict__ batch_idx,
                             const float* __restrict__ mean,
                             const float* __restrict__ inv) {
    const int C4 = 64;
    long long total = (long long)Nv * C4;
    long long i = (long long)blockIdx.x * blockDim.x + threadIdx.x;
    long long stride = (long long)gridDim.x * blockDim.x;
    for (; i < total; i += stride) {
        int row = (int)(i / C4);
        int cg = (int)(i % C4);
        int b = batch_idx[row];
        float4 v = ((float4*)y)[i];
        float4 f = ((const float4*)feats)[i];
        float4 m = ((const float4*)mean)[b * C4 + cg];
        float4 sv = ((const float4*)inv)[b * C4 + cg];
        v.x = fmaxf((v.x - m.x) * sv.x + f.x, 0.f);
        v.y = fmaxf((v.y - m.y) * sv.y + f.y, 0.f);
        v.z = fmaxf((v.z - m.z) * sv.z + f.z, 0.f);
        v.w = fmaxf((v.w - m.w) * sv.w + f.w, 0.f);
        ((float4*)y)[i] = v;
    }
}

// ---------------- launch -----------------------------------------------------
extern "C" void kernel_launch(void* const* d_in, const int* in_sizes, int n_in,
                              void* d_out, int out_size) {
    const float* feats     = (const float*)d_in[0];
    const float* W1        = (const float*)d_in[1];
    const float* W2        = (const float*)d_in[2];
    const float* W3        = (const float*)d_in[3];
    const int*   in_idx    = (const int*)d_in[4];
    const int*   out_idx   = (const int*)d_in[5];
    const int*   batch_idx = (const int*)d_in[6];
    float* out = (float*)d_out;

    float *p_x2, *p_sum1, *p_sq1, *p_sum2, *p_sq2, *p_sum3, *p_sq3;
    cudaGetSymbolAddress((void**)&p_x2, g_x2);
    cudaGetSymbolAddress((void**)&p_sum1, g_sum1);
    cudaGetSymbolAddress((void**)&p_sq1, g_sq1);
    cudaGetSymbolAddress((void**)&p_sum2, g_sum2);
    cudaGetSymbolAddress((void**)&p_sq2, g_sq2);
    cudaGetSymbolAddress((void**)&p_sum3, g_sum3);
    cudaGetSymbolAddress((void**)&p_sq3, g_sq3);

    const int smemA = 55296;
    const int smem2 = 92160;   // 2 A stages (73728) + W hi/lo (18432)
    cudaFuncSetAttribute(conv1_mma_kernel, cudaFuncAttributeMaxDynamicSharedMemorySize, smemA);
    cudaFuncSetAttribute(conv2_mma_kernel, cudaFuncAttributeMaxDynamicSharedMemorySize, smem2);
    cudaFuncSetAttribute(conv3_mma_kernel, cudaFuncAttributeMaxDynamicSharedMemorySize, smemA);

    zero_kernel<<<2048, 256>>>();
    count_kernel<<<391, 256>>>(batch_idx);
    wsplit_kernel<<<(16384 + Kk * 4096 + 16384 + 255) / 256, 256>>>(W1, W2, W3);

    // conv1 (tensor) + fused stats1
    conv1_mma_kernel<<<(Nv + 127) / 128, 256, smemA>>>(feats, batch_idx, p_sum1, p_sq1);
    finalize_kernel<<<1, 256>>>(p_sum1, p_sq1, 64);

    // norm1 + relu + bf16 hi/lo split
    norm_split_kernel<<<4096, 256>>>(batch_idx, p_sum1, p_sq1);

    // conv2: persistent pipelined tensor gather-GEMM-scatter
    conv2_mma_kernel<<<C2_GRID, 256, smem2>>>(in_idx, out_idx);
    stats2_kernel<<<(Nv + 127) / 128, 256>>>(p_x2, batch_idx, p_sum2, p_sq2);
    finalize_kernel<<<1, 256>>>(p_sum2, p_sq2, 64);

    // conv3 (tensor, norm2+relu fused) + fused stats3
    dim3 g3((Nv + 127) / 128, 4);
    conv3_mma_kernel<<<g3, 256, smemA>>>(out, batch_idx, p_sum2, p_sq2, p_sum3, p_sq3);
    finalize_kernel<<<4, 256>>>(p_sum3, p_sq3, 256);

    final_kernel<<<16384, 256>>>(out, feats, batch_idx, p_sum3, p_sq3);
}

// round 8
// speedup vs baseline: 2.3182x; 1.1835x over previous
#include <cuda_runtime.h>
#include <cuda_bf16.h>
#include <cuda_fp16.h>
#include <cstdint>

#define Nv   200000
#define Kk   27
#define Mm   100000
#define Bb   4
#define EPSf 1e-5f
#define C2_TPK 782                 // tiles per k offset (ceil(Mm/128))
#define C2_TILES (Kk * C2_TPK)     // 21114
#define C2_GRID 296                // 2 CTAs/SM * 148

// ---------------- scratch (device globals — no runtime allocation) ----------
__device__ float g_x1[(size_t)Nv * 64];          // conv1 out (raw, pre-norm)
__device__ float g_x2[(size_t)Nv * 64];          // conv2 accum (raw, pre-norm)
__device__ __half g_x1h[(size_t)Nv * 64];        // normalized x1, fp16 hi
__device__ __half g_x1l[(size_t)Nv * 64];        // normalized x1, fp16 lo
__device__ __nv_bfloat16 g_x2h[(size_t)Nv * 64]; // normalized x2, bf16 hi
__device__ __nv_bfloat16 g_x2l[(size_t)Nv * 64]; // normalized x2, bf16 lo
__device__ __nv_bfloat16 g_W1h[64 * 256],  g_W1l[64 * 256];    // [d][c] col-major
__device__ __half        g_W2h[Kk * 4096];                     // [k][d][c] fp16
__device__ __nv_bfloat16 g_W3h[256 * 64],  g_W3l[256 * 64];    // [n][c]
__device__ float g_sum1[Bb * 64], g_sq1[Bb * 64];
__device__ float g_sum2[Bb * 64], g_sq2[Bb * 64];
__device__ float g_sum3[Bb * 256], g_sq3[Bb * 256];
__device__ int   g_cnt[Bb];

// ---------------- helpers -----------------------------------------------------
__device__ __forceinline__ void red_v4(float* p, float a, float b, float c, float d) {
    asm volatile("red.global.add.v4.f32 [%0], {%1,%2,%3,%4};"
                 :: "l"(p), "f"(a), "f"(b), "f"(c), "f"(d) : "memory");
}
__device__ __forceinline__ uint32_t smem_u32(const void* p) {
    uint32_t a;
    asm("{ .reg .u64 t; cvta.to.shared.u64 t, %1; cvt.u32.u64 %0, t; }"
        : "=r"(a) : "l"(p));
    return a;
}
__device__ __forceinline__ void ldsm_x4(uint32_t* r, uint32_t addr) {
    asm volatile("ldmatrix.sync.aligned.m8n8.x4.shared.b16 {%0,%1,%2,%3}, [%4];"
        : "=r"(r[0]), "=r"(r[1]), "=r"(r[2]), "=r"(r[3]) : "r"(addr));
}
__device__ __forceinline__ void mma_bf16(float* c, const uint32_t* a,
                                         uint32_t b0, uint32_t b1) {
    asm volatile("mma.sync.aligned.m16n8k16.row.col.f32.bf16.bf16.f32 "
        "{%0,%1,%2,%3}, {%4,%5,%6,%7}, {%8,%9}, {%0,%1,%2,%3};"
        : "+f"(c[0]), "+f"(c[1]), "+f"(c[2]), "+f"(c[3])
        : "r"(a[0]), "r"(a[1]), "r"(a[2]), "r"(a[3]), "r"(b0), "r"(b1));
}
__device__ __forceinline__ void mma_f16(float* c, const uint32_t* a,
                                        uint32_t b0, uint32_t b1) {
    asm volatile("mma.sync.aligned.m16n8k16.row.col.f32.f16.f16.f32 "
        "{%0,%1,%2,%3}, {%4,%5,%6,%7}, {%8,%9}, {%0,%1,%2,%3};"
        : "+f"(c[0]), "+f"(c[1]), "+f"(c[2]), "+f"(c[3])
        : "r"(a[0]), "r"(a[1]), "r"(a[2]), "r"(a[3]), "r"(b0), "r"(b1));
}
__device__ __forceinline__ void split_bf(float a, __nv_bfloat16& h, __nv_bfloat16& l) {
    h = __float2bfloat16(a);
    l = __float2bfloat16(a - __bfloat162float(h));
}
__device__ __forceinline__ void split_h(float a, __half& h, __half& l) {
    h = __float2half_rn(a);
    l = __float2half_rn(a - __half2float(h));
}
__device__ __forceinline__ void cp16(uint32_t dst, const void* src, int sz) {
    asm volatile("cp.async.cg.shared.global [%0], [%1], 16, %2;"
                 :: "r"(dst), "l"(src), "r"(sz));
}
#define CP_COMMIT() asm volatile("cp.async.commit_group;" ::: "memory")
#define CP_WAIT0()  asm volatile("cp.async.wait_group 0;" ::: "memory")

// ---------------- zero scratch ----------------------------------------------
__global__ void zero_kernel() {
    long long i = (long long)blockIdx.x * blockDim.x + threadIdx.x;
    long long stride = (long long)gridDim.x * blockDim.x;
    const long long total4 = (long long)Nv * 16;
    float4* p = reinterpret_cast<float4*>(g_x2);
    float4 z = make_float4(0.f, 0.f, 0.f, 0.f);
    for (long long j = i; j < total4; j += stride) p[j] = z;
    if (i < Bb * 64)  { g_sum1[i] = 0.f; g_sq1[i] = 0.f; g_sum2[i] = 0.f; g_sq2[i] = 0.f; }
    if (i < Bb * 256) { g_sum3[i] = 0.f; g_sq3[i] = 0.f; }
    if (i < Bb) g_cnt[i] = 0;
}

// ---------------- per-batch counts ------------------------------------------
__global__ void count_kernel(const int* __restrict__ batch_idx) {
    __shared__ int s[Bb];
    if (threadIdx.x < Bb) s[threadIdx.x] = 0;
    __syncthreads();
    int i = blockIdx.x * blockDim.x + threadIdx.x;
    int stride = gridDim.x * blockDim.x;
    for (int j = i; j < Nv; j += stride) atomicAdd(&s[batch_idx[j]], 1);
    __syncthreads();
    if (threadIdx.x < Bb) atomicAdd(&g_cnt[threadIdx.x], s[threadIdx.x]);
}

// ---------------- weight pre-split -------------------------------------------
__global__ void wsplit_kernel(const float* __restrict__ W1,
                              const float* __restrict__ W2,
                              const float* __restrict__ W3) {
    int i = blockIdx.x * blockDim.x + threadIdx.x;
    if (i < 16384) {
        int d = i >> 8, c = i & 255;
        __nv_bfloat16 h, l;
        split_bf(W1[c * 64 + d], h, l);
        g_W1h[i] = h; g_W1l[i] = l;
    } else if (i < 16384 + Kk * 4096) {
        int j = i - 16384;
        int kk = j >> 12, r = j & 4095;
        int d = r >> 6, c = r & 63;
        g_W2h[j] = __float2half_rn(W2[kk * 4096 + c * 64 + d]);
    } else if (i < 16384 + Kk * 4096 + 16384) {
        int j = i - 16384 - Kk * 4096;
        int n = j >> 6, c = j & 63;
        __nv_bfloat16 h, l;
        split_bf(W3[c * 256 + n], h, l);
        g_W3h[j] = h; g_W3l[j] = l;
    }
}

// ---------------- conv1: mma.sync, x1 = feats @ W1, fused stats1 --------------
__global__ void __launch_bounds__(256, 2) conv1_mma_kernel(const float* __restrict__ feats,
                                                           const int* __restrict__ batch_idx,
                                                           float* __restrict__ gsum,
                                                           float* __restrict__ gsq) {
    extern __shared__ __align__(16) char sm1[];
    __nv_bfloat16* Ah = (__nv_bfloat16*)sm1;
    __nv_bfloat16* Al = (__nv_bfloat16*)(sm1 + 18432);
    __nv_bfloat16* Wh = (__nv_bfloat16*)(sm1 + 36864);
    __nv_bfloat16* Wl = (__nv_bfloat16*)(sm1 + 46080);
    float* Cs = (float*)sm1;
    __shared__ int s_b[128];
    __shared__ float sred[256], qred[256];

    int t = threadIdx.x;
    int row0 = blockIdx.x * 128;
    if (t < 128) {
        int r = row0 + t;
        s_b[t] = (r < Nv) ? batch_idx[r] : -1;
    }

    int wid = t >> 5, lane = t & 31;
    int mb = (wid >> 1) * 32;
    int nb = (wid & 1) * 32;
    int a_row = lane & 15;
    int a_koff = (lane >> 4) << 3;
    int b_n = (lane & 7) + ((lane >> 4) << 3);
    int b_koff = ((lane >> 3) & 1) << 3;

    float acc[2][4][4];
#pragma unroll
    for (int i = 0; i < 2; i++)
#pragma unroll
        for (int j = 0; j < 4; j++)
#pragma unroll
            for (int q = 0; q < 4; q++) acc[i][j][q] = 0.f;

    for (int k0 = 0; k0 < 256; k0 += 64) {
        __syncthreads();
#pragma unroll
        for (int e4 = t; e4 < 2048; e4 += 256) {
            int r = e4 >> 4, cg = e4 & 15;
            int row = row0 + r;
            float4 v = make_float4(0.f, 0.f, 0.f, 0.f);
            if (row < Nv) v = *(const float4*)&feats[(size_t)row * 256 + k0 + cg * 4];
            __nv_bfloat16 h0, h1, h2, h3, l0, l1, l2, l3;
            split_bf(v.x, h0, l0); split_bf(v.y, h1, l1);
            split_bf(v.z, h2, l2); split_bf(v.w, h3, l3);
            __nv_bfloat162* ph = (__nv_bfloat162*)&Ah[r * 72 + cg * 4];
            __nv_bfloat162* pl = (__nv_bfloat162*)&Al[r * 72 + cg * 4];
            ph[0] = __nv_bfloat162(h0, h1); ph[1] = __nv_bfloat162(h2, h3);
            pl[0] = __nv_bfloat162(l0, l1); pl[1] = __nv_bfloat162(l2, l3);
        }
#pragma unroll
        for (int e4 = t; e4 < 512; e4 += 256) {
            int d = e4 >> 3, q = e4 & 7;
            *(uint4*)&Wh[d * 72 + q * 8] = *(const uint4*)&g_W1h[d * 256 + k0 + q * 8];
            *(uint4*)&Wl[d * 72 + q * 8] = *(const uint4*)&g_W1l[d * 256 + k0 + q * 8];
        }
        __syncthreads();

#pragma unroll
        for (int term = 0; term < 3; term++) {
            const __nv_bfloat16* A = (term == 1) ? Al : Ah;
            const __nv_bfloat16* W = (term == 2) ? Wl : Wh;
#pragma unroll
            for (int ks = 0; ks < 4; ks++) {
                int kc = ks * 16;
                uint32_t af0[4], af1[4], bf0[4], bf1[4];
                ldsm_x4(af0, smem_u32(&A[(mb + a_row) * 72 + kc + a_koff]));
                ldsm_x4(af1, smem_u32(&A[(mb + 16 + a_row) * 72 + kc + a_koff]));
                ldsm_x4(bf0, smem_u32(&W[(nb + b_n) * 72 + kc + b_koff]));
                ldsm_x4(bf1, smem_u32(&W[(nb + 16 + b_n) * 72 + kc + b_koff]));
                mma_bf16(acc[0][0], af0, bf0[0], bf0[1]);
                mma_bf16(acc[0][1], af0, bf0[2], bf0[3]);
                mma_bf16(acc[0][2], af0, bf1[0], bf1[1]);
                mma_bf16(acc[0][3], af0, bf1[2], bf1[3]);
                mma_bf16(acc[1][0], af1, bf0[0], bf0[1]);
                mma_bf16(acc[1][1], af1, bf0[2], bf0[3]);
                mma_bf16(acc[1][2], af1, bf1[0], bf1[1]);
                mma_bf16(acc[1][3], af1, bf1[2], bf1[3]);
            }
        }
    }

    __syncthreads();
    int g = lane >> 2, tg = lane & 3;
#pragma unroll
    for (int mi = 0; mi < 2; mi++) {
        int row = mb + mi * 16 + g;
#pragma unroll
        for (int nj = 0; nj < 4; nj++) {
            int col = nb + nj * 8 + tg * 2;
            *(float2*)&Cs[row * 68 + col]       = make_float2(acc[mi][nj][0], acc[mi][nj][1]);
            *(float2*)&Cs[(row + 8) * 68 + col] = make_float2(acc[mi][nj][2], acc[mi][nj][3]);
        }
    }
    __syncthreads();

#pragma unroll
    for (int e4 = t; e4 < 2048; e4 += 256) {
        int r = e4 >> 4, cg = e4 & 15;
        int row = row0 + r;
        if (row < Nv)
            *(float4*)&g_x1[(size_t)row * 64 + cg * 4] = *(const float4*)&Cs[r * 68 + cg * 4];
    }

    int b0 = s_b[0];
    bool fast;
    if (s_b[127] == b0) fast = true;
    else if (row0 + 127 >= Nv) {
        int lastr = Nv - 1 - row0;
        fast = (lastr >= 0 && s_b[lastr] == b0);
    } else fast = false;

    if (fast) {
        int col = t & 63, rg = t >> 6;
        float s = 0.f, q = 0.f;
#pragma unroll 8
        for (int r = rg * 32; r < rg * 32 + 32; r++) {
            float v = Cs[r * 68 + col];
            s += v; q += v * v;
        }
        sred[rg * 64 + col] = s;
        qred[rg * 64 + col] = q;
        __syncthreads();
        if (t < 64) {
            float v = sred[t] + sred[64 + t] + sred[128 + t] + sred[192 + t];
            atomicAdd(&gsum[b0 * 64 + t], v);
        } else if (t < 128) {
            int c = t - 64;
            float v = qred[c] + qred[64 + c] + qred[128 + c] + qred[192 + c];
            atomicAdd(&gsq[b0 * 64 + c], v);
        }
    } else {
        for (int e = t; e < 8192; e += 256) {
            int r = e >> 6, c = e & 63;
            if (row0 + r < Nv) {
                float v = Cs[r * 68 + c];
                int b = s_b[r];
                atomicAdd(&gsum[b * 64 + c], v);
                atomicAdd(&gsq[b * 64 + c], v * v);
            }
        }
    }
}

// ---------------- finalize stats ---------------------------------------------
__global__ void finalize_kernel(float* sumArr, float* sqArr, int C) {
    int i = blockIdx.x * blockDim.x + threadIdx.x;
    if (i < Bb * C) {
        float cnt = (float)g_cnt[i / C];
        float mean = sumArr[i] / cnt;
        float var = sqArr[i] / cnt - mean * mean;
        sumArr[i] = mean;
        sqArr[i] = rsqrtf(fmaxf(var, 0.f) + EPSf);
    }
}

// ---------------- norm1 + relu + fp16 hi/lo split (feeds conv2) --------------
__global__ void __launch_bounds__(256) norm_split_h_kernel(const int* __restrict__ batch_idx,
                                                           const float* __restrict__ mean,
                                                           const float* __restrict__ inv) {
    long long total = (long long)Nv * 16;
    long long i = (long long)blockIdx.x * blockDim.x + threadIdx.x;
    long long stride = (long long)gridDim.x * blockDim.x;
    for (; i < total; i += stride) {
        int row = (int)(i >> 4);
        int cg = (int)(i & 15);
        int b = batch_idx[row];
        float4 v = ((const float4*)g_x1)[i];
        float4 m = ((const float4*)mean)[b * 16 + cg];
        float4 s = ((const float4*)inv)[b * 16 + cg];
        float a0 = fmaxf((v.x - m.x) * s.x, 0.f);
        float a1 = fmaxf((v.y - m.y) * s.y, 0.f);
        float a2 = fmaxf((v.z - m.z) * s.z, 0.f);
        float a3 = fmaxf((v.w - m.w) * s.w, 0.f);
        __half h0, h1, h2, h3, l0, l1, l2, l3;
        split_h(a0, h0, l0); split_h(a1, h1, l1);
        split_h(a2, h2, l2); split_h(a3, h3, l3);
        __half2* ph = (__half2*)&g_x1h[(size_t)row * 64 + cg * 4];
        __half2* pl = (__half2*)&g_x1l[(size_t)row * 64 + cg * 4];
        ph[0] = __half2(h0, h1);
        ph[1] = __half2(h2, h3);
        pl[0] = __half2(l0, l1);
        pl[1] = __half2(l2, l3);
    }
}

// ---------------- norm2 + relu + bf16 hi/lo split (feeds conv3) --------------
__global__ void __launch_bounds__(256) norm_split_b_kernel(const int* __restrict__ batch_idx,
                                                           const float* __restrict__ mean,
                                                           const float* __restrict__ inv) {
    long long total = (long long)Nv * 16;
    long long i = (long long)blockIdx.x * blockDim.x + threadIdx.x;
    long long stride = (long long)gridDim.x * blockDim.x;
    for (; i < total; i += stride) {
        int row = (int)(i >> 4);
        int cg = (int)(i & 15);
        int b = batch_idx[row];
        float4 v = ((const float4*)g_x2)[i];
        float4 m = ((const float4*)mean)[b * 16 + cg];
        float4 s = ((const float4*)inv)[b * 16 + cg];
        float a0 = fmaxf((v.x - m.x) * s.x, 0.f);
        float a1 = fmaxf((v.y - m.y) * s.y, 0.f);
        float a2 = fmaxf((v.z - m.z) * s.z, 0.f);
        float a3 = fmaxf((v.w - m.w) * s.w, 0.f);
        __nv_bfloat16 h0, h1, h2, h3, l0, l1, l2, l3;
        split_bf(a0, h0, l0); split_bf(a1, h1, l1);
        split_bf(a2, h2, l2); split_bf(a3, h3, l3);
        __nv_bfloat162* ph = (__nv_bfloat162*)&g_x2h[(size_t)row * 64 + cg * 4];
        __nv_bfloat162* pl = (__nv_bfloat162*)&g_x2l[(size_t)row * 64 + cg * 4];
        ph[0] = __nv_bfloat162(h0, h1);
        ph[1] = __nv_bfloat162(h2, h3);
        pl[0] = __nv_bfloat162(l0, l1);
        pl[1] = __nv_bfloat162(l2, l3);
    }
}

// ---------------- conv2: persistent pipelined fp16 2-term gather-GEMM-scatter
// grid 296 (2/SM); 2-stage cp.async pipeline; per tile M=128 pairs, N=64, K=64
// smem: stage s A at s*36864 (Ah 18432 + Al 18432); Wh at 73728 (9216)
__global__ void __launch_bounds__(256, 2) conv2_mma_kernel(const int* __restrict__ in_idx,
                                                           const int* __restrict__ out_idx) {
    extern __shared__ __align__(16) char sm2[];
    __half* Wh = (__half*)(sm2 + 73728);
    __shared__ int s_in[2][128], s_out[2][128];

    int t = threadIdx.x;
    int per = (C2_TILES + C2_GRID - 1) / C2_GRID;   // 72
    int start = blockIdx.x * per;
    int end = min(start + per, C2_TILES);
    if (start >= end) return;

    int wid = t >> 5, lane = t & 31;
    int mb = (wid >> 1) * 32;
    int nb = (wid & 1) * 32;
    int a_row = lane & 15;
    int a_koff = (lane >> 4) << 3;
    int b_n = (lane & 7) + ((lane >> 4) << 3);
    int b_koff = ((lane >> 3) & 1) << 3;

    int cur_k = -1;

    {
        int k0 = start / C2_TPK;
        int m0 = (start % C2_TPK) * 128;
        if (t < 128) {
            int p = m0 + t;
            bool v = (p < Mm);
            s_in[0][t]  = v ? in_idx[(size_t)k0 * Mm + p] : -1;
            s_out[0][t] = v ? out_idx[(size_t)k0 * Mm + p] : -1;
        }
    }
    __syncthreads();
    {
        char* base = sm2;   // stage 0
#pragma unroll
        for (int e = t; e < 1024; e += 256) {
            int r = e >> 3, q = e & 7;
            int src = s_in[0][r];
            bool v = (src >= 0);
            size_t off = (size_t)(v ? src : 0) * 64 + q * 8;
            int sz = v ? 16 : 0;
            cp16(smem_u32(base + r * 144 + q * 16),         g_x1h + off, sz);
            cp16(smem_u32(base + 18432 + r * 144 + q * 16), g_x1l + off, sz);
        }
        CP_COMMIT();
    }

    for (int i = start; i < end; i++) {
        int s = (i - start) & 1;
        int ns = s ^ 1;
        int k = i / C2_TPK;

        int ri = -1, ro = -1;
        bool have_next = (i + 1 < end);
        if (have_next && t < 128) {
            int nk = (i + 1) / C2_TPK;
            int m0 = ((i + 1) % C2_TPK) * 128;
            int p = m0 + t;
            if (p < Mm) {
                ri = in_idx[(size_t)nk * Mm + p];
                ro = out_idx[(size_t)nk * Mm + p];
            }
        }

        CP_WAIT0();
        __syncthreads();

        if (have_next && t < 128) { s_in[ns][t] = ri; s_out[ns][t] = ro; }
        if (k != cur_k) {
            const __half* Wkh = g_W2h + (size_t)k * 4096;
#pragma unroll
            for (int e4 = t; e4 < 512; e4 += 256) {
                int d = e4 >> 3, q = e4 & 7;
                *(uint4*)&Wh[d * 72 + q * 8] = *(const uint4*)&Wkh[d * 64 + q * 8];
            }
            cur_k = k;
        }
        __syncthreads();

        if (have_next) {
            char* base = sm2 + ns * 36864;
#pragma unroll
            for (int e = t; e < 1024; e += 256) {
                int r = e >> 3, q = e & 7;
                int src = s_in[ns][r];
                bool v = (src >= 0);
                size_t off = (size_t)(v ? src : 0) * 64 + q * 8;
                int sz = v ? 16 : 0;
                cp16(smem_u32(base + r * 144 + q * 16),         g_x1h + off, sz);
                cp16(smem_u32(base + 18432 + r * 144 + q * 16), g_x1l + off, sz);
            }
            CP_COMMIT();
        }

        const __half* AhS = (const __half*)(sm2 + s * 36864);
        const __half* AlS = (const __half*)(sm2 + s * 36864 + 18432);

        float acc[2][4][4];
#pragma unroll
        for (int ii = 0; ii < 2; ii++)
#pragma unroll
            for (int j = 0; j < 4; j++)
#pragma unroll
                for (int q = 0; q < 4; q++) acc[ii][j][q] = 0.f;

#pragma unroll
        for (int term = 0; term < 2; term++) {
            const __half* A = term ? AlS : AhS;
#pragma unroll
            for (int ks = 0; ks < 4; ks++) {
                int k0 = ks * 16;
                uint32_t af0[4], af1[4], bf0[4], bf1[4];
                ldsm_x4(af0, smem_u32(&A[(mb + a_row) * 72 + k0 + a_koff]));
                ldsm_x4(af1, smem_u32(&A[(mb + 16 + a_row) * 72 + k0 + a_koff]));
                ldsm_x4(bf0, smem_u32(&Wh[(nb + b_n) * 72 + k0 + b_koff]));
                ldsm_x4(bf1, smem_u32(&Wh[(nb + 16 + b_n) * 72 + k0 + b_koff]));
                mma_f16(acc[0][0], af0, bf0[0], bf0[1]);
                mma_f16(acc[0][1], af0, bf0[2], bf0[3]);
                mma_f16(acc[0][2], af0, bf1[0], bf1[1]);
                mma_f16(acc[0][3], af0, bf1[2], bf1[3]);
                mma_f16(acc[1][0], af1, bf0[0], bf0[1]);
                mma_f16(acc[1][1], af1, bf0[2], bf0[3]);
                mma_f16(acc[1][2], af1, bf1[0], bf1[1]);
                mma_f16(acc[1][3], af1, bf1[2], bf1[3]);
            }
        }

        __syncthreads();

        float* Cs = (float*)(sm2 + s * 36864);
        int g = lane >> 2, tg = lane & 3;
#pragma unroll
        for (int mi = 0; mi < 2; mi++) {
            int row = mb + mi * 16 + g;
#pragma unroll
            for (int nj = 0; nj < 4; nj++) {
                int col = nb + nj * 8 + tg * 2;
                *(float2*)&Cs[row * 68 + col]       = make_float2(acc[mi][nj][0], acc[mi][nj][1]);
                *(float2*)&Cs[(row + 8) * 68 + col] = make_float2(acc[mi][nj][2], acc[mi][nj][3]);
            }
        }
        __syncthreads();

        {
            int r = t >> 1, h = (t & 1) * 32;
            int dst = s_out[s][r];
            if (dst >= 0) {
                float* p = g_x2 + (size_t)dst * 64 + h;
                const float* c = &Cs[r * 68 + h];
#pragma unroll
                for (int j = 0; j < 8; j++)
                    red_v4(p + j * 4, c[j * 4], c[j * 4 + 1], c[j * 4 + 2], c[j * 4 + 3]);
            }
        }
    }
}

// ---------------- stats2 ------------------------------------------------------
__global__ void __launch_bounds__(256) stats2_kernel(const float* __restrict__ x,
                                                     const int* __restrict__ batch_idx,
                                                     float* __restrict__ gsum,
                                                     float* __restrict__ gsq) {
    __shared__ float sm[2048];
    int t = threadIdx.x;
    int r0 = blockIdx.x * 128;
    int r1 = min(r0 + 128, Nv);
    int cg = t & 15, rg = t >> 4;
    int b0 = batch_idx[r0], b1 = batch_idx[r1 - 1];

    if (b0 == b1) {
        float4 s = make_float4(0.f, 0.f, 0.f, 0.f);
        float4 q = make_float4(0.f, 0.f, 0.f, 0.f);
#pragma unroll 4
        for (int r = r0 + rg; r < r1; r += 16) {
            float4 v = *(const float4*)&x[(size_t)r * 64 + cg * 4];
            s.x += v.x; s.y += v.y; s.z += v.z; s.w += v.w;
            q.x += v.x * v.x; q.y += v.y * v.y; q.z += v.z * v.z; q.w += v.w * v.w;
        }
        *(float4*)&sm[rg * 64 + cg * 4]        = s;
        *(float4*)&sm[1024 + rg * 64 + cg * 4] = q;
        __syncthreads();
        if (t < 64) {
            float v = 0.f;
#pragma unroll
            for (int u = 0; u < 16; u++) v += sm[u * 64 + t];
            atomicAdd(&gsum[b0 * 64 + t], v);
        } else if (t < 128) {
            int c = t - 64;
            float v = 0.f;
#pragma unroll
            for (int u = 0; u < 16; u++) v += sm[1024 + u * 64 + c];
            atomicAdd(&gsq[b0 * 64 + c], v);
        }
    } else {
        for (int i = t; i < 512; i += 256) sm[i] = 0.f;
        __syncthreads();
        for (int r = r0 + rg; r < r1; r += 16) {
            int b = batch_idx[r];
            float4 v = *(const float4*)&x[(size_t)r * 64 + cg * 4];
            atomicAdd(&sm[b * 64 + cg * 4], v.x);
            atomicAdd(&sm[b * 64 + cg * 4 + 1], v.y);
            atomicAdd(&sm[b * 64 + cg * 4 + 2], v.z);
            atomicAdd(&sm[b * 64 + cg * 4 + 3], v.w);
            atomicAdd(&sm[256 + b * 64 + cg * 4], v.x * v.x);
            atomicAdd(&sm[256 + b * 64 + cg * 4 + 1], v.y * v.y);
            atomicAdd(&sm[256 + b * 64 + cg * 4 + 2], v.z * v.z);
            atomicAdd(&sm[256 + b * 64 + cg * 4 + 3], v.w * v.w);
        }
        __syncthreads();
        if (t < 256) {
            if (sm[t] != 0.f)       atomicAdd(&gsum[t], sm[t]);
            if (sm[256 + t] != 0.f) atomicAdd(&gsq[t], sm[256 + t]);
        }
    }
}

// ---------------- conv3: mma.sync, pre-split bf16 gather -> GEMM -> out + stats3
__global__ void __launch_bounds__(256, 2) conv3_mma_kernel(float* __restrict__ out,
                                                           const int* __restrict__ batch_idx,
                                                           float* __restrict__ gsum,
                                                           float* __restrict__ gsq) {
    extern __shared__ __align__(16) char sm3[];
    __nv_bfloat16* Ah = (__nv_bfloat16*)sm3;
    __nv_bfloat16* Al = (__nv_bfloat16*)(sm3 + 18432);
    __nv_bfloat16* Wh = (__nv_bfloat16*)(sm3 + 36864);
    __nv_bfloat16* Wl = (__nv_bfloat16*)(sm3 + 46080);
    float* Cs = (float*)sm3;
    __shared__ int s_b[128];
    __shared__ float sred[256], qred[256];

    int t = threadIdx.x;
    int row0 = blockIdx.x * 128;
    int col0 = blockIdx.y * 64;

    if (t < 128) {
        int r = row0 + t;
        s_b[t] = (r < Nv) ? batch_idx[r] : -1;
    }

    // gather pre-split bf16 rows
#pragma unroll
    for (int e = t; e < 1024; e += 256) {
        int r = e >> 3, q = e & 7;
        int row = row0 + r;
        uint4 vh = make_uint4(0u, 0u, 0u, 0u);
        uint4 vl = vh;
        if (row < Nv) {
            vh = *(const uint4*)&g_x2h[(size_t)row * 64 + q * 8];
            vl = *(const uint4*)&g_x2l[(size_t)row * 64 + q * 8];
        }
        *(uint4*)&Ah[r * 72 + q * 8] = vh;
        *(uint4*)&Al[r * 72 + q * 8] = vl;
    }
#pragma unroll
    for (int e4 = t; e4 < 512; e4 += 256) {
        int n = e4 >> 3, q = e4 & 7;
        *(uint4*)&Wh[n * 72 + q * 8] = *(const uint4*)&g_W3h[(col0 + n) * 64 + q * 8];
        *(uint4*)&Wl[n * 72 + q * 8] = *(const uint4*)&g_W3l[(col0 + n) * 64 + q * 8];
    }
    __syncthreads();

    int wid = t >> 5, lane = t & 31;
    int mb = (wid >> 1) * 32;
    int nb = (wid & 1) * 32;

    float acc[2][4][4];
#pragma unroll
    for (int i = 0; i < 2; i++)
#pragma unroll
        for (int j = 0; j < 4; j++)
#pragma unroll
            for (int q = 0; q < 4; q++) acc[i][j][q] = 0.f;

    int a_row = lane & 15;
    int a_koff = (lane >> 4) << 3;
    int b_n = (lane & 7) + ((lane >> 4) << 3);
    int b_koff = ((lane >> 3) & 1) << 3;

#pragma unroll
    for (int term = 0; term < 3; term++) {
        const __nv_bfloat16* A = (term == 1) ? Al : Ah;
        const __nv_bfloat16* W = (term == 2) ? Wl : Wh;
#pragma unroll
        for (int ks = 0; ks < 4; ks++) {
            int k0 = ks * 16;
            uint32_t af0[4], af1[4], bf0[4], bf1[4];
            ldsm_x4(af0, smem_u32(&A[(mb + a_row) * 72 + k0 + a_koff]));
            ldsm_x4(af1, smem_u32(&A[(mb + 16 + a_row) * 72 + k0 + a_koff]));
            ldsm_x4(bf0, smem_u32(&W[(nb + b_n) * 72 + k0 + b_koff]));
            ldsm_x4(bf1, smem_u32(&W[(nb + 16 + b_n) * 72 + k0 + b_koff]));
            mma_bf16(acc[0][0], af0, bf0[0], bf0[1]);
            mma_bf16(acc[0][1], af0, bf0[2], bf0[3]);
            mma_bf16(acc[0][2], af0, bf1[0], bf1[1]);
            mma_bf16(acc[0][3], af0, bf1[2], bf1[3]);
            mma_bf16(acc[1][0], af1, bf0[0], bf0[1]);
            mma_bf16(acc[1][1], af1, bf0[2], bf0[3]);
            mma_bf16(acc[1][2], af1, bf1[0], bf1[1]);
            mma_bf16(acc[1][3], af1, bf1[2], bf1[3]);
        }
    }

    __syncthreads();
    int g = lane >> 2, tg = lane & 3;
#pragma unroll
    for (int mi = 0; mi < 2; mi++) {
        int row = mb + mi * 16 + g;
#pragma unroll
        for (int nj = 0; nj < 4; nj++) {
            int col = nb + nj * 8 + tg * 2;
            *(float2*)&Cs[row * 68 + col]       = make_float2(acc[mi][nj][0], acc[mi][nj][1]);
            *(float2*)&Cs[(row + 8) * 68 + col] = make_float2(acc[mi][nj][2], acc[mi][nj][3]);
        }
    }
    __syncthreads();

#pragma unroll
    for (int e4 = t; e4 < 2048; e4 += 256) {
        int r = e4 >> 4, cg = e4 & 15;
        int row = row0 + r;
        if (row < Nv)
            *(float4*)&out[(size_t)row * 256 + col0 + cg * 4] = *(const float4*)&Cs[r * 68 + cg * 4];
    }

    int b0 = s_b[0];
    bool fast;
    if (s_b[127] == b0) fast = true;
    else if (row0 + 127 >= Nv) {
        int lastr = Nv - 1 - row0;
        fast = (lastr >= 0 && s_b[lastr] == b0);
    } else fast = false;

    if (fast) {
        int col = t & 63, rg = t >> 6;
        float s = 0.f, q = 0.f;
#pragma unroll 8
        for (int r = rg * 32; r < rg * 32 + 32; r++) {
            float v = Cs[r * 68 + col];
            s += v; q += v * v;
        }
        sred[rg * 64 + col] = s;
        qred[rg * 64 + col] = q;
        __syncthreads();
        if (t < 64) {
            float v = sred[t] + sred[64 + t] + sred[128 + t] + sred[192 + t];
            atomicAdd(&gsum[b0 * 256 + col0 + t], v);
        } else if (t < 128) {
            int c = t - 64;
            float v = qred[c] + qred[64 + c] + qred[128 + c] + qred[192 + c];
            atomicAdd(&gsq[b0 * 256 + col0 + c], v);
        }
    } else {
        for (int e = t; e < 8192; e += 256) {
            int r = e >> 6, c = e & 63;
            if (row0 + r < Nv) {
                float v = Cs[r * 68 + c];
                int b = s_b[r];
                atomicAdd(&gsum[b * 256 + col0 + c], v);
                atomicAdd(&gsq[b * 256 + col0 + c], v * v);
            }
        }
    }
}

// ---------------- final: normalize3 + residual + relu ------------------------
__global__ void final_kernel(float* __restrict__ y,
                             const float* __restrict__ feats,
                             const int* __restrict__ batch_idx,
                             const float* __restrict__ mean,
                             const float* __restrict__ inv) {
    const int C4 = 64;
    long long total = (long long)Nv * C4;
    long long i = (long long)blockIdx.x * blockDim.x + threadIdx.x;
    long long stride = (long long)gridDim.x * blockDim.x;
    for (; i < total; i += stride) {
        int row = (int)(i / C4);
        int cg = (int)(i % C4);
        int b = batch_idx[row];
        float4 v = ((float4*)y)[i];
        float4 f = ((const float4*)feats)[i];
        float4 m = ((const float4*)mean)[b * C4 + cg];
        float4 sv = ((const float4*)inv)[b * C4 + cg];
        v.x = fmaxf((v.x - m.x) * sv.x + f.x, 0.f);
        v.y = fmaxf((v.y - m.y) * sv.y + f.y, 0.f);
        v.z = fmaxf((v.z - m.z) * sv.z + f.z, 0.f);
        v.w = fmaxf((v.w - m.w) * sv.w + f.w, 0.f);
        ((float4*)y)[i] = v;
    }
}

// ---------------- launch -----------------------------------------------------
extern "C" void kernel_launch(void* const* d_in, const int* in_sizes, int n_in,
                              void* d_out, int out_size) {
    const float* feats     = (const float*)d_in[0];
    const float* W1        = (const float*)d_in[1];
    const float* W2        = (const float*)d_in[2];
    const float* W3        = (const float*)d_in[3];
    const int*   in_idx    = (const int*)d_in[4];
    const int*   out_idx   = (const int*)d_in[5];
    const int*   batch_idx = (const int*)d_in[6];
    float* out = (float*)d_out;

    float *p_x2, *p_sum1, *p_sq1, *p_sum2, *p_sq2, *p_sum3, *p_sq3;
    cudaGetSymbolAddress((void**)&p_x2, g_x2);
    cudaGetSymbolAddress((void**)&p_sum1, g_sum1);
    cudaGetSymbolAddress((void**)&p_sq1, g_sq1);
    cudaGetSymbolAddress((void**)&p_sum2, g_sum2);
    cudaGetSymbolAddress((void**)&p_sq2, g_sq2);
    cudaGetSymbolAddress((void**)&p_sum3, g_sum3);
    cudaGetSymbolAddress((void**)&p_sq3, g_sq3);

    const int smemA = 55296;
    const int smem2 = 82944;   // 2 A stages (73728) + Wh (9216)
    cudaFuncSetAttribute(conv1_mma_kernel, cudaFuncAttributeMaxDynamicSharedMemorySize, smemA);
    cudaFuncSetAttribute(conv2_mma_kernel, cudaFuncAttributeMaxDynamicSharedMemorySize, smem2);
    cudaFuncSetAttribute(conv3_mma_kernel, cudaFuncAttributeMaxDynamicSharedMemorySize, smemA);

    zero_kernel<<<2048, 256>>>();
    count_kernel<<<391, 256>>>(batch_idx);
    wsplit_kernel<<<(16384 + Kk * 4096 + 16384 + 255) / 256, 256>>>(W1, W2, W3);

    // conv1 (tensor) + fused stats1
    conv1_mma_kernel<<<(Nv + 127) / 128, 256, smemA>>>(feats, batch_idx, p_sum1, p_sq1);
    finalize_kernel<<<1, 256>>>(p_sum1, p_sq1, 64);

    // norm1 + relu + fp16 hi/lo split
    norm_split_h_kernel<<<4096, 256>>>(batch_idx, p_sum1, p_sq1);

    // conv2: persistent pipelined fp16 2-term tensor gather-GEMM-scatter
    conv2_mma_kernel<<<C2_GRID, 256, smem2>>>(in_idx, out_idx);
    stats2_kernel<<<(Nv + 127) / 128, 256>>>(p_x2, batch_idx, p_sum2, p_sq2);
    finalize_kernel<<<1, 256>>>(p_sum2, p_sq2, 64);

    // norm2 + relu + bf16 hi/lo split
    norm_split_b_kernel<<<4096, 256>>>(batch_idx, p_sum2, p_sq2);

    // conv3 (tensor, pre-split gather) + fused stats3
    dim3 g3((Nv + 127) / 128, 4);
    conv3_mma_kernel<<<g3, 256, smemA>>>(out, batch_idx, p_sum3, p_sq3);
    finalize_kernel<<<4, 256>>>(p_sum3, p_sq3, 256);

    final_kernel<<<16384, 256>>>(out, feats, batch_idx, p_sum3, p_sq3);
}

// round 9
// speedup vs baseline: 2.6544x; 1.1451x over previous
#include <cuda_runtime.h>
#include <cuda_bf16.h>
#include <cuda_fp16.h>
#include <cstdint>

#define Nv   200000
#define Kk   27
#define Mm   100000
#define Bb   4
#define EPSf 1e-5f
#define C2_TPK 782                 // tiles per k offset (ceil(Mm/128))
#define C2_TILES (Kk * C2_TPK)     // 21114
#define C2_GRID 296                // 2 CTAs/SM * 148

// ---------------- scratch (device globals — no runtime allocation) ----------
__device__ float g_x1[(size_t)Nv * 64];          // conv1 out (raw, pre-norm)
__device__ float g_x2[(size_t)Nv * 64];          // conv2 accum (raw, pre-norm)
__device__ __half g_x1h[(size_t)Nv * 64];        // normalized x1, fp16 hi
__device__ __half g_x1l[(size_t)Nv * 64];        // normalized x1, fp16 lo
__device__ __half g_x2h[(size_t)Nv * 64];        // normalized x2, fp16 hi
__device__ __half g_x2l[(size_t)Nv * 64];        // normalized x2, fp16 lo
__device__ __nv_bfloat16 g_W1h[64 * 256],  g_W1l[64 * 256];    // [d][c] col-major
__device__ __half        g_W2h[Kk * 4096];                     // [k][d][c] fp16
__device__ __half        g_W3h[256 * 64];                      // [n][c] fp16
__device__ float g_sum1[Bb * 64], g_sq1[Bb * 64];
__device__ float g_sum2[Bb * 64], g_sq2[Bb * 64];
__device__ float g_sum3[Bb * 256], g_sq3[Bb * 256];
__device__ int   g_cnt[Bb];

// ---------------- helpers -----------------------------------------------------
__device__ __forceinline__ void red_v4(float* p, float a, float b, float c, float d) {
    asm volatile("red.global.add.v4.f32 [%0], {%1,%2,%3,%4};"
                 :: "l"(p), "f"(a), "f"(b), "f"(c), "f"(d) : "memory");
}
__device__ __forceinline__ void red_v2(float* p, float a, float b) {
    asm volatile("red.global.add.v2.f32 [%0], {%1,%2};"
                 :: "l"(p), "f"(a), "f"(b) : "memory");
}
__device__ __forceinline__ uint32_t smem_u32(const void* p) {
    uint32_t a;
    asm("{ .reg .u64 t; cvta.to.shared.u64 t, %1; cvt.u32.u64 %0, t; }"
        : "=r"(a) : "l"(p));
    return a;
}
__device__ __forceinline__ void ldsm_x4(uint32_t* r, uint32_t addr) {
    asm volatile("ldmatrix.sync.aligned.m8n8.x4.shared.b16 {%0,%1,%2,%3}, [%4];"
        : "=r"(r[0]), "=r"(r[1]), "=r"(r[2]), "=r"(r[3]) : "r"(addr));
}
__device__ __forceinline__ void mma_bf16(float* c, const uint32_t* a,
                                         uint32_t b0, uint32_t b1) {
    asm volatile("mma.sync.aligned.m16n8k16.row.col.f32.bf16.bf16.f32 "
        "{%0,%1,%2,%3}, {%4,%5,%6,%7}, {%8,%9}, {%0,%1,%2,%3};"
        : "+f"(c[0]), "+f"(c[1]), "+f"(c[2]), "+f"(c[3])
        : "r"(a[0]), "r"(a[1]), "r"(a[2]), "r"(a[3]), "r"(b0), "r"(b1));
}
__device__ __forceinline__ void mma_f16(float* c, const uint32_t* a,
                                        uint32_t b0, uint32_t b1) {
    asm volatile("mma.sync.aligned.m16n8k16.row.col.f32.f16.f16.f32 "
        "{%0,%1,%2,%3}, {%4,%5,%6,%7}, {%8,%9}, {%0,%1,%2,%3};"
        : "+f"(c[0]), "+f"(c[1]), "+f"(c[2]), "+f"(c[3])
        : "r"(a[0]), "r"(a[1]), "r"(a[2]), "r"(a[3]), "r"(b0), "r"(b1));
}
__device__ __forceinline__ void split_bf(float a, __nv_bfloat16& h, __nv_bfloat16& l) {
    h = __float2bfloat16(a);
    l = __float2bfloat16(a - __bfloat162float(h));
}
__device__ __forceinline__ void split_h(float a, __half& h, __half& l) {
    h = __float2half_rn(a);
    l = __float2half_rn(a - __half2float(h));
}
__device__ __forceinline__ void cp16(uint32_t dst, const void* src, int sz) {
    asm volatile("cp.async.cg.shared.global [%0], [%1], 16, %2;"
                 :: "r"(dst), "l"(src), "r"(sz));
}
#define CP_COMMIT() asm volatile("cp.async.commit_group;" ::: "memory")
#define CP_WAIT0()  asm volatile("cp.async.wait_group 0;" ::: "memory")

// ---------------- zero scratch ----------------------------------------------
__global__ void zero_kernel() {
    long long i = (long long)blockIdx.x * blockDim.x + threadIdx.x;
    long long stride = (long long)gridDim.x * blockDim.x;
    const long long total4 = (long long)Nv * 16;
    float4* p = reinterpret_cast<float4*>(g_x2);
    float4 z = make_float4(0.f, 0.f, 0.f, 0.f);
    for (long long j = i; j < total4; j += stride) p[j] = z;
    if (i < Bb * 64)  { g_sum1[i] = 0.f; g_sq1[i] = 0.f; g_sum2[i] = 0.f; g_sq2[i] = 0.f; }
    if (i < Bb * 256) { g_sum3[i] = 0.f; g_sq3[i] = 0.f; }
    if (i < Bb) g_cnt[i] = 0;
}

// ---------------- per-batch counts ------------------------------------------
__global__ void count_kernel(const int* __restrict__ batch_idx) {
    __shared__ int s[Bb];
    if (threadIdx.x < Bb) s[threadIdx.x] = 0;
    __syncthreads();
    int i = blockIdx.x * blockDim.x + threadIdx.x;
    int stride = gridDim.x * blockDim.x;
    for (int j = i; j < Nv; j += stride) atomicAdd(&s[batch_idx[j]], 1);
    __syncthreads();
    if (threadIdx.x < Bb) atomicAdd(&g_cnt[threadIdx.x], s[threadIdx.x]);
}

// ---------------- weight pre-split -------------------------------------------
__global__ void wsplit_kernel(const float* __restrict__ W1,
                              const float* __restrict__ W2,
                              const float* __restrict__ W3) {
    int i = blockIdx.x * blockDim.x + threadIdx.x;
    if (i < 16384) {
        int d = i >> 8, c = i & 255;
        __nv_bfloat16 h, l;
        split_bf(W1[c * 64 + d], h, l);
        g_W1h[i] = h; g_W1l[i] = l;
    } else if (i < 16384 + Kk * 4096) {
        int j = i - 16384;
        int kk = j >> 12, r = j & 4095;
        int d = r >> 6, c = r & 63;
        g_W2h[j] = __float2half_rn(W2[kk * 4096 + c * 64 + d]);
    } else if (i < 16384 + Kk * 4096 + 16384) {
        int j = i - 16384 - Kk * 4096;
        int n = j >> 6, c = j & 63;
        g_W3h[j] = __float2half_rn(W3[c * 256 + n]);
    }
}

// ---------------- conv1: mma.sync, x1 = feats @ W1, fused stats1 --------------
__global__ void __launch_bounds__(256, 2) conv1_mma_kernel(const float* __restrict__ feats,
                                                           const int* __restrict__ batch_idx,
                                                           float* __restrict__ gsum,
                                                           float* __restrict__ gsq) {
    extern __shared__ __align__(16) char sm1[];
    __nv_bfloat16* Ah = (__nv_bfloat16*)sm1;
    __nv_bfloat16* Al = (__nv_bfloat16*)(sm1 + 18432);
    __nv_bfloat16* Wh = (__nv_bfloat16*)(sm1 + 36864);
    __nv_bfloat16* Wl = (__nv_bfloat16*)(sm1 + 46080);
    float* Cs = (float*)sm1;
    __shared__ int s_b[128];
    __shared__ float sred[256], qred[256];

    int t = threadIdx.x;
    int row0 = blockIdx.x * 128;
    if (t < 128) {
        int r = row0 + t;
        s_b[t] = (r < Nv) ? batch_idx[r] : -1;
    }

    int wid = t >> 5, lane = t & 31;
    int mb = (wid >> 1) * 32;
    int nb = (wid & 1) * 32;
    int a_row = lane & 15;
    int a_koff = (lane >> 4) << 3;
    int b_n = (lane & 7) + ((lane >> 4) << 3);
    int b_koff = ((lane >> 3) & 1) << 3;

    float acc[2][4][4];
#pragma unroll
    for (int i = 0; i < 2; i++)
#pragma unroll
        for (int j = 0; j < 4; j++)
#pragma unroll
            for (int q = 0; q < 4; q++) acc[i][j][q] = 0.f;

    for (int k0 = 0; k0 < 256; k0 += 64) {
        __syncthreads();
#pragma unroll
        for (int e4 = t; e4 < 2048; e4 += 256) {
            int r = e4 >> 4, cg = e4 & 15;
            int row = row0 + r;
            float4 v = make_float4(0.f, 0.f, 0.f, 0.f);
            if (row < Nv) v = *(const float4*)&feats[(size_t)row * 256 + k0 + cg * 4];
            __nv_bfloat16 h0, h1, h2, h3, l0, l1, l2, l3;
            split_bf(v.x, h0, l0); split_bf(v.y, h1, l1);
            split_bf(v.z, h2, l2); split_bf(v.w, h3, l3);
            __nv_bfloat162* ph = (__nv_bfloat162*)&Ah[r * 72 + cg * 4];
            __nv_bfloat162* pl = (__nv_bfloat162*)&Al[r * 72 + cg * 4];
            ph[0] = __nv_bfloat162(h0, h1); ph[1] = __nv_bfloat162(h2, h3);
            pl[0] = __nv_bfloat162(l0, l1); pl[1] = __nv_bfloat162(l2, l3);
        }
#pragma unroll
        for (int e4 = t; e4 < 512; e4 += 256) {
            int d = e4 >> 3, q = e4 & 7;
            *(uint4*)&Wh[d * 72 + q * 8] = *(const uint4*)&g_W1h[d * 256 + k0 + q * 8];
            *(uint4*)&Wl[d * 72 + q * 8] = *(const uint4*)&g_W1l[d * 256 + k0 + q * 8];
        }
        __syncthreads();

#pragma unroll
        for (int term = 0; term < 3; term++) {
            const __nv_bfloat16* A = (term == 1) ? Al : Ah;
            const __nv_bfloat16* W = (term == 2) ? Wl : Wh;
#pragma unroll
            for (int ks = 0; ks < 4; ks++) {
                int kc = ks * 16;
                uint32_t af0[4], af1[4], bf0[4], bf1[4];
                ldsm_x4(af0, smem_u32(&A[(mb + a_row) * 72 + kc + a_koff]));
                ldsm_x4(af1, smem_u32(&A[(mb + 16 + a_row) * 72 + kc + a_koff]));
                ldsm_x4(bf0, smem_u32(&W[(nb + b_n) * 72 + kc + b_koff]));
                ldsm_x4(bf1, smem_u32(&W[(nb + 16 + b_n) * 72 + kc + b_koff]));
                mma_bf16(acc[0][0], af0, bf0[0], bf0[1]);
                mma_bf16(acc[0][1], af0, bf0[2], bf0[3]);
                mma_bf16(acc[0][2], af0, bf1[0], bf1[1]);
                mma_bf16(acc[0][3], af0, bf1[2], bf1[3]);
                mma_bf16(acc[1][0], af1, bf0[0], bf0[1]);
                mma_bf16(acc[1][1], af1, bf0[2], bf0[3]);
                mma_bf16(acc[1][2], af1, bf1[0], bf1[1]);
                mma_bf16(acc[1][3], af1, bf1[2], bf1[3]);
            }
        }
    }

    __syncthreads();
    int g = lane >> 2, tg = lane & 3;
#pragma unroll
    for (int mi = 0; mi < 2; mi++) {
        int row = mb + mi * 16 + g;
#pragma unroll
        for (int nj = 0; nj < 4; nj++) {
            int col = nb + nj * 8 + tg * 2;
            *(float2*)&Cs[row * 68 + col]       = make_float2(acc[mi][nj][0], acc[mi][nj][1]);
            *(float2*)&Cs[(row + 8) * 68 + col] = make_float2(acc[mi][nj][2], acc[mi][nj][3]);
        }
    }
    __syncthreads();

#pragma unroll
    for (int e4 = t; e4 < 2048; e4 += 256) {
        int r = e4 >> 4, cg = e4 & 15;
        int row = row0 + r;
        if (row < Nv)
            *(float4*)&g_x1[(size_t)row * 64 + cg * 4] = *(const float4*)&Cs[r * 68 + cg * 4];
    }

    int b0 = s_b[0];
    bool fast;
    if (s_b[127] == b0) fast = true;
    else if (row0 + 127 >= Nv) {
        int lastr = Nv - 1 - row0;
        fast = (lastr >= 0 && s_b[lastr] == b0);
    } else fast = false;

    if (fast) {
        int col = t & 63, rg = t >> 6;
        float s = 0.f, q = 0.f;
#pragma unroll 8
        for (int r = rg * 32; r < rg * 32 + 32; r++) {
            float v = Cs[r * 68 + col];
            s += v; q += v * v;
        }
        sred[rg * 64 + col] = s;
        qred[rg * 64 + col] = q;
        __syncthreads();
        if (t < 64) {
            float v = sred[t] + sred[64 + t] + sred[128 + t] + sred[192 + t];
            atomicAdd(&gsum[b0 * 64 + t], v);
        } else if (t < 128) {
            int c = t - 64;
            float v = qred[c] + qred[64 + c] + qred[128 + c] + qred[192 + c];
            atomicAdd(&gsq[b0 * 64 + c], v);
        }
    } else {
        for (int e = t; e < 8192; e += 256) {
            int r = e >> 6, c = e & 63;
            if (row0 + r < Nv) {
                float v = Cs[r * 68 + c];
                int b = s_b[r];
                atomicAdd(&gsum[b * 64 + c], v);
                atomicAdd(&gsq[b * 64 + c], v * v);
            }
        }
    }
}

// ---------------- finalize stats ---------------------------------------------
__global__ void finalize_kernel(float* sumArr, float* sqArr, int C) {
    int i = blockIdx.x * blockDim.x + threadIdx.x;
    if (i < Bb * C) {
        float cnt = (float)g_cnt[i / C];
        float mean = sumArr[i] / cnt;
        float var = sqArr[i] / cnt - mean * mean;
        sumArr[i] = mean;
        sqArr[i] = rsqrtf(fmaxf(var, 0.f) + EPSf);
    }
}

// ---------------- norm + relu + fp16 hi/lo split (generic) -------------------
__global__ void __launch_bounds__(256) norm_split_kernel(const float* __restrict__ x,
                                                         __half* __restrict__ oh,
                                                         __half* __restrict__ ol,
                                                         const int* __restrict__ batch_idx,
                                                         const float* __restrict__ mean,
                                                         const float* __restrict__ inv) {
    long long total = (long long)Nv * 16;
    long long i = (long long)blockIdx.x * blockDim.x + threadIdx.x;
    long long stride = (long long)gridDim.x * blockDim.x;
    for (; i < total; i += stride) {
        int row = (int)(i >> 4);
        int cg = (int)(i & 15);
        int b = batch_idx[row];
        float4 v = ((const float4*)x)[i];
        float4 m = ((const float4*)mean)[b * 16 + cg];
        float4 s = ((const float4*)inv)[b * 16 + cg];
        float a0 = fmaxf((v.x - m.x) * s.x, 0.f);
        float a1 = fmaxf((v.y - m.y) * s.y, 0.f);
        float a2 = fmaxf((v.z - m.z) * s.z, 0.f);
        float a3 = fmaxf((v.w - m.w) * s.w, 0.f);
        __half h0, h1, h2, h3, l0, l1, l2, l3;
        split_h(a0, h0, l0); split_h(a1, h1, l1);
        split_h(a2, h2, l2); split_h(a3, h3, l3);
        __half2* ph = (__half2*)&oh[(size_t)row * 64 + cg * 4];
        __half2* pl = (__half2*)&ol[(size_t)row * 64 + cg * 4];
        ph[0] = __half2(h0, h1);
        ph[1] = __half2(h2, h3);
        pl[0] = __half2(l0, l1);
        pl[1] = __half2(l2, l3);
    }
}

// ---------------- conv2: persistent pipelined fp16 2-term gather-GEMM-scatter
// grid 296 (2/SM); 2-stage cp.async pipeline; register-direct red.v2 scatter
__global__ void __launch_bounds__(256, 2) conv2_mma_kernel(const int* __restrict__ in_idx,
                                                           const int* __restrict__ out_idx) {
    extern __shared__ __align__(16) char sm2[];
    __half* Wh = (__half*)(sm2 + 73728);
    __shared__ int s_in[2][128], s_out[2][128];

    int t = threadIdx.x;
    int per = (C2_TILES + C2_GRID - 1) / C2_GRID;   // 72
    int start = blockIdx.x * per;
    int end = min(start + per, C2_TILES);
    if (start >= end) return;

    int wid = t >> 5, lane = t & 31;
    int mb = (wid >> 1) * 32;
    int nb = (wid & 1) * 32;
    int a_row = lane & 15;
    int a_koff = (lane >> 4) << 3;
    int b_n = (lane & 7) + ((lane >> 4) << 3);
    int b_koff = ((lane >> 3) & 1) << 3;
    int g = lane >> 2, tg = lane & 3;

    int cur_k = -1;

    {
        int k0 = start / C2_TPK;
        int m0 = (start % C2_TPK) * 128;
        if (t < 128) {
            int p = m0 + t;
            bool v = (p < Mm);
            s_in[0][t]  = v ? in_idx[(size_t)k0 * Mm + p] : -1;
            s_out[0][t] = v ? out_idx[(size_t)k0 * Mm + p] : -1;
        }
    }
    __syncthreads();
    {
        char* base = sm2;   // stage 0
#pragma unroll
        for (int e = t; e < 1024; e += 256) {
            int r = e >> 3, q = e & 7;
            int src = s_in[0][r];
            bool v = (src >= 0);
            size_t off = (size_t)(v ? src : 0) * 64 + q * 8;
            int sz = v ? 16 : 0;
            cp16(smem_u32(base + r * 144 + q * 16),         g_x1h + off, sz);
            cp16(smem_u32(base + 18432 + r * 144 + q * 16), g_x1l + off, sz);
        }
        CP_COMMIT();
    }

    for (int i = start; i < end; i++) {
        int s = (i - start) & 1;
        int ns = s ^ 1;
        int k = i / C2_TPK;

        int ri = -1, ro = -1;
        bool have_next = (i + 1 < end);
        if (have_next && t < 128) {
            int nk = (i + 1) / C2_TPK;
            int m0 = ((i + 1) % C2_TPK) * 128;
            int p = m0 + t;
            if (p < Mm) {
                ri = in_idx[(size_t)nk * Mm + p];
                ro = out_idx[(size_t)nk * Mm + p];
            }
        }

        CP_WAIT0();
        __syncthreads();   // stage s ready; everyone past prev iter's reads

        if (have_next && t < 128) { s_in[ns][t] = ri; s_out[ns][t] = ro; }
        if (k != cur_k) {
            const __half* Wkh = g_W2h + (size_t)k * 4096;
#pragma unroll
            for (int e4 = t; e4 < 512; e4 += 256) {
                int d = e4 >> 3, q = e4 & 7;
                *(uint4*)&Wh[d * 72 + q * 8] = *(const uint4*)&Wkh[d * 64 + q * 8];
            }
            cur_k = k;
        }
        __syncthreads();

        if (have_next) {
            char* base = sm2 + ns * 36864;
#pragma unroll
            for (int e = t; e < 1024; e += 256) {
                int r = e >> 3, q = e & 7;
                int src = s_in[ns][r];
                bool v = (src >= 0);
                size_t off = (size_t)(v ? src : 0) * 64 + q * 8;
                int sz = v ? 16 : 0;
                cp16(smem_u32(base + r * 144 + q * 16),         g_x1h + off, sz);
                cp16(smem_u32(base + 18432 + r * 144 + q * 16), g_x1l + off, sz);
            }
            CP_COMMIT();
        }

        const __half* AhS = (const __half*)(sm2 + s * 36864);
        const __half* AlS = (const __half*)(sm2 + s * 36864 + 18432);

        float acc[2][4][4];
#pragma unroll
        for (int ii = 0; ii < 2; ii++)
#pragma unroll
            for (int j = 0; j < 4; j++)
#pragma unroll
                for (int q = 0; q < 4; q++) acc[ii][j][q] = 0.f;

#pragma unroll
        for (int term = 0; term < 2; term++) {
            const __half* A = term ? AlS : AhS;
#pragma unroll
            for (int ks = 0; ks < 4; ks++) {
                int k0 = ks * 16;
                uint32_t af0[4], af1[4], bf0[4], bf1[4];
                ldsm_x4(af0, smem_u32(&A[(mb + a_row) * 72 + k0 + a_koff]));
                ldsm_x4(af1, smem_u32(&A[(mb + 16 + a_row) * 72 + k0 + a_koff]));
                ldsm_x4(bf0, smem_u32(&Wh[(nb + b_n) * 72 + k0 + b_koff]));
                ldsm_x4(bf1, smem_u32(&Wh[(nb + 16 + b_n) * 72 + k0 + b_koff]));
                mma_f16(acc[0][0], af0, bf0[0], bf0[1]);
                mma_f16(acc[0][1], af0, bf0[2], bf0[3]);
                mma_f16(acc[0][2], af0, bf1[0], bf1[1]);
                mma_f16(acc[0][3], af0, bf1[2], bf1[3]);
                mma_f16(acc[1][0], af1, bf0[0], bf0[1]);
                mma_f16(acc[1][1], af1, bf0[2], bf0[3]);
                mma_f16(acc[1][2], af1, bf1[0], bf1[1]);
                mma_f16(acc[1][3], af1, bf1[2], bf1[3]);
            }
        }

        // scatter directly from registers (no staging, no extra syncs)
#pragma unroll
        for (int mi = 0; mi < 2; mi++) {
            int row = mb + mi * 16 + g;
            int dst0 = s_out[s][row];
            int dst1 = s_out[s][row + 8];
#pragma unroll
            for (int nj = 0; nj < 4; nj++) {
                int col = nb + nj * 8 + tg * 2;
                if (dst0 >= 0)
                    red_v2(g_x2 + (size_t)dst0 * 64 + col, acc[mi][nj][0], acc[mi][nj][1]);
                if (dst1 >= 0)
                    red_v2(g_x2 + (size_t)dst1 * 64 + col, acc[mi][nj][2], acc[mi][nj][3]);
            }
        }
    }
}

// ---------------- stats2 ------------------------------------------------------
__global__ void __launch_bounds__(256) stats2_kernel(const float* __restrict__ x,
                                                     const int* __restrict__ batch_idx,
                                                     float* __restrict__ gsum,
                                                     float* __restrict__ gsq) {
    __shared__ float sm[2048];
    int t = threadIdx.x;
    int r0 = blockIdx.x * 128;
    int r1 = min(r0 + 128, Nv);
    int cg = t & 15, rg = t >> 4;
    int b0 = batch_idx[r0], b1 = batch_idx[r1 - 1];

    if (b0 == b1) {
        float4 s = make_float4(0.f, 0.f, 0.f, 0.f);
        float4 q = make_float4(0.f, 0.f, 0.f, 0.f);
#pragma unroll 4
        for (int r = r0 + rg; r < r1; r += 16) {
            float4 v = *(const float4*)&x[(size_t)r * 64 + cg * 4];
            s.x += v.x; s.y += v.y; s.z += v.z; s.w += v.w;
            q.x += v.x * v.x; q.y += v.y * v.y; q.z += v.z * v.z; q.w += v.w * v.w;
        }
        *(float4*)&sm[rg * 64 + cg * 4]        = s;
        *(float4*)&sm[1024 + rg * 64 + cg * 4] = q;
        __syncthreads();
        if (t < 64) {
            float v = 0.f;
#pragma unroll
            for (int u = 0; u < 16; u++) v += sm[u * 64 + t];
            atomicAdd(&gsum[b0 * 64 + t], v);
        } else if (t < 128) {
            int c = t - 64;
            float v = 0.f;
#pragma unroll
            for (int u = 0; u < 16; u++) v += sm[1024 + u * 64 + c];
            atomicAdd(&gsq[b0 * 64 + c], v);
        }
    } else {
        for (int i = t; i < 512; i += 256) sm[i] = 0.f;
        __syncthreads();
        for (int r = r0 + rg; r < r1; r += 16) {
            int b = batch_idx[r];
            float4 v = *(const float4*)&x[(size_t)r * 64 + cg * 4];
            atomicAdd(&sm[b * 64 + cg * 4], v.x);
            atomicAdd(&sm[b * 64 + cg * 4 + 1], v.y);
            atomicAdd(&sm[b * 64 + cg * 4 + 2], v.z);
            atomicAdd(&sm[b * 64 + cg * 4 + 3], v.w);
            atomicAdd(&sm[256 + b * 64 + cg * 4], v.x * v.x);
            atomicAdd(&sm[256 + b * 64 + cg * 4 + 1], v.y * v.y);
            atomicAdd(&sm[256 + b * 64 + cg * 4 + 2], v.z * v.z);
            atomicAdd(&sm[256 + b * 64 + cg * 4 + 3], v.w * v.w);
        }
        __syncthreads();
        if (t < 256) {
            if (sm[t] != 0.f)       atomicAdd(&gsum[t], sm[t]);
            if (sm[256 + t] != 0.f) atomicAdd(&gsq[t], sm[256 + t]);
        }
    }
}

// ---------------- conv3: mma.sync fp16 2-term, pre-split gather -> out + stats3
__global__ void __launch_bounds__(256, 2) conv3_mma_kernel(float* __restrict__ out,
                                                           const int* __restrict__ batch_idx,
                                                           float* __restrict__ gsum,
                                                           float* __restrict__ gsq) {
    extern __shared__ __align__(16) char sm3[];
    __half* Ah = (__half*)sm3;
    __half* Al = (__half*)(sm3 + 18432);
    __half* Wh = (__half*)(sm3 + 36864);    // 64x72 fp16 = 9216 -> 46080 total
    float* Cs = (float*)sm3;                // overlay 128x68 f32 = 34816
    __shared__ int s_b[128];
    __shared__ float sred[256], qred[256];

    int t = threadIdx.x;
    int row0 = blockIdx.x * 128;
    int col0 = blockIdx.y * 64;

    if (t < 128) {
        int r = row0 + t;
        s_b[t] = (r < Nv) ? batch_idx[r] : -1;
    }

#pragma unroll
    for (int e = t; e < 1024; e += 256) {
        int r = e >> 3, q = e & 7;
        int row = row0 + r;
        uint4 vh = make_uint4(0u, 0u, 0u, 0u);
        uint4 vl = vh;
        if (row < Nv) {
            vh = *(const uint4*)&g_x2h[(size_t)row * 64 + q * 8];
            vl = *(const uint4*)&g_x2l[(size_t)row * 64 + q * 8];
        }
        *(uint4*)&Ah[r * 72 + q * 8] = vh;
        *(uint4*)&Al[r * 72 + q * 8] = vl;
    }
#pragma unroll
    for (int e4 = t; e4 < 512; e4 += 256) {
        int n = e4 >> 3, q = e4 & 7;
        *(uint4*)&Wh[n * 72 + q * 8] = *(const uint4*)&g_W3h[(col0 + n) * 64 + q * 8];
    }
    __syncthreads();

    int wid = t >> 5, lane = t & 31;
    int mb = (wid >> 1) * 32;
    int nb = (wid & 1) * 32;

    float acc[2][4][4];
#pragma unroll
    for (int i = 0; i < 2; i++)
#pragma unroll
        for (int j = 0; j < 4; j++)
#pragma unroll
            for (int q = 0; q < 4; q++) acc[i][j][q] = 0.f;

    int a_row = lane & 15;
    int a_koff = (lane >> 4) << 3;
    int b_n = (lane & 7) + ((lane >> 4) << 3);
    int b_koff = ((lane >> 3) & 1) << 3;

#pragma unroll
    for (int term = 0; term < 2; term++) {
        const __half* A = term ? Al : Ah;
#pragma unroll
        for (int ks = 0; ks < 4; ks++) {
            int k0 = ks * 16;
            uint32_t af0[4], af1[4], bf0[4], bf1[4];
            ldsm_x4(af0, smem_u32(&A[(mb + a_row) * 72 + k0 + a_koff]));
            ldsm_x4(af1, smem_u32(&A[(mb + 16 + a_row) * 72 + k0 + a_koff]));
            ldsm_x4(bf0, smem_u32(&Wh[(nb + b_n) * 72 + k0 + b_koff]));
            ldsm_x4(bf1, smem_u32(&Wh[(nb + 16 + b_n) * 72 + k0 + b_koff]));
            mma_f16(acc[0][0], af0, bf0[0], bf0[1]);
            mma_f16(acc[0][1], af0, bf0[2], bf0[3]);
            mma_f16(acc[0][2], af0, bf1[0], bf1[1]);
            mma_f16(acc[0][3], af0, bf1[2], bf1[3]);
            mma_f16(acc[1][0], af1, bf0[0], bf0[1]);
            mma_f16(acc[1][1], af1, bf0[2], bf0[3]);
            mma_f16(acc[1][2], af1, bf1[0], bf1[1]);
            mma_f16(acc[1][3], af1, bf1[2], bf1[3]);
        }
    }

    __syncthreads();
    int g = lane >> 2, tg = lane & 3;
#pragma unroll
    for (int mi = 0; mi < 2; mi++) {
        int row = mb + mi * 16 + g;
#pragma unroll
        for (int nj = 0; nj < 4; nj++) {
            int col = nb + nj * 8 + tg * 2;
            *(float2*)&Cs[row * 68 + col]       = make_float2(acc[mi][nj][0], acc[mi][nj][1]);
            *(float2*)&Cs[(row + 8) * 68 + col] = make_float2(acc[mi][nj][2], acc[mi][nj][3]);
        }
    }
    __syncthreads();

#pragma unroll
    for (int e4 = t; e4 < 2048; e4 += 256) {
        int r = e4 >> 4, cg = e4 & 15;
        int row = row0 + r;
        if (row < Nv)
            *(float4*)&out[(size_t)row * 256 + col0 + cg * 4] = *(const float4*)&Cs[r * 68 + cg * 4];
    }

    int b0 = s_b[0];
    bool fast;
    if (s_b[127] == b0) fast = true;
    else if (row0 + 127 >= Nv) {
        int lastr = Nv - 1 - row0;
        fast = (lastr >= 0 && s_b[lastr] == b0);
    } else fast = false;

    if (fast) {
        int col = t & 63, rg = t >> 6;
        float s = 0.f, q = 0.f;
#pragma unroll 8
        for (int r = rg * 32; r < rg * 32 + 32; r++) {
            float v = Cs[r * 68 + col];
            s += v; q += v * v;
        }
        sred[rg * 64 + col] = s;
        qred[rg * 64 + col] = q;
        __syncthreads();
        if (t < 64) {
            float v = sred[t] + sred[64 + t] + sred[128 + t] + sred[192 + t];
            atomicAdd(&gsum[b0 * 256 + col0 + t], v);
        } else if (t < 128) {
            int c = t - 64;
            float v = qred[c] + qred[64 + c] + qred[128 + c] + qred[192 + c];
            atomicAdd(&gsq[b0 * 256 + col0 + c], v);
        }
    } else {
        for (int e = t; e < 8192; e += 256) {
            int r = e >> 6, c = e & 63;
            if (row0 + r < Nv) {
                float v = Cs[r * 68 + c];
                int b = s_b[r];
                atomicAdd(&gsum[b * 256 + col0 + c], v);
                atomicAdd(&gsq[b * 256 + col0 + c], v * v);
            }
        }
    }
}

// ---------------- final: normalize3 + residual + relu ------------------------
__global__ void final_kernel(float* __restrict__ y,
                             const float* __restrict__ feats,
                             const int* __restrict__ batch_idx,
                             const float* __restrict__ mean,
                             const float* __restrict__ inv) {
    const int C4 = 64;
    long long total = (long long)Nv * C4;
    long long i = (long long)blockIdx.x * blockDim.x + threadIdx.x;
    long long stride = (long long)gridDim.x * blockDim.x;
    for (; i < total; i += stride) {
        int row = (int)(i / C4);
        int cg = (int)(i % C4);
        int b = batch_idx[row];
        float4 v = ((float4*)y)[i];
        float4 f = ((const float4*)feats)[i];
        float4 m = ((const float4*)mean)[b * C4 + cg];
        float4 sv = ((const float4*)inv)[b * C4 + cg];
        v.x = fmaxf((v.x - m.x) * sv.x + f.x, 0.f);
        v.y = fmaxf((v.y - m.y) * sv.y + f.y, 0.f);
        v.z = fmaxf((v.z - m.z) * sv.z + f.z, 0.f);
        v.w = fmaxf((v.w - m.w) * sv.w + f.w, 0.f);
        ((float4*)y)[i] = v;
    }
}

// ---------------- launch -----------------------------------------------------
extern "C" void kernel_launch(void* const* d_in, const int* in_sizes, int n_in,
                              void* d_out, int out_size) {
    const float* feats     = (const float*)d_in[0];
    const float* W1        = (const float*)d_in[1];
    const float* W2        = (const float*)d_in[2];
    const float* W3        = (const float*)d_in[3];
    const int*   in_idx    = (const int*)d_in[4];
    const int*   out_idx   = (const int*)d_in[5];
    const int*   batch_idx = (const int*)d_in[6];
    float* out = (float*)d_out;

    float *p_x1, *p_x2, *p_sum1, *p_sq1, *p_sum2, *p_sq2, *p_sum3, *p_sq3;
    __half *p_x1h, *p_x1l, *p_x2h, *p_x2l;
    cudaGetSymbolAddress((void**)&p_x1, g_x1);
    cudaGetSymbolAddress((void**)&p_x2, g_x2);
    cudaGetSymbolAddress((void**)&p_x1h, g_x1h);
    cudaGetSymbolAddress((void**)&p_x1l, g_x1l);
    cudaGetSymbolAddress((void**)&p_x2h, g_x2h);
    cudaGetSymbolAddress((void**)&p_x2l, g_x2l);
    cudaGetSymbolAddress((void**)&p_sum1, g_sum1);
    cudaGetSymbolAddress((void**)&p_sq1, g_sq1);
    cudaGetSymbolAddress((void**)&p_sum2, g_sum2);
    cudaGetSymbolAddress((void**)&p_sq2, g_sq2);
    cudaGetSymbolAddress((void**)&p_sum3, g_sum3);
    cudaGetSymbolAddress((void**)&p_sq3, g_sq3);

    const int smem1 = 55296;
    const int smem2 = 82944;   // 2 A stages (73728) + Wh (9216)
    const int smem3 = 46080;   // Ah + Al + Wh
    cudaFuncSetAttribute(conv1_mma_kernel, cudaFuncAttributeMaxDynamicSharedMemorySize, smem1);
    cudaFuncSetAttribute(conv2_mma_kernel, cudaFuncAttributeMaxDynamicSharedMemorySize, smem2);
    cudaFuncSetAttribute(conv3_mma_kernel, cudaFuncAttributeMaxDynamicSharedMemorySize, smem3);

    zero_kernel<<<2048, 256>>>();
    count_kernel<<<391, 256>>>(batch_idx);
    wsplit_kernel<<<(16384 + Kk * 4096 + 16384 + 255) / 256, 256>>>(W1, W2, W3);

    // conv1 (tensor) + fused stats1
    conv1_mma_kernel<<<(Nv + 127) / 128, 256, smem1>>>(feats, batch_idx, p_sum1, p_sq1);
    finalize_kernel<<<1, 256>>>(p_sum1, p_sq1, 64);

    // norm1 + relu + fp16 hi/lo split
    norm_split_kernel<<<4096, 256>>>(p_x1, p_x1h, p_x1l, batch_idx, p_sum1, p_sq1);

    // conv2: persistent pipelined fp16 2-term, register-direct scatter
    conv2_mma_kernel<<<C2_GRID, 256, smem2>>>(in_idx, out_idx);
    stats2_kernel<<<(Nv + 127) / 128, 256>>>(p_x2, batch_idx, p_sum2, p_sq2);
    finalize_kernel<<<1, 256>>>(p_sum2, p_sq2, 64);

    // norm2 + relu + fp16 hi/lo split
    norm_split_kernel<<<4096, 256>>>(p_x2, p_x2h, p_x2l, batch_idx, p_sum2, p_sq2);

    // conv3 (tensor fp16 2-term) + fused stats3
    dim3 g3((Nv + 127) / 128, 4);
    conv3_mma_kernel<<<g3, 256, smem3>>>(out, batch_idx, p_sum3, p_sq3);
    finalize_kernel<<<4, 256>>>(p_sum3, p_sq3, 256);

    final_kernel<<<16384, 256>>>(out, feats, batch_idx, p_sum3, p_sq3);
}

// round 10
// speedup vs baseline: 3.0042x; 1.1318x over previous
#include <cuda_runtime.h>
#include <cuda_bf16.h>
#include <cuda_fp16.h>
#include <cstdint>

#define Nv   200000
#define Kk   27
#define Mm   100000
#define Bb   4
#define EPSf 1e-5f
#define C2_TPK 782                 // tiles per k offset (ceil(Mm/128))
#define C2_TILES (Kk * C2_TPK)     // 21114
#define C2_GRID 296                // 2 CTAs/SM * 148

// ---------------- scratch (device globals — no runtime allocation) ----------
__device__ float g_x1[(size_t)Nv * 64];          // conv1 out (raw, pre-norm)
__device__ float g_x2[(size_t)Nv * 64];          // conv2 accum (raw, pre-norm)
__device__ __half g_x1h[(size_t)Nv * 64];        // normalized x1, fp16
__device__ __half g_x2h[(size_t)Nv * 64];        // normalized x2, fp16
__device__ __nv_bfloat16 g_W1h[64 * 256],  g_W1l[64 * 256];    // [d][c] col-major
__device__ __half        g_W2h[Kk * 4096];                     // [k][d][c] fp16
__device__ __half        g_W3h[256 * 64];                      // [n][c] fp16
__device__ float g_sum1[Bb * 64], g_sq1[Bb * 64];
__device__ float g_sum2[Bb * 64], g_sq2[Bb * 64];
__device__ float g_sum3[Bb * 256], g_sq3[Bb * 256];
__device__ int   g_cnt[Bb];

// ---------------- helpers -----------------------------------------------------
__device__ __forceinline__ void red_v2(float* p, float a, float b) {
    asm volatile("red.global.add.v2.f32 [%0], {%1,%2};"
                 :: "l"(p), "f"(a), "f"(b) : "memory");
}
__device__ __forceinline__ uint32_t smem_u32(const void* p) {
    uint32_t a;
    asm("{ .reg .u64 t; cvta.to.shared.u64 t, %1; cvt.u32.u64 %0, t; }"
        : "=r"(a) : "l"(p));
    return a;
}
__device__ __forceinline__ void ldsm_x4(uint32_t* r, uint32_t addr) {
    asm volatile("ldmatrix.sync.aligned.m8n8.x4.shared.b16 {%0,%1,%2,%3}, [%4];"
        : "=r"(r[0]), "=r"(r[1]), "=r"(r[2]), "=r"(r[3]) : "r"(addr));
}
__device__ __forceinline__ void mma_bf16(float* c, const uint32_t* a,
                                         uint32_t b0, uint32_t b1) {
    asm volatile("mma.sync.aligned.m16n8k16.row.col.f32.bf16.bf16.f32 "
        "{%0,%1,%2,%3}, {%4,%5,%6,%7}, {%8,%9}, {%0,%1,%2,%3};"
        : "+f"(c[0]), "+f"(c[1]), "+f"(c[2]), "+f"(c[3])
        : "r"(a[0]), "r"(a[1]), "r"(a[2]), "r"(a[3]), "r"(b0), "r"(b1));
}
__device__ __forceinline__ void mma_f16(float* c, const uint32_t* a,
                                        uint32_t b0, uint32_t b1) {
    asm volatile("mma.sync.aligned.m16n8k16.row.col.f32.f16.f16.f32 "
        "{%0,%1,%2,%3}, {%4,%5,%6,%7}, {%8,%9}, {%0,%1,%2,%3};"
        : "+f"(c[0]), "+f"(c[1]), "+f"(c[2]), "+f"(c[3])
        : "r"(a[0]), "r"(a[1]), "r"(a[2]), "r"(a[3]), "r"(b0), "r"(b1));
}
__device__ __forceinline__ void split_bf(float a, __nv_bfloat16& h, __nv_bfloat16& l) {
    h = __float2bfloat16(a);
    l = __float2bfloat16(a - __bfloat162float(h));
}
__device__ __forceinline__ void cp16(uint32_t dst, const void* src, int sz) {
    asm volatile("cp.async.cg.shared.global [%0], [%1], 16, %2;"
                 :: "r"(dst), "l"(src), "r"(sz));
}
#define CP_COMMIT() asm volatile("cp.async.commit_group;" ::: "memory")
#define CP_WAIT0()  asm volatile("cp.async.wait_group 0;" ::: "memory")

// ---------------- zero scratch ----------------------------------------------
__global__ void zero_kernel() {
    long long i = (long long)blockIdx.x * blockDim.x + threadIdx.x;
    long long stride = (long long)gridDim.x * blockDim.x;
    const long long total4 = (long long)Nv * 16;
    float4* p = reinterpret_cast<float4*>(g_x2);
    float4 z = make_float4(0.f, 0.f, 0.f, 0.f);
    for (long long j = i; j < total4; j += stride) p[j] = z;
    if (i < Bb * 64)  { g_sum1[i] = 0.f; g_sq1[i] = 0.f; g_sum2[i] = 0.f; g_sq2[i] = 0.f; }
    if (i < Bb * 256) { g_sum3[i] = 0.f; g_sq3[i] = 0.f; }
    if (i < Bb) g_cnt[i] = 0;
}

// ---------------- per-batch counts ------------------------------------------
__global__ void count_kernel(const int* __restrict__ batch_idx) {
    __shared__ int s[Bb];
    if (threadIdx.x < Bb) s[threadIdx.x] = 0;
    __syncthreads();
    int i = blockIdx.x * blockDim.x + threadIdx.x;
    int stride = gridDim.x * blockDim.x;
    for (int j = i; j < Nv; j += stride) atomicAdd(&s[batch_idx[j]], 1);
    __syncthreads();
    if (threadIdx.x < Bb) atomicAdd(&g_cnt[threadIdx.x], s[threadIdx.x]);
}

// ---------------- weight pre-split -------------------------------------------
__global__ void wsplit_kernel(const float* __restrict__ W1,
                              const float* __restrict__ W2,
                              const float* __restrict__ W3) {
    int i = blockIdx.x * blockDim.x + threadIdx.x;
    if (i < 16384) {
        int d = i >> 8, c = i & 255;
        __nv_bfloat16 h, l;
        split_bf(W1[c * 64 + d], h, l);
        g_W1h[i] = h; g_W1l[i] = l;
    } else if (i < 16384 + Kk * 4096) {
        int j = i - 16384;
        int kk = j >> 12, r = j & 4095;
        int d = r >> 6, c = r & 63;
        g_W2h[j] = __float2half_rn(W2[kk * 4096 + c * 64 + d]);
    } else if (i < 16384 + Kk * 4096 + 16384) {
        int j = i - 16384 - Kk * 4096;
        int n = j >> 6, c = j & 63;
        g_W3h[j] = __float2half_rn(W3[c * 256 + n]);
    }
}

// ---------------- conv1: mma.sync bf16 3-term, fused stats1 -------------------
__global__ void __launch_bounds__(256, 2) conv1_mma_kernel(const float* __restrict__ feats,
                                                           const int* __restrict__ batch_idx,
                                                           float* __restrict__ gsum,
                                                           float* __restrict__ gsq) {
    extern __shared__ __align__(16) char sm1[];
    __nv_bfloat16* Ah = (__nv_bfloat16*)sm1;
    __nv_bfloat16* Al = (__nv_bfloat16*)(sm1 + 18432);
    __nv_bfloat16* Wh = (__nv_bfloat16*)(sm1 + 36864);
    __nv_bfloat16* Wl = (__nv_bfloat16*)(sm1 + 46080);
    float* Cs = (float*)sm1;
    __shared__ int s_b[128];
    __shared__ float sred[256], qred[256];

    int t = threadIdx.x;
    int row0 = blockIdx.x * 128;
    if (t < 128) {
        int r = row0 + t;
        s_b[t] = (r < Nv) ? batch_idx[r] : -1;
    }

    int wid = t >> 5, lane = t & 31;
    int mb = (wid >> 1) * 32;
    int nb = (wid & 1) * 32;
    int a_row = lane & 15;
    int a_koff = (lane >> 4) << 3;
    int b_n = (lane & 7) + ((lane >> 4) << 3);
    int b_koff = ((lane >> 3) & 1) << 3;

    float acc[2][4][4];
#pragma unroll
    for (int i = 0; i < 2; i++)
#pragma unroll
        for (int j = 0; j < 4; j++)
#pragma unroll
            for (int q = 0; q < 4; q++) acc[i][j][q] = 0.f;

    for (int k0 = 0; k0 < 256; k0 += 64) {
        __syncthreads();
#pragma unroll
        for (int e4 = t; e4 < 2048; e4 += 256) {
            int r = e4 >> 4, cg = e4 & 15;
            int row = row0 + r;
            float4 v = make_float4(0.f, 0.f, 0.f, 0.f);
            if (row < Nv) v = *(const float4*)&feats[(size_t)row * 256 + k0 + cg * 4];
            __nv_bfloat16 h0, h1, h2, h3, l0, l1, l2, l3;
            split_bf(v.x, h0, l0); split_bf(v.y, h1, l1);
            split_bf(v.z, h2, l2); split_bf(v.w, h3, l3);
            __nv_bfloat162* ph = (__nv_bfloat162*)&Ah[r * 72 + cg * 4];
            __nv_bfloat162* pl = (__nv_bfloat162*)&Al[r * 72 + cg * 4];
            ph[0] = __nv_bfloat162(h0, h1); ph[1] = __nv_bfloat162(h2, h3);
            pl[0] = __nv_bfloat162(l0, l1); pl[1] = __nv_bfloat162(l2, l3);
        }
#pragma unroll
        for (int e4 = t; e4 < 512; e4 += 256) {
            int d = e4 >> 3, q = e4 & 7;
            *(uint4*)&Wh[d * 72 + q * 8] = *(const uint4*)&g_W1h[d * 256 + k0 + q * 8];
            *(uint4*)&Wl[d * 72 + q * 8] = *(const uint4*)&g_W1l[d * 256 + k0 + q * 8];
        }
        __syncthreads();

#pragma unroll
        for (int term = 0; term < 3; term++) {
            const __nv_bfloat16* A = (term == 1) ? Al : Ah;
            const __nv_bfloat16* W = (term == 2) ? Wl : Wh;
#pragma unroll
            for (int ks = 0; ks < 4; ks++) {
                int kc = ks * 16;
                uint32_t af0[4], af1[4], bf0[4], bf1[4];
                ldsm_x4(af0, smem_u32(&A[(mb + a_row) * 72 + kc + a_koff]));
                ldsm_x4(af1, smem_u32(&A[(mb + 16 + a_row) * 72 + kc + a_koff]));
                ldsm_x4(bf0, smem_u32(&W[(nb + b_n) * 72 + kc + b_koff]));
                ldsm_x4(bf1, smem_u32(&W[(nb + 16 + b_n) * 72 + kc + b_koff]));
                mma_bf16(acc[0][0], af0, bf0[0], bf0[1]);
                mma_bf16(acc[0][1], af0, bf0[2], bf0[3]);
                mma_bf16(acc[0][2], af0, bf1[0], bf1[1]);
                mma_bf16(acc[0][3], af0, bf1[2], bf1[3]);
                mma_bf16(acc[1][0], af1, bf0[0], bf0[1]);
                mma_bf16(acc[1][1], af1, bf0[2], bf0[3]);
                mma_bf16(acc[1][2], af1, bf1[0], bf1[1]);
                mma_bf16(acc[1][3], af1, bf1[2], bf1[3]);
            }
        }
    }

    __syncthreads();
    int g = lane >> 2, tg = lane & 3;
#pragma unroll
    for (int mi = 0; mi < 2; mi++) {
        int row = mb + mi * 16 + g;
#pragma unroll
        for (int nj = 0; nj < 4; nj++) {
            int col = nb + nj * 8 + tg * 2;
            *(float2*)&Cs[row * 68 + col]       = make_float2(acc[mi][nj][0], acc[mi][nj][1]);
            *(float2*)&Cs[(row + 8) * 68 + col] = make_float2(acc[mi][nj][2], acc[mi][nj][3]);
        }
    }
    __syncthreads();

#pragma unroll
    for (int e4 = t; e4 < 2048; e4 += 256) {
        int r = e4 >> 4, cg = e4 & 15;
        int row = row0 + r;
        if (row < Nv)
            *(float4*)&g_x1[(size_t)row * 64 + cg * 4] = *(const float4*)&Cs[r * 68 + cg * 4];
    }

    int b0 = s_b[0];
    bool fast;
    if (s_b[127] == b0) fast = true;
    else if (row0 + 127 >= Nv) {
        int lastr = Nv - 1 - row0;
        fast = (lastr >= 0 && s_b[lastr] == b0);
    } else fast = false;

    if (fast) {
        int col = t & 63, rg = t >> 6;
        float s = 0.f, q = 0.f;
#pragma unroll 8
        for (int r = rg * 32; r < rg * 32 + 32; r++) {
            float v = Cs[r * 68 + col];
            s += v; q += v * v;
        }
        sred[rg * 64 + col] = s;
        qred[rg * 64 + col] = q;
        __syncthreads();
        if (t < 64) {
            float v = sred[t] + sred[64 + t] + sred[128 + t] + sred[192 + t];
            atomicAdd(&gsum[b0 * 64 + t], v);
        } else if (t < 128) {
            int c = t - 64;
            float v = qred[c] + qred[64 + c] + qred[128 + c] + qred[192 + c];
            atomicAdd(&gsq[b0 * 64 + c], v);
        }
    } else {
        for (int e = t; e < 8192; e += 256) {
            int r = e >> 6, c = e & 63;
            if (row0 + r < Nv) {
                float v = Cs[r * 68 + c];
                int b = s_b[r];
                atomicAdd(&gsum[b * 64 + c], v);
                atomicAdd(&gsq[b * 64 + c], v * v);
            }
        }
    }
}

// ---------------- finalize stats ---------------------------------------------
__global__ void finalize_kernel(float* sumArr, float* sqArr, int C) {
    int i = blockIdx.x * blockDim.x + threadIdx.x;
    if (i < Bb * C) {
        float cnt = (float)g_cnt[i / C];
        float mean = sumArr[i] / cnt;
        float var = sqArr[i] / cnt - mean * mean;
        sumArr[i] = mean;
        sqArr[i] = rsqrtf(fmaxf(var, 0.f) + EPSf);
    }
}

// ---------------- norm + relu -> fp16 (single) -------------------------------
__global__ void __launch_bounds__(256) norm_f16_kernel(const float* __restrict__ x,
                                                       __half* __restrict__ oh,
                                                       const int* __restrict__ batch_idx,
                                                       const float* __restrict__ mean,
                                                       const float* __restrict__ inv) {
    long long total = (long long)Nv * 16;
    long long i = (long long)blockIdx.x * blockDim.x + threadIdx.x;
    long long stride = (long long)gridDim.x * blockDim.x;
    for (; i < total; i += stride) {
        int row = (int)(i >> 4);
        int cg = (int)(i & 15);
        int b = batch_idx[row];
        float4 v = ((const float4*)x)[i];
        float4 m = ((const float4*)mean)[b * 16 + cg];
        float4 s = ((const float4*)inv)[b * 16 + cg];
        __half h0 = __float2half_rn(fmaxf((v.x - m.x) * s.x, 0.f));
        __half h1 = __float2half_rn(fmaxf((v.y - m.y) * s.y, 0.f));
        __half h2 = __float2half_rn(fmaxf((v.z - m.z) * s.z, 0.f));
        __half h3 = __float2half_rn(fmaxf((v.w - m.w) * s.w, 0.f));
        __half2* ph = (__half2*)&oh[(size_t)row * 64 + cg * 4];
        ph[0] = __half2(h0, h1);
        ph[1] = __half2(h2, h3);
    }
}

// ---------------- conv2: persistent pipelined fp16 single-A gather-GEMM-scatter
// grid 296 (2/SM); 2-stage cp.async pipeline; register-direct red.v2 scatter
// smem: stage s A at s*18432; Wh at 36864 (9216) -> 46080 total
__global__ void __launch_bounds__(256, 2) conv2_mma_kernel(const int* __restrict__ in_idx,
                                                           const int* __restrict__ out_idx) {
    extern __shared__ __align__(16) char sm2[];
    __half* Wh = (__half*)(sm2 + 36864);
    __shared__ int s_in[2][128], s_out[2][128];

    int t = threadIdx.x;
    int per = (C2_TILES + C2_GRID - 1) / C2_GRID;   // 72
    int start = blockIdx.x * per;
    int end = min(start + per, C2_TILES);
    if (start >= end) return;

    int wid = t >> 5, lane = t & 31;
    int mb = (wid >> 1) * 32;
    int nb = (wid & 1) * 32;
    int a_row = lane & 15;
    int a_koff = (lane >> 4) << 3;
    int b_n = (lane & 7) + ((lane >> 4) << 3);
    int b_koff = ((lane >> 3) & 1) << 3;
    int g = lane >> 2, tg = lane & 3;

    int cur_k = -1;

    {
        int k0 = start / C2_TPK;
        int m0 = (start % C2_TPK) * 128;
        if (t < 128) {
            int p = m0 + t;
            bool v = (p < Mm);
            s_in[0][t]  = v ? in_idx[(size_t)k0 * Mm + p] : -1;
            s_out[0][t] = v ? out_idx[(size_t)k0 * Mm + p] : -1;
        }
    }
    __syncthreads();
    {
        char* base = sm2;   // stage 0
#pragma unroll
        for (int e = t; e < 1024; e += 256) {
            int r = e >> 3, q = e & 7;
            int src = s_in[0][r];
            bool v = (src >= 0);
            size_t off = (size_t)(v ? src : 0) * 64 + q * 8;
            cp16(smem_u32(base + r * 144 + q * 16), g_x1h + off, v ? 16 : 0);
        }
        CP_COMMIT();
    }

    for (int i = start; i < end; i++) {
        int s = (i - start) & 1;
        int ns = s ^ 1;
        int k = i / C2_TPK;

        int ri = -1, ro = -1;
        bool have_next = (i + 1 < end);
        if (have_next && t < 128) {
            int nk = (i + 1) / C2_TPK;
            int m0 = ((i + 1) % C2_TPK) * 128;
            int p = m0 + t;
            if (p < Mm) {
                ri = in_idx[(size_t)nk * Mm + p];
                ro = out_idx[(size_t)nk * Mm + p];
            }
        }

        CP_WAIT0();
        __syncthreads();   // stage s ready; everyone past prev iter's scatter

        if (have_next && t < 128) { s_in[ns][t] = ri; s_out[ns][t] = ro; }
        if (k != cur_k) {
            const __half* Wkh = g_W2h + (size_t)k * 4096;
#pragma unroll
            for (int e4 = t; e4 < 512; e4 += 256) {
                int d = e4 >> 3, q = e4 & 7;
                *(uint4*)&Wh[d * 72 + q * 8] = *(const uint4*)&Wkh[d * 64 + q * 8];
            }
            cur_k = k;
        }
        __syncthreads();

        if (have_next) {
            char* base = sm2 + ns * 18432;
#pragma unroll
            for (int e = t; e < 1024; e += 256) {
                int r = e >> 3, q = e & 7;
                int src = s_in[ns][r];
                bool v = (src >= 0);
                size_t off = (size_t)(v ? src : 0) * 64 + q * 8;
                cp16(smem_u32(base + r * 144 + q * 16), g_x1h + off, v ? 16 : 0);
            }
            CP_COMMIT();
        }

        const __half* A = (const __half*)(sm2 + s * 18432);

        float acc[2][4][4];
#pragma unroll
        for (int ii = 0; ii < 2; ii++)
#pragma unroll
            for (int j = 0; j < 4; j++)
#pragma unroll
                for (int q = 0; q < 4; q++) acc[ii][j][q] = 0.f;

#pragma unroll
        for (int ks = 0; ks < 4; ks++) {
            int k0 = ks * 16;
            uint32_t af0[4], af1[4], bf0[4], bf1[4];
            ldsm_x4(af0, smem_u32(&A[(mb + a_row) * 72 + k0 + a_koff]));
            ldsm_x4(af1, smem_u32(&A[(mb + 16 + a_row) * 72 + k0 + a_koff]));
            ldsm_x4(bf0, smem_u32(&Wh[(nb + b_n) * 72 + k0 + b_koff]));
            ldsm_x4(bf1, smem_u32(&Wh[(nb + 16 + b_n) * 72 + k0 + b_koff]));
            mma_f16(acc[0][0], af0, bf0[0], bf0[1]);
            mma_f16(acc[0][1], af0, bf0[2], bf0[3]);
            mma_f16(acc[0][2], af0, bf1[0], bf1[1]);
            mma_f16(acc[0][3], af0, bf1[2], bf1[3]);
            mma_f16(acc[1][0], af1, bf0[0], bf0[1]);
            mma_f16(acc[1][1], af1, bf0[2], bf0[3]);
            mma_f16(acc[1][2], af1, bf1[0], bf1[1]);
            mma_f16(acc[1][3], af1, bf1[2], bf1[3]);
        }

        // scatter directly from registers
#pragma unroll
        for (int mi = 0; mi < 2; mi++) {
            int row = mb + mi * 16 + g;
            int dst0 = s_out[s][row];
            int dst1 = s_out[s][row + 8];
#pragma unroll
            for (int nj = 0; nj < 4; nj++) {
                int col = nb + nj * 8 + tg * 2;
                if (dst0 >= 0)
                    red_v2(g_x2 + (size_t)dst0 * 64 + col, acc[mi][nj][0], acc[mi][nj][1]);
                if (dst1 >= 0)
                    red_v2(g_x2 + (size_t)dst1 * 64 + col, acc[mi][nj][2], acc[mi][nj][3]);
            }
        }
    }
}

// ---------------- stats2 ------------------------------------------------------
__global__ void __launch_bounds__(256) stats2_kernel(const float* __restrict__ x,
                                                     const int* __restrict__ batch_idx,
                                                     float* __restrict__ gsum,
                                                     float* __restrict__ gsq) {
    __shared__ float sm[2048];
    int t = threadIdx.x;
    int r0 = blockIdx.x * 128;
    int r1 = min(r0 + 128, Nv);
    int cg = t & 15, rg = t >> 4;
    int b0 = batch_idx[r0], b1 = batch_idx[r1 - 1];

    if (b0 == b1) {
        float4 s = make_float4(0.f, 0.f, 0.f, 0.f);
        float4 q = make_float4(0.f, 0.f, 0.f, 0.f);
#pragma unroll 4
        for (int r = r0 + rg; r < r1; r += 16) {
            float4 v = *(const float4*)&x[(size_t)r * 64 + cg * 4];
            s.x += v.x; s.y += v.y; s.z += v.z; s.w += v.w;
            q.x += v.x * v.x; q.y += v.y * v.y; q.z += v.z * v.z; q.w += v.w * v.w;
        }
        *(float4*)&sm[rg * 64 + cg * 4]        = s;
        *(float4*)&sm[1024 + rg * 64 + cg * 4] = q;
        __syncthreads();
        if (t < 64) {
            float v = 0.f;
#pragma unroll
            for (int u = 0; u < 16; u++) v += sm[u * 64 + t];
            atomicAdd(&gsum[b0 * 64 + t], v);
        } else if (t < 128) {
            int c = t - 64;
            float v = 0.f;
#pragma unroll
            for (int u = 0; u < 16; u++) v += sm[1024 + u * 64 + c];
            atomicAdd(&gsq[b0 * 64 + c], v);
        }
    } else {
        for (int i = t; i < 512; i += 256) sm[i] = 0.f;
        __syncthreads();
        for (int r = r0 + rg; r < r1; r += 16) {
            int b = batch_idx[r];
            float4 v = *(const float4*)&x[(size_t)r * 64 + cg * 4];
            atomicAdd(&sm[b * 64 + cg * 4], v.x);
            atomicAdd(&sm[b * 64 + cg * 4 + 1], v.y);
            atomicAdd(&sm[b * 64 + cg * 4 + 2], v.z);
            atomicAdd(&sm[b * 64 + cg * 4 + 3], v.w);
            atomicAdd(&sm[256 + b * 64 + cg * 4], v.x * v.x);
            atomicAdd(&sm[256 + b * 64 + cg * 4 + 1], v.y * v.y);
            atomicAdd(&sm[256 + b * 64 + cg * 4 + 2], v.z * v.z);
            atomicAdd(&sm[256 + b * 64 + cg * 4 + 3], v.w * v.w);
        }
        __syncthreads();
        if (t < 256) {
            if (sm[t] != 0.f)       atomicAdd(&gsum[t], sm[t]);
            if (sm[256 + t] != 0.f) atomicAdd(&gsq[t], sm[256 + t]);
        }
    }
}

// ---------------- conv3: mma.sync fp16 single-A -> out + stats3 ---------------
// grid (1563, 4); smem: Ah 18432 + Wh 9216 = 27648; Cs overlay 34816 -> 36864
__global__ void __launch_bounds__(256, 2) conv3_mma_kernel(float* __restrict__ out,
                                                           const int* __restrict__ batch_idx,
                                                           float* __restrict__ gsum,
                                                           float* __restrict__ gsq) {
    extern __shared__ __align__(16) char sm3[];
    __half* Ah = (__half*)sm3;
    __half* Wh = (__half*)(sm3 + 18432);
    float* Cs = (float*)sm3;                // overlay 128x68 f32 = 34816
    __shared__ int s_b[128];
    __shared__ float sred[256], qred[256];

    int t = threadIdx.x;
    int row0 = blockIdx.x * 128;
    int col0 = blockIdx.y * 64;

    if (t < 128) {
        int r = row0 + t;
        s_b[t] = (r < Nv) ? batch_idx[r] : -1;
    }

#pragma unroll
    for (int e = t; e < 1024; e += 256) {
        int r = e >> 3, q = e & 7;
        int row = row0 + r;
        uint4 vh = make_uint4(0u, 0u, 0u, 0u);
        if (row < Nv) vh = *(const uint4*)&g_x2h[(size_t)row * 64 + q * 8];
        *(uint4*)&Ah[r * 72 + q * 8] = vh;
    }
#pragma unroll
    for (int e4 = t; e4 < 512; e4 += 256) {
        int n = e4 >> 3, q = e4 & 7;
        *(uint4*)&Wh[n * 72 + q * 8] = *(const uint4*)&g_W3h[(col0 + n) * 64 + q * 8];
    }
    __syncthreads();

    int wid = t >> 5, lane = t & 31;
    int mb = (wid >> 1) * 32;
    int nb = (wid & 1) * 32;

    float acc[2][4][4];
#pragma unroll
    for (int i = 0; i < 2; i++)
#pragma unroll
        for (int j = 0; j < 4; j++)
#pragma unroll
            for (int q = 0; q < 4; q++) acc[i][j][q] = 0.f;

    int a_row = lane & 15;
    int a_koff = (lane >> 4) << 3;
    int b_n = (lane & 7) + ((lane >> 4) << 3);
    int b_koff = ((lane >> 3) & 1) << 3;

#pragma unroll
    for (int ks = 0; ks < 4; ks++) {
        int k0 = ks * 16;
        uint32_t af0[4], af1[4], bf0[4], bf1[4];
        ldsm_x4(af0, smem_u32(&Ah[(mb + a_row) * 72 + k0 + a_koff]));
        ldsm_x4(af1, smem_u32(&Ah[(mb + 16 + a_row) * 72 + k0 + a_koff]));
        ldsm_x4(bf0, smem_u32(&Wh[(nb + b_n) * 72 + k0 + b_koff]));
        ldsm_x4(bf1, smem_u32(&Wh[(nb + 16 + b_n) * 72 + k0 + b_koff]));
        mma_f16(acc[0][0], af0, bf0[0], bf0[1]);
        mma_f16(acc[0][1], af0, bf0[2], bf0[3]);
        mma_f16(acc[0][2], af0, bf1[0], bf1[1]);
        mma_f16(acc[0][3], af0, bf1[2], bf1[3]);
        mma_f16(acc[1][0], af1, bf0[0], bf0[1]);
        mma_f16(acc[1][1], af1, bf0[2], bf0[3]);
        mma_f16(acc[1][2], af1, bf1[0], bf1[1]);
        mma_f16(acc[1][3], af1, bf1[2], bf1[3]);
    }

    __syncthreads();
    int g = lane >> 2, tg = lane & 3;
#pragma unroll
    for (int mi = 0; mi < 2; mi++) {
        int row = mb + mi * 16 + g;
#pragma unroll
        for (int nj = 0; nj < 4; nj++) {
            int col = nb + nj * 8 + tg * 2;
            *(float2*)&Cs[row * 68 + col]       = make_float2(acc[mi][nj][0], acc[mi][nj][1]);
            *(float2*)&Cs[(row + 8) * 68 + col] = make_float2(acc[mi][nj][2], acc[mi][nj][3]);
        }
    }
    __syncthreads();

#pragma unroll
    for (int e4 = t; e4 < 2048; e4 += 256) {
        int r = e4 >> 4, cg = e4 & 15;
        int row = row0 + r;
        if (row < Nv)
            *(float4*)&out[(size_t)row * 256 + col0 + cg * 4] = *(const float4*)&Cs[r * 68 + cg * 4];
    }

    int b0 = s_b[0];
    bool fast;
    if (s_b[127] == b0) fast = true;
    else if (row0 + 127 >= Nv) {
        int lastr = Nv - 1 - row0;
        fast = (lastr >= 0 && s_b[lastr] == b0);
    } else fast = false;

    if (fast) {
        int col = t & 63, rg = t >> 6;
        float s = 0.f, q = 0.f;
#pragma unroll 8
        for (int r = rg * 32; r < rg * 32 + 32; r++) {
            float v = Cs[r * 68 + col];
            s += v; q += v * v;
        }
        sred[rg * 64 + col] = s;
        qred[rg * 64 + col] = q;
        __syncthreads();
        if (t < 64) {
            float v = sred[t] + sred[64 + t] + sred[128 + t] + sred[192 + t];
            atomicAdd(&gsum[b0 * 256 + col0 + t], v);
        } else if (t < 128) {
            int c = t - 64;
            float v = qred[c] + qred[64 + c] + qred[128 + c] + qred[192 + c];
            atomicAdd(&gsq[b0 * 256 + col0 + c], v);
        }
    } else {
        for (int e = t; e < 8192; e += 256) {
            int r = e >> 6, c = e & 63;
            if (row0 + r < Nv) {
                float v = Cs[r * 68 + c];
                int b = s_b[r];
                atomicAdd(&gsum[b * 256 + col0 + c], v);
                atomicAdd(&gsq[b * 256 + col0 + c], v * v);
            }
        }
    }
}

// ---------------- final: normalize3 + residual + relu ------------------------
__global__ void final_kernel(float* __restrict__ y,
                             const float* __restrict__ feats,
                             const int* __restrict__ batch_idx,
                             const float* __restrict__ mean,
                             const float* __restrict__ inv) {
    const int C4 = 64;
    long long total = (long long)Nv * C4;
    long long i = (long long)blockIdx.x * blockDim.x + threadIdx.x;
    long long stride = (long long)gridDim.x * blockDim.x;
    for (; i < total; i += stride) {
        int row = (int)(i / C4);
        int cg = (int)(i % C4);
        int b = batch_idx[row];
        float4 v = ((float4*)y)[i];
        float4 f = ((const float4*)feats)[i];
        float4 m = ((const float4*)mean)[b * C4 + cg];
        float4 sv = ((const float4*)inv)[b * C4 + cg];
        v.x = fmaxf((v.x - m.x) * sv.x + f.x, 0.f);
        v.y = fmaxf((v.y - m.y) * sv.y + f.y, 0.f);
        v.z = fmaxf((v.z - m.z) * sv.z + f.z, 0.f);
        v.w = fmaxf((v.w - m.w) * sv.w + f.w, 0.f);
        ((float4*)y)[i] = v;
    }
}

// ---------------- launch -----------------------------------------------------
extern "C" void kernel_launch(void* const* d_in, const int* in_sizes, int n_in,
                              void* d_out, int out_size) {
    const float* feats     = (const float*)d_in[0];
    const float* W1        = (const float*)d_in[1];
    const float* W2        = (const float*)d_in[2];
    const float* W3        = (const float*)d_in[3];
    const int*   in_idx    = (const int*)d_in[4];
    const int*   out_idx   = (const int*)d_in[5];
    const int*   batch_idx = (const int*)d_in[6];
    float* out = (float*)d_out;

    float *p_x1, *p_x2, *p_sum1, *p_sq1, *p_sum2, *p_sq2, *p_sum3, *p_sq3;
    __half *p_x1h, *p_x2h;
    cudaGetSymbolAddress((void**)&p_x1, g_x1);
    cudaGetSymbolAddress((void**)&p_x2, g_x2);
    cudaGetSymbolAddress((void**)&p_x1h, g_x1h);
    cudaGetSymbolAddress((void**)&p_x2h, g_x2h);
    cudaGetSymbolAddress((void**)&p_sum1, g_sum1);
    cudaGetSymbolAddress((void**)&p_sq1, g_sq1);
    cudaGetSymbolAddress((void**)&p_sum2, g_sum2);
    cudaGetSymbolAddress((void**)&p_sq2, g_sq2);
    cudaGetSymbolAddress((void**)&p_sum3, g_sum3);
    cudaGetSymbolAddress((void**)&p_sq3, g_sq3);

    const int smem1 = 55296;
    const int smem2 = 46080;   // 2 A stages (36864) + Wh (9216)
    const int smem3 = 36864;   // Ah + Wh (27648), Cs overlay 34816
    cudaFuncSetAttribute(conv1_mma_kernel, cudaFuncAttributeMaxDynamicSharedMemorySize, smem1);
    cudaFuncSetAttribute(conv2_mma_kernel, cudaFuncAttributeMaxDynamicSharedMemorySize, smem2);
    cudaFuncSetAttribute(conv3_mma_kernel, cudaFuncAttributeMaxDynamicSharedMemorySize, smem3);

    zero_kernel<<<2048, 256>>>();
    count_kernel<<<391, 256>>>(batch_idx);
    wsplit_kernel<<<(16384 + Kk * 4096 + 16384 + 255) / 256, 256>>>(W1, W2, W3);

    // conv1 (tensor bf16 3-term) + fused stats1
    conv1_mma_kernel<<<(Nv + 127) / 128, 256, smem1>>>(feats, batch_idx, p_sum1, p_sq1);
    finalize_kernel<<<1, 256>>>(p_sum1, p_sq1, 64);

    // norm1 + relu -> fp16
    norm_f16_kernel<<<4096, 256>>>(p_x1, p_x1h, batch_idx, p_sum1, p_sq1);

    // conv2: persistent pipelined fp16 single-A, register-direct scatter
    conv2_mma_kernel<<<C2_GRID, 256, smem2>>>(in_idx, out_idx);
    stats2_kernel<<<(Nv + 127) / 128, 256>>>(p_x2, batch_idx, p_sum2, p_sq2);
    finalize_kernel<<<1, 256>>>(p_sum2, p_sq2, 64);

    // norm2 + relu -> fp16
    norm_f16_kernel<<<4096, 256>>>(p_x2, p_x2h, batch_idx, p_sum2, p_sq2);

    // conv3 (tensor fp16 single-A) + fused stats3
    dim3 g3((Nv + 127) / 128, 4);
    conv3_mma_kernel<<<g3, 256, smem3>>>(out, batch_idx, p_sum3, p_sq3);
    finalize_kernel<<<4, 256>>>(p_sum3, p_sq3, 256);

    final_kernel<<<16384, 256>>>(out, feats, batch_idx, p_sum3, p_sq3);
}

// round 11
// speedup vs baseline: 3.2007x; 1.0654x over previous
#include <cuda_runtime.h>
#include <cuda_bf16.h>
#include <cuda_fp16.h>
#include <cstdint>

#define Nv   200000
#define Kk   27
#define Mm   100000
#define Bb   4
#define EPSf 1e-5f
#define C2_TPK 782                 // tiles per k offset (ceil(Mm/128))
#define C2_TILES (Kk * C2_TPK)     // 21114
#define C2_GRID 296                // 2 CTAs/SM * 148

// ---------------- scratch (device globals — no runtime allocation) ----------
__device__ float g_x1[(size_t)Nv * 64];          // conv1 out (raw, pre-norm)
__device__ float g_x2[(size_t)Nv * 64];          // conv2 accum (raw, pre-norm)
__device__ __half g_x1h[(size_t)Nv * 64];        // normalized x1, fp16
__device__ __half g_x2h[(size_t)Nv * 64];        // normalized x2, fp16
__device__ __half g_x3h[(size_t)Nv * 256];       // conv3 out (raw, fp16)
__device__ __nv_bfloat16 g_W1h[64 * 256],  g_W1l[64 * 256];    // [d][c] col-major
__device__ __half        g_W2h[Kk * 4096];                     // [k][d][c] fp16
__device__ __half        g_W3h[256 * 64];                      // [n][c] fp16
__device__ float g_sum1[Bb * 64], g_sq1[Bb * 64];
__device__ float g_sum2[Bb * 64], g_sq2[Bb * 64];
__device__ float g_sum3[Bb * 256], g_sq3[Bb * 256];
__device__ int   g_cnt[Bb];

// ---------------- helpers -----------------------------------------------------
__device__ __forceinline__ void red_v2(float* p, float a, float b) {
    asm volatile("red.global.add.v2.f32 [%0], {%1,%2};"
                 :: "l"(p), "f"(a), "f"(b) : "memory");
}
__device__ __forceinline__ uint32_t smem_u32(const void* p) {
    uint32_t a;
    asm("{ .reg .u64 t; cvta.to.shared.u64 t, %1; cvt.u32.u64 %0, t; }"
        : "=r"(a) : "l"(p));
    return a;
}
__device__ __forceinline__ void ldsm_x4(uint32_t* r, uint32_t addr) {
    asm volatile("ldmatrix.sync.aligned.m8n8.x4.shared.b16 {%0,%1,%2,%3}, [%4];"
        : "=r"(r[0]), "=r"(r[1]), "=r"(r[2]), "=r"(r[3]) : "r"(addr));
}
__device__ __forceinline__ void mma_bf16(float* c, const uint32_t* a,
                                         uint32_t b0, uint32_t b1) {
    asm volatile("mma.sync.aligned.m16n8k16.row.col.f32.bf16.bf16.f32 "
        "{%0,%1,%2,%3}, {%4,%5,%6,%7}, {%8,%9}, {%0,%1,%2,%3};"
        : "+f"(c[0]), "+f"(c[1]), "+f"(c[2]), "+f"(c[3])
        : "r"(a[0]), "r"(a[1]), "r"(a[2]), "r"(a[3]), "r"(b0), "r"(b1));
}
__device__ __forceinline__ void mma_f16(float* c, const uint32_t* a,
                                        uint32_t b0, uint32_t b1) {
    asm volatile("mma.sync.aligned.m16n8k16.row.col.f32.f16.f16.f32 "
        "{%0,%1,%2,%3}, {%4,%5,%6,%7}, {%8,%9}, {%0,%1,%2,%3};"
        : "+f"(c[0]), "+f"(c[1]), "+f"(c[2]), "+f"(c[3])
        : "r"(a[0]), "r"(a[1]), "r"(a[2]), "r"(a[3]), "r"(b0), "r"(b1));
}
__device__ __forceinline__ void split_bf(float a, __nv_bfloat16& h, __nv_bfloat16& l) {
    h = __float2bfloat16(a);
    l = __float2bfloat16(a - __bfloat162float(h));
}
__device__ __forceinline__ void cp16(uint32_t dst, const void* src, int sz) {
    asm volatile("cp.async.cg.shared.global [%0], [%1], 16, %2;"
                 :: "r"(dst), "l"(src), "r"(sz));
}
#define CP_COMMIT() asm volatile("cp.async.commit_group;" ::: "memory")
#define CP_WAIT0()  asm volatile("cp.async.wait_group 0;" ::: "memory")

// ---------------- small zero: stats accumulators + counts --------------------
__global__ void small_zero_kernel() {
    int t = threadIdx.x;
    for (int i = t; i < Bb * 64; i += 256) {
        g_sum1[i] = 0.f; g_sq1[i] = 0.f; g_sum2[i] = 0.f; g_sq2[i] = 0.f;
    }
    for (int i = t; i < Bb * 256; i += 256) { g_sum3[i] = 0.f; g_sq3[i] = 0.f; }
    if (t < Bb) g_cnt[t] = 0;
}

// ---------------- setup: zero g_x2 + weight split + batch counts -------------
__global__ void __launch_bounds__(256) setup_kernel(const float* __restrict__ W1,
                                                    const float* __restrict__ W2,
                                                    const float* __restrict__ W3,
                                                    const int* __restrict__ batch_idx) {
    __shared__ int s_cnt[Bb];
    int t = threadIdx.x;
    if (t < Bb) s_cnt[t] = 0;
    __syncthreads();

    long long gi = (long long)blockIdx.x * blockDim.x + t;
    long long stride = (long long)gridDim.x * blockDim.x;

    // zero g_x2 (grid-stride, float4)
    {
        const long long total4 = (long long)Nv * 16;
        float4* p = reinterpret_cast<float4*>(g_x2);
        float4 z = make_float4(0.f, 0.f, 0.f, 0.f);
        for (long long j = gi; j < total4; j += stride) p[j] = z;
    }
    // weight splits (single shot; grid covers range)
    {
        long long i = gi;
        if (i < 16384) {
            int d = (int)(i >> 8), c = (int)(i & 255);
            __nv_bfloat16 h, l;
            split_bf(W1[c * 64 + d], h, l);
            g_W1h[i] = h; g_W1l[i] = l;
        } else if (i < 16384 + Kk * 4096) {
            int j = (int)(i - 16384);
            int kk = j >> 12, r = j & 4095;
            int d = r >> 6, c = r & 63;
            g_W2h[j] = __float2half_rn(W2[kk * 4096 + c * 64 + d]);
        } else if (i < 16384 + Kk * 4096 + 16384) {
            int j = (int)(i - 16384 - Kk * 4096);
            int n = j >> 6, c = j & 63;
            g_W3h[j] = __float2half_rn(W3[c * 256 + n]);
        }
    }
    // batch counts (grid-stride + smem histogram)
    for (long long j = gi; j < Nv; j += stride) atomicAdd(&s_cnt[batch_idx[j]], 1);
    __syncthreads();
    if (t < Bb && s_cnt[t] != 0) atomicAdd(&g_cnt[t], s_cnt[t]);
}

// ---------------- conv1: mma.sync bf16 3-term, fused stats1 -------------------
__global__ void __launch_bounds__(256, 2) conv1_mma_kernel(const float* __restrict__ feats,
                                                           const int* __restrict__ batch_idx,
                                                           float* __restrict__ gsum,
                                                           float* __restrict__ gsq) {
    extern __shared__ __align__(16) char sm1[];
    __nv_bfloat16* Ah = (__nv_bfloat16*)sm1;
    __nv_bfloat16* Al = (__nv_bfloat16*)(sm1 + 18432);
    __nv_bfloat16* Wh = (__nv_bfloat16*)(sm1 + 36864);
    __nv_bfloat16* Wl = (__nv_bfloat16*)(sm1 + 46080);
    float* Cs = (float*)sm1;
    __shared__ int s_b[128];
    __shared__ float sred[256], qred[256];

    int t = threadIdx.x;
    int row0 = blockIdx.x * 128;
    if (t < 128) {
        int r = row0 + t;
        s_b[t] = (r < Nv) ? batch_idx[r] : -1;
    }

    int wid = t >> 5, lane = t & 31;
    int mb = (wid >> 1) * 32;
    int nb = (wid & 1) * 32;
    int a_row = lane & 15;
    int a_koff = (lane >> 4) << 3;
    int b_n = (lane & 7) + ((lane >> 4) << 3);
    int b_koff = ((lane >> 3) & 1) << 3;

    float acc[2][4][4];
#pragma unroll
    for (int i = 0; i < 2; i++)
#pragma unroll
        for (int j = 0; j < 4; j++)
#pragma unroll
            for (int q = 0; q < 4; q++) acc[i][j][q] = 0.f;

    for (int k0 = 0; k0 < 256; k0 += 64) {
        __syncthreads();
#pragma unroll
        for (int e4 = t; e4 < 2048; e4 += 256) {
            int r = e4 >> 4, cg = e4 & 15;
            int row = row0 + r;
            float4 v = make_float4(0.f, 0.f, 0.f, 0.f);
            if (row < Nv) v = *(const float4*)&feats[(size_t)row * 256 + k0 + cg * 4];
            __nv_bfloat16 h0, h1, h2, h3, l0, l1, l2, l3;
            split_bf(v.x, h0, l0); split_bf(v.y, h1, l1);
            split_bf(v.z, h2, l2); split_bf(v.w, h3, l3);
            __nv_bfloat162* ph = (__nv_bfloat162*)&Ah[r * 72 + cg * 4];
            __nv_bfloat162* pl = (__nv_bfloat162*)&Al[r * 72 + cg * 4];
            ph[0] = __nv_bfloat162(h0, h1); ph[1] = __nv_bfloat162(h2, h3);
            pl[0] = __nv_bfloat162(l0, l1); pl[1] = __nv_bfloat162(l2, l3);
        }
#pragma unroll
        for (int e4 = t; e4 < 512; e4 += 256) {
            int d = e4 >> 3, q = e4 & 7;
            *(uint4*)&Wh[d * 72 + q * 8] = *(const uint4*)&g_W1h[d * 256 + k0 + q * 8];
            *(uint4*)&Wl[d * 72 + q * 8] = *(const uint4*)&g_W1l[d * 256 + k0 + q * 8];
        }
        __syncthreads();

#pragma unroll
        for (int term = 0; term < 3; term++) {
            const __nv_bfloat16* A = (term == 1) ? Al : Ah;
            const __nv_bfloat16* W = (term == 2) ? Wl : Wh;
#pragma unroll
            for (int ks = 0; ks < 4; ks++) {
                int kc = ks * 16;
                uint32_t af0[4], af1[4], bf0[4], bf1[4];
                ldsm_x4(af0, smem_u32(&A[(mb + a_row) * 72 + kc + a_koff]));
                ldsm_x4(af1, smem_u32(&A[(mb + 16 + a_row) * 72 + kc + a_koff]));
                ldsm_x4(bf0, smem_u32(&W[(nb + b_n) * 72 + kc + b_koff]));
                ldsm_x4(bf1, smem_u32(&W[(nb + 16 + b_n) * 72 + kc + b_koff]));
                mma_bf16(acc[0][0], af0, bf0[0], bf0[1]);
                mma_bf16(acc[0][1], af0, bf0[2], bf0[3]);
                mma_bf16(acc[0][2], af0, bf1[0], bf1[1]);
                mma_bf16(acc[0][3], af0, bf1[2], bf1[3]);
                mma_bf16(acc[1][0], af1, bf0[0], bf0[1]);
                mma_bf16(acc[1][1], af1, bf0[2], bf0[3]);
                mma_bf16(acc[1][2], af1, bf1[0], bf1[1]);
                mma_bf16(acc[1][3], af1, bf1[2], bf1[3]);
            }
        }
    }

    __syncthreads();
    int g = lane >> 2, tg = lane & 3;
#pragma unroll
    for (int mi = 0; mi < 2; mi++) {
        int row = mb + mi * 16 + g;
#pragma unroll
        for (int nj = 0; nj < 4; nj++) {
            int col = nb + nj * 8 + tg * 2;
            *(float2*)&Cs[row * 68 + col]       = make_float2(acc[mi][nj][0], acc[mi][nj][1]);
            *(float2*)&Cs[(row + 8) * 68 + col] = make_float2(acc[mi][nj][2], acc[mi][nj][3]);
        }
    }
    __syncthreads();

#pragma unroll
    for (int e4 = t; e4 < 2048; e4 += 256) {
        int r = e4 >> 4, cg = e4 & 15;
        int row = row0 + r;
        if (row < Nv)
            *(float4*)&g_x1[(size_t)row * 64 + cg * 4] = *(const float4*)&Cs[r * 68 + cg * 4];
    }

    int b0 = s_b[0];
    bool fast;
    if (s_b[127] == b0) fast = true;
    else if (row0 + 127 >= Nv) {
        int lastr = Nv - 1 - row0;
        fast = (lastr >= 0 && s_b[lastr] == b0);
    } else fast = false;

    if (fast) {
        int col = t & 63, rg = t >> 6;
        float s = 0.f, q = 0.f;
#pragma unroll 8
        for (int r = rg * 32; r < rg * 32 + 32; r++) {
            float v = Cs[r * 68 + col];
            s += v; q += v * v;
        }
        sred[rg * 64 + col] = s;
        qred[rg * 64 + col] = q;
        __syncthreads();
        if (t < 64) {
            float v = sred[t] + sred[64 + t] + sred[128 + t] + sred[192 + t];
            atomicAdd(&gsum[b0 * 64 + t], v);
        } else if (t < 128) {
            int c = t - 64;
            float v = qred[c] + qred[64 + c] + qred[128 + c] + qred[192 + c];
            atomicAdd(&gsq[b0 * 64 + c], v);
        }
    } else {
        for (int e = t; e < 8192; e += 256) {
            int r = e >> 6, c = e & 63;
            if (row0 + r < Nv) {
                float v = Cs[r * 68 + c];
                int b = s_b[r];
                atomicAdd(&gsum[b * 64 + c], v);
                atomicAdd(&gsq[b * 64 + c], v * v);
            }
        }
    }
}

// ---------------- finalize stats ---------------------------------------------
__global__ void finalize_kernel(float* sumArr, float* sqArr, int C) {
    int i = blockIdx.x * blockDim.x + threadIdx.x;
    if (i < Bb * C) {
        float cnt = (float)g_cnt[i / C];
        float mean = sumArr[i] / cnt;
        float var = sqArr[i] / cnt - mean * mean;
        sumArr[i] = mean;
        sqArr[i] = rsqrtf(fmaxf(var, 0.f) + EPSf);
    }
}

// ---------------- norm + relu -> fp16 (single) -------------------------------
__global__ void __launch_bounds__(256) norm_f16_kernel(const float* __restrict__ x,
                                                       __half* __restrict__ oh,
                                                       const int* __restrict__ batch_idx,
                                                       const float* __restrict__ mean,
                                                       const float* __restrict__ inv) {
    long long total = (long long)Nv * 16;
    long long i = (long long)blockIdx.x * blockDim.x + threadIdx.x;
    long long stride = (long long)gridDim.x * blockDim.x;
    for (; i < total; i += stride) {
        int row = (int)(i >> 4);
        int cg = (int)(i & 15);
        int b = batch_idx[row];
        float4 v = ((const float4*)x)[i];
        float4 m = ((const float4*)mean)[b * 16 + cg];
        float4 s = ((const float4*)inv)[b * 16 + cg];
        __half h0 = __float2half_rn(fmaxf((v.x - m.x) * s.x, 0.f));
        __half h1 = __float2half_rn(fmaxf((v.y - m.y) * s.y, 0.f));
        __half h2 = __float2half_rn(fmaxf((v.z - m.z) * s.z, 0.f));
        __half h3 = __float2half_rn(fmaxf((v.w - m.w) * s.w, 0.f));
        __half2* ph = (__half2*)&oh[(size_t)row * 64 + cg * 4];
        ph[0] = __half2(h0, h1);
        ph[1] = __half2(h2, h3);
    }
}

// ---------------- conv2: persistent pipelined fp16 single-A gather-GEMM-scatter
__global__ void __launch_bounds__(256, 2) conv2_mma_kernel(const int* __restrict__ in_idx,
                                                           const int* __restrict__ out_idx) {
    extern __shared__ __align__(16) char sm2[];
    __half* Wh = (__half*)(sm2 + 36864);
    __shared__ int s_in[2][128], s_out[2][128];

    int t = threadIdx.x;
    int per = (C2_TILES + C2_GRID - 1) / C2_GRID;   // 72
    int start = blockIdx.x * per;
    int end = min(start + per, C2_TILES);
    if (start >= end) return;

    int wid = t >> 5, lane = t & 31;
    int mb = (wid >> 1) * 32;
    int nb = (wid & 1) * 32;
    int a_row = lane & 15;
    int a_koff = (lane >> 4) << 3;
    int b_n = (lane & 7) + ((lane >> 4) << 3);
    int b_koff = ((lane >> 3) & 1) << 3;
    int g = lane >> 2, tg = lane & 3;

    int cur_k = -1;

    {
        int k0 = start / C2_TPK;
        int m0 = (start % C2_TPK) * 128;
        if (t < 128) {
            int p = m0 + t;
            bool v = (p < Mm);
            s_in[0][t]  = v ? in_idx[(size_t)k0 * Mm + p] : -1;
            s_out[0][t] = v ? out_idx[(size_t)k0 * Mm + p] : -1;
        }
    }
    __syncthreads();
    {
        char* base = sm2;   // stage 0
#pragma unroll
        for (int e = t; e < 1024; e += 256) {
            int r = e >> 3, q = e & 7;
            int src = s_in[0][r];
            bool v = (src >= 0);
            size_t off = (size_t)(v ? src : 0) * 64 + q * 8;
            cp16(smem_u32(base + r * 144 + q * 16), g_x1h + off, v ? 16 : 0);
        }
        CP_COMMIT();
    }

    for (int i = start; i < end; i++) {
        int s = (i - start) & 1;
        int ns = s ^ 1;
        int k = i / C2_TPK;

        int ri = -1, ro = -1;
        bool have_next = (i + 1 < end);
        if (have_next && t < 128) {
            int nk = (i + 1) / C2_TPK;
            int m0 = ((i + 1) % C2_TPK) * 128;
            int p = m0 + t;
            if (p < Mm) {
                ri = in_idx[(size_t)nk * Mm + p];
                ro = out_idx[(size_t)nk * Mm + p];
            }
        }

        CP_WAIT0();
        __syncthreads();

        if (have_next && t < 128) { s_in[ns][t] = ri; s_out[ns][t] = ro; }
        if (k != cur_k) {
            const __half* Wkh = g_W2h + (size_t)k * 4096;
#pragma unroll
            for (int e4 = t; e4 < 512; e4 += 256) {
                int d = e4 >> 3, q = e4 & 7;
                *(uint4*)&Wh[d * 72 + q * 8] = *(const uint4*)&Wkh[d * 64 + q * 8];
            }
            cur_k = k;
        }
        __syncthreads();

        if (have_next) {
            char* base = sm2 + ns * 18432;
#pragma unroll
            for (int e = t; e < 1024; e += 256) {
                int r = e >> 3, q = e & 7;
                int src = s_in[ns][r];
                bool v = (src >= 0);
                size_t off = (size_t)(v ? src : 0) * 64 + q * 8;
                cp16(smem_u32(base + r * 144 + q * 16), g_x1h + off, v ? 16 : 0);
            }
            CP_COMMIT();
        }

        const __half* A = (const __half*)(sm2 + s * 18432);

        float acc[2][4][4];
#pragma unroll
        for (int ii = 0; ii < 2; ii++)
#pragma unroll
            for (int j = 0; j < 4; j++)
#pragma unroll
                for (int q = 0; q < 4; q++) acc[ii][j][q] = 0.f;

#pragma unroll
        for (int ks = 0; ks < 4; ks++) {
            int k0 = ks * 16;
            uint32_t af0[4], af1[4], bf0[4], bf1[4];
            ldsm_x4(af0, smem_u32(&A[(mb + a_row) * 72 + k0 + a_koff]));
            ldsm_x4(af1, smem_u32(&A[(mb + 16 + a_row) * 72 + k0 + a_koff]));
            ldsm_x4(bf0, smem_u32(&Wh[(nb + b_n) * 72 + k0 + b_koff]));
            ldsm_x4(bf1, smem_u32(&Wh[(nb + 16 + b_n) * 72 + k0 + b_koff]));
            mma_f16(acc[0][0], af0, bf0[0], bf0[1]);
            mma_f16(acc[0][1], af0, bf0[2], bf0[3]);
            mma_f16(acc[0][2], af0, bf1[0], bf1[1]);
            mma_f16(acc[0][3], af0, bf1[2], bf1[3]);
            mma_f16(acc[1][0], af1, bf0[0], bf0[1]);
            mma_f16(acc[1][1], af1, bf0[2], bf0[3]);
            mma_f16(acc[1][2], af1, bf1[0], bf1[1]);
            mma_f16(acc[1][3], af1, bf1[2], bf1[3]);
        }

        // scatter directly from registers
#pragma unroll
        for (int mi = 0; mi < 2; mi++) {
            int row = mb + mi * 16 + g;
            int dst0 = s_out[s][row];
            int dst1 = s_out[s][row + 8];
#pragma unroll
            for (int nj = 0; nj < 4; nj++) {
                int col = nb + nj * 8 + tg * 2;
                if (dst0 >= 0)
                    red_v2(g_x2 + (size_t)dst0 * 64 + col, acc[mi][nj][0], acc[mi][nj][1]);
                if (dst1 >= 0)
                    red_v2(g_x2 + (size_t)dst1 * 64 + col, acc[mi][nj][2], acc[mi][nj][3]);
            }
        }
    }
}

// ---------------- stats2 ------------------------------------------------------
__global__ void __launch_bounds__(256) stats2_kernel(const float* __restrict__ x,
                                                     const int* __restrict__ batch_idx,
                                                     float* __restrict__ gsum,
                                                     float* __restrict__ gsq) {
    __shared__ float sm[2048];
    int t = threadIdx.x;
    int r0 = blockIdx.x * 128;
    int r1 = min(r0 + 128, Nv);
    int cg = t & 15, rg = t >> 4;
    int b0 = batch_idx[r0], b1 = batch_idx[r1 - 1];

    if (b0 == b1) {
        float4 s = make_float4(0.f, 0.f, 0.f, 0.f);
        float4 q = make_float4(0.f, 0.f, 0.f, 0.f);
#pragma unroll 4
        for (int r = r0 + rg; r < r1; r += 16) {
            float4 v = *(const float4*)&x[(size_t)r * 64 + cg * 4];
            s.x += v.x; s.y += v.y; s.z += v.z; s.w += v.w;
            q.x += v.x * v.x; q.y += v.y * v.y; q.z += v.z * v.z; q.w += v.w * v.w;
        }
        *(float4*)&sm[rg * 64 + cg * 4]        = s;
        *(float4*)&sm[1024 + rg * 64 + cg * 4] = q;
        __syncthreads();
        if (t < 64) {
            float v = 0.f;
#pragma unroll
            for (int u = 0; u < 16; u++) v += sm[u * 64 + t];
            atomicAdd(&gsum[b0 * 64 + t], v);
        } else if (t < 128) {
            int c = t - 64;
            float v = 0.f;
#pragma unroll
            for (int u = 0; u < 16; u++) v += sm[1024 + u * 64 + c];
            atomicAdd(&gsq[b0 * 64 + c], v);
        }
    } else {
        for (int i = t; i < 512; i += 256) sm[i] = 0.f;
        __syncthreads();
        for (int r = r0 + rg; r < r1; r += 16) {
            int b = batch_idx[r];
            float4 v = *(const float4*)&x[(size_t)r * 64 + cg * 4];
            atomicAdd(&sm[b * 64 + cg * 4], v.x);
            atomicAdd(&sm[b * 64 + cg * 4 + 1], v.y);
            atomicAdd(&sm[b * 64 + cg * 4 + 2], v.z);
            atomicAdd(&sm[b * 64 + cg * 4 + 3], v.w);
            atomicAdd(&sm[256 + b * 64 + cg * 4], v.x * v.x);
            atomicAdd(&sm[256 + b * 64 + cg * 4 + 1], v.y * v.y);
            atomicAdd(&sm[256 + b * 64 + cg * 4 + 2], v.z * v.z);
            atomicAdd(&sm[256 + b * 64 + cg * 4 + 3], v.w * v.w);
        }
        __syncthreads();
        if (t < 256) {
            if (sm[t] != 0.f)       atomicAdd(&gsum[t], sm[t]);
            if (sm[256 + t] != 0.f) atomicAdd(&gsq[t], sm[256 + t]);
        }
    }
}

// ---------------- conv3: mma.sync fp16 single-A -> fp16 x3 + stats3 ----------
__global__ void __launch_bounds__(256, 2) conv3_mma_kernel(const int* __restrict__ batch_idx,
                                                           float* __restrict__ gsum,
                                                           float* __restrict__ gsq) {
    extern __shared__ __align__(16) char sm3[];
    __half* Ah = (__half*)sm3;
    __half* Wh = (__half*)(sm3 + 18432);
    float* Cs = (float*)sm3;                // overlay 128x68 f32 = 34816
    __shared__ int s_b[128];
    __shared__ float sred[256], qred[256];

    int t = threadIdx.x;
    int row0 = blockIdx.x * 128;
    int col0 = blockIdx.y * 64;

    if (t < 128) {
        int r = row0 + t;
        s_b[t] = (r < Nv) ? batch_idx[r] : -1;
    }

#pragma unroll
    for (int e = t; e < 1024; e += 256) {
        int r = e >> 3, q = e & 7;
        int row = row0 + r;
        uint4 vh = make_uint4(0u, 0u, 0u, 0u);
        if (row < Nv) vh = *(const uint4*)&g_x2h[(size_t)row * 64 + q * 8];
        *(uint4*)&Ah[r * 72 + q * 8] = vh;
    }
#pragma unroll
    for (int e4 = t; e4 < 512; e4 += 256) {
        int n = e4 >> 3, q = e4 & 7;
        *(uint4*)&Wh[n * 72 + q * 8] = *(const uint4*)&g_W3h[(col0 + n) * 64 + q * 8];
    }
    __syncthreads();

    int wid = t >> 5, lane = t & 31;
    int mb = (wid >> 1) * 32;
    int nb = (wid & 1) * 32;

    float acc[2][4][4];
#pragma unroll
    for (int i = 0; i < 2; i++)
#pragma unroll
        for (int j = 0; j < 4; j++)
#pragma unroll
            for (int q = 0; q < 4; q++) acc[i][j][q] = 0.f;

    int a_row = lane & 15;
    int a_koff = (lane >> 4) << 3;
    int b_n = (lane & 7) + ((lane >> 4) << 3);
    int b_koff = ((lane >> 3) & 1) << 3;

#pragma unroll
    for (int ks = 0; ks < 4; ks++) {
        int k0 = ks * 16;
        uint32_t af0[4], af1[4], bf0[4], bf1[4];
        ldsm_x4(af0, smem_u32(&Ah[(mb + a_row) * 72 + k0 + a_koff]));
        ldsm_x4(af1, smem_u32(&Ah[(mb + 16 + a_row) * 72 + k0 + a_koff]));
        ldsm_x4(bf0, smem_u32(&Wh[(nb + b_n) * 72 + k0 + b_koff]));
        ldsm_x4(bf1, smem_u32(&Wh[(nb + 16 + b_n) * 72 + k0 + b_koff]));
        mma_f16(acc[0][0], af0, bf0[0], bf0[1]);
        mma_f16(acc[0][1], af0, bf0[2], bf0[3]);
        mma_f16(acc[0][2], af0, bf1[0], bf1[1]);
        mma_f16(acc[0][3], af0, bf1[2], bf1[3]);
        mma_f16(acc[1][0], af1, bf0[0], bf0[1]);
        mma_f16(acc[1][1], af1, bf0[2], bf0[3]);
        mma_f16(acc[1][2], af1, bf1[0], bf1[1]);
        mma_f16(acc[1][3], af1, bf1[2], bf1[3]);
    }

    __syncthreads();
    int g = lane >> 2, tg = lane & 3;
#pragma unroll
    for (int mi = 0; mi < 2; mi++) {
        int row = mb + mi * 16 + g;
#pragma unroll
        for (int nj = 0; nj < 4; nj++) {
            int col = nb + nj * 8 + tg * 2;
            *(float2*)&Cs[row * 68 + col]       = make_float2(acc[mi][nj][0], acc[mi][nj][1]);
            *(float2*)&Cs[(row + 8) * 68 + col] = make_float2(acc[mi][nj][2], acc[mi][nj][3]);
        }
    }
    __syncthreads();

    // write x3 slice as fp16
#pragma unroll
    for (int e4 = t; e4 < 2048; e4 += 256) {
        int r = e4 >> 4, cg = e4 & 15;
        int row = row0 + r;
        if (row < Nv) {
            float4 v = *(const float4*)&Cs[r * 68 + cg * 4];
            __half2 h0 = __floats2half2_rn(v.x, v.y);
            __half2 h1 = __floats2half2_rn(v.z, v.w);
            uint2 u;
            u.x = *(uint32_t*)&h0;
            u.y = *(uint32_t*)&h1;
            *(uint2*)&g_x3h[(size_t)row * 256 + col0 + cg * 4] = u;
        }
    }

    int b0 = s_b[0];
    bool fast;
    if (s_b[127] == b0) fast = true;
    else if (row0 + 127 >= Nv) {
        int lastr = Nv - 1 - row0;
        fast = (lastr >= 0 && s_b[lastr] == b0);
    } else fast = false;

    if (fast) {
        int col = t & 63, rg = t >> 6;
        float s = 0.f, q = 0.f;
#pragma unroll 8
        for (int r = rg * 32; r < rg * 32 + 32; r++) {
            float v = Cs[r * 68 + col];
            s += v; q += v * v;
        }
        sred[rg * 64 + col] = s;
        qred[rg * 64 + col] = q;
        __syncthreads();
        if (t < 64) {
            float v = sred[t] + sred[64 + t] + sred[128 + t] + sred[192 + t];
            atomicAdd(&gsum[b0 * 256 + col0 + t], v);
        } else if (t < 128) {
            int c = t - 64;
            float v = qred[c] + qred[64 + c] + qred[128 + c] + qred[192 + c];
            atomicAdd(&gsq[b0 * 256 + col0 + c], v);
        }
    } else {
        for (int e = t; e < 8192; e += 256) {
            int r = e >> 6, c = e & 63;
            if (row0 + r < Nv) {
                float v = Cs[r * 68 + c];
                int b = s_b[r];
                atomicAdd(&gsum[b * 256 + col0 + c], v);
                atomicAdd(&gsq[b * 256 + col0 + c], v * v);
            }
        }
    }
}

// ---------------- final: normalize3(fp16 x3) + residual + relu ---------------
__global__ void final_kernel(float* __restrict__ y,
                             const float* __restrict__ feats,
                             const int* __restrict__ batch_idx,
                             const float* __restrict__ mean,
                             const float* __restrict__ inv) {
    const int C4 = 64;
    long long total = (long long)Nv * C4;
    long long i = (long long)blockIdx.x * blockDim.x + threadIdx.x;
    long long stride = (long long)gridDim.x * blockDim.x;
    for (; i < total; i += stride) {
        int row = (int)(i / C4);
        int cg = (int)(i % C4);
        int b = batch_idx[row];
        uint2 u = *(const uint2*)&g_x3h[(size_t)row * 256 + cg * 4];
        __half2 p0 = *(__half2*)&u.x;
        __half2 p1 = *(__half2*)&u.y;
        float2 f0 = __half22float2(p0);
        float2 f1 = __half22float2(p1);
        float4 f = ((const float4*)feats)[i];
        float4 m = ((const float4*)mean)[b * C4 + cg];
        float4 sv = ((const float4*)inv)[b * C4 + cg];
        float4 v;
        v.x = fmaxf((f0.x - m.x) * sv.x + f.x, 0.f);
        v.y = fmaxf((f0.y - m.y) * sv.y + f.y, 0.f);
        v.z = fmaxf((f1.x - m.z) * sv.z + f.z, 0.f);
        v.w = fmaxf((f1.y - m.w) * sv.w + f.w, 0.f);
        ((float4*)y)[i] = v;
    }
}

// ---------------- launch -----------------------------------------------------
extern "C" void kernel_launch(void* const* d_in, const int* in_sizes, int n_in,
                              void* d_out, int out_size) {
    const float* feats     = (const float*)d_in[0];
    const float* W1        = (const float*)d_in[1];
    const float* W2        = (const float*)d_in[2];
    const float* W3        = (const float*)d_in[3];
    const int*   in_idx    = (const int*)d_in[4];
    const int*   out_idx   = (const int*)d_in[5];
    const int*   batch_idx = (const int*)d_in[6];
    float* out = (float*)d_out;

    float *p_x1, *p_x2, *p_sum1, *p_sq1, *p_sum2, *p_sq2, *p_sum3, *p_sq3;
    __half *p_x1h, *p_x2h;
    cudaGetSymbolAddress((void**)&p_x1, g_x1);
    cudaGetSymbolAddress((void**)&p_x2, g_x2);
    cudaGetSymbolAddress((void**)&p_x1h, g_x1h);
    cudaGetSymbolAddress((void**)&p_x2h, g_x2h);
    cudaGetSymbolAddress((void**)&p_sum1, g_sum1);
    cudaGetSymbolAddress((void**)&p_sq1, g_sq1);
    cudaGetSymbolAddress((void**)&p_sum2, g_sum2);
    cudaGetSymbolAddress((void**)&p_sq2, g_sq2);
    cudaGetSymbolAddress((void**)&p_sum3, g_sum3);
    cudaGetSymbolAddress((void**)&p_sq3, g_sq3);

    const int smem1 = 55296;
    const int smem2 = 46080;   // 2 A stages (36864) + Wh (9216)
    const int smem3 = 36864;   // Ah + Wh (27648), Cs overlay 34816
    cudaFuncSetAttribute(conv1_mma_kernel, cudaFuncAttributeMaxDynamicSharedMemorySize, smem1);
    cudaFuncSetAttribute(conv2_mma_kernel, cudaFuncAttributeMaxDynamicSharedMemorySize, smem2);
    cudaFuncSetAttribute(conv3_mma_kernel, cudaFuncAttributeMaxDynamicSharedMemorySize, smem3);

    small_zero_kernel<<<1, 256>>>();
    setup_kernel<<<2048, 256>>>(W1, W2, W3, batch_idx);

    // conv1 (tensor bf16 3-term) + fused stats1
    conv1_mma_kernel<<<(Nv + 127) / 128, 256, smem1>>>(feats, batch_idx, p_sum1, p_sq1);
    finalize_kernel<<<1, 256>>>(p_sum1, p_sq1, 64);

    // norm1 + relu -> fp16
    norm_f16_kernel<<<4096, 256>>>(p_x1, p_x1h, batch_idx, p_sum1, p_sq1);

    // conv2: persistent pipelined fp16 single-A, register-direct scatter
    conv2_mma_kernel<<<C2_GRID, 256, smem2>>>(in_idx, out_idx);
    stats2_kernel<<<(Nv + 127) / 128, 256>>>(p_x2, batch_idx, p_sum2, p_sq2);
    finalize_kernel<<<1, 256>>>(p_sum2, p_sq2, 64);

    // norm2 + relu -> fp16
    norm_f16_kernel<<<4096, 256>>>(p_x2, p_x2h, batch_idx, p_sum2, p_sq2);

    // conv3 (tensor fp16 single-A) -> fp16 x3 + fused stats3
    dim3 g3((Nv + 127) / 128, 4);
    conv3_mma_kernel<<<g3, 256, smem3>>>(batch_idx, p_sum3, p_sq3);
    finalize_kernel<<<4, 256>>>(p_sum3, p_sq3, 256);

    final_kernel<<<16384, 256>>>(out, feats, batch_idx, p_sum3, p_sq3);
}

// round 12
// speedup vs baseline: 3.3650x; 1.0514x over previous
#include <cuda_runtime.h>
#include <cuda_bf16.h>
#include <cuda_fp16.h>
#include <cstdint>

#define Nv   200000
#define Kk   27
#define Mm   100000
#define Bb   4
#define EPSf 1e-5f
#define C2_TPK 782                 // tiles per k offset (ceil(Mm/128))
#define C2_TILES (Kk * C2_TPK)     // 21114
#define C2_GRID 296                // 2 CTAs/SM * 148

// ---------------- scratch (device globals — no runtime allocation) ----------
__device__ float g_x1[(size_t)Nv * 64];          // conv1 out (raw, pre-norm)
__device__ float g_x2[(size_t)Nv * 64];          // conv2 accum (raw, pre-norm)
__device__ __half g_x1h[(size_t)Nv * 64];        // normalized x1, fp16
__device__ __half g_x2h[(size_t)Nv * 64];        // normalized x2, fp16
__device__ __half g_x3h[(size_t)Nv * 256];       // conv3 out (raw, fp16)
__device__ __half g_W1h[64 * 256];               // [d][c] col-major fp16
__device__ __half g_W2h[Kk * 4096];              // [k][d][c] fp16
__device__ __half g_W3h[256 * 64];               // [n][c] fp16
__device__ float g_sum1[Bb * 64], g_sq1[Bb * 64];
__device__ float g_sum2[Bb * 64], g_sq2[Bb * 64];
__device__ float g_sum3[Bb * 256], g_sq3[Bb * 256];
__device__ int   g_cnt[Bb];

// ---------------- helpers -----------------------------------------------------
__device__ __forceinline__ void red_v2(float* p, float a, float b) {
    asm volatile("red.global.add.v2.f32 [%0], {%1,%2};"
                 :: "l"(p), "f"(a), "f"(b) : "memory");
}
__device__ __forceinline__ uint32_t smem_u32(const void* p) {
    uint32_t a;
    asm("{ .reg .u64 t; cvta.to.shared.u64 t, %1; cvt.u32.u64 %0, t; }"
        : "=r"(a) : "l"(p));
    return a;
}
__device__ __forceinline__ void ldsm_x4(uint32_t* r, uint32_t addr) {
    asm volatile("ldmatrix.sync.aligned.m8n8.x4.shared.b16 {%0,%1,%2,%3}, [%4];"
        : "=r"(r[0]), "=r"(r[1]), "=r"(r[2]), "=r"(r[3]) : "r"(addr));
}
__device__ __forceinline__ void mma_f16(float* c, const uint32_t* a,
                                        uint32_t b0, uint32_t b1) {
    asm volatile("mma.sync.aligned.m16n8k16.row.col.f32.f16.f16.f32 "
        "{%0,%1,%2,%3}, {%4,%5,%6,%7}, {%8,%9}, {%0,%1,%2,%3};"
        : "+f"(c[0]), "+f"(c[1]), "+f"(c[2]), "+f"(c[3])
        : "r"(a[0]), "r"(a[1]), "r"(a[2]), "r"(a[3]), "r"(b0), "r"(b1));
}
__device__ __forceinline__ void cp16(uint32_t dst, const void* src, int sz) {
    asm volatile("cp.async.cg.shared.global [%0], [%1], 16, %2;"
                 :: "r"(dst), "l"(src), "r"(sz));
}
#define CP_COMMIT() asm volatile("cp.async.commit_group;" ::: "memory")
#define CP_WAIT0()  asm volatile("cp.async.wait_group 0;" ::: "memory")

// ---------------- small zero: stats accumulators + counts --------------------
__global__ void small_zero_kernel() {
    int t = threadIdx.x;
    for (int i = t; i < Bb * 64; i += 256) {
        g_sum1[i] = 0.f; g_sq1[i] = 0.f; g_sum2[i] = 0.f; g_sq2[i] = 0.f;
    }
    for (int i = t; i < Bb * 256; i += 256) { g_sum3[i] = 0.f; g_sq3[i] = 0.f; }
    if (t < Bb) g_cnt[t] = 0;
}

// ---------------- setup: zero g_x2 + weight fp16 + batch counts --------------
__global__ void __launch_bounds__(256) setup_kernel(const float* __restrict__ W1,
                                                    const float* __restrict__ W2,
                                                    const float* __restrict__ W3,
                                                    const int* __restrict__ batch_idx) {
    __shared__ int s_cnt[Bb];
    int t = threadIdx.x;
    if (t < Bb) s_cnt[t] = 0;
    __syncthreads();

    long long gi = (long long)blockIdx.x * blockDim.x + t;
    long long stride = (long long)gridDim.x * blockDim.x;

    {
        const long long total4 = (long long)Nv * 16;
        float4* p = reinterpret_cast<float4*>(g_x2);
        float4 z = make_float4(0.f, 0.f, 0.f, 0.f);
        for (long long j = gi; j < total4; j += stride) p[j] = z;
    }
    {
        long long i = gi;
        if (i < 16384) {
            int d = (int)(i >> 8), c = (int)(i & 255);
            g_W1h[i] = __float2half_rn(W1[c * 64 + d]);
        } else if (i < 16384 + Kk * 4096) {
            int j = (int)(i - 16384);
            int kk = j >> 12, r = j & 4095;
            int d = r >> 6, c = r & 63;
            g_W2h[j] = __float2half_rn(W2[kk * 4096 + c * 64 + d]);
        } else if (i < 16384 + Kk * 4096 + 16384) {
            int j = (int)(i - 16384 - Kk * 4096);
            int n = j >> 6, c = j & 63;
            g_W3h[j] = __float2half_rn(W3[c * 256 + n]);
        }
    }
    for (long long j = gi; j < Nv; j += stride) atomicAdd(&s_cnt[batch_idx[j]], 1);
    __syncthreads();
    if (t < Bb && s_cnt[t] != 0) atomicAdd(&g_cnt[t], s_cnt[t]);
}

// ---------------- conv1: mma.sync fp16 single-term, fused stats1 -------------
// grid 1563; 256 thr; tile M=128, N=64, K=256 (4 chunks)
// smem: Ah 128x72 fp16 (18432) + Wh 64x72 fp16 (9216) = 27648; Cs overlay 34816
__global__ void __launch_bounds__(256, 2) conv1_mma_kernel(const float* __restrict__ feats,
                                                           const int* __restrict__ batch_idx,
                                                           float* __restrict__ gsum,
                                                           float* __restrict__ gsq) {
    extern __shared__ __align__(16) char sm1[];
    __half* Ah = (__half*)sm1;
    __half* Wh = (__half*)(sm1 + 18432);
    float* Cs = (float*)sm1;
    __shared__ int s_b[128];
    __shared__ float sred[256], qred[256];

    int t = threadIdx.x;
    int row0 = blockIdx.x * 128;
    if (t < 128) {
        int r = row0 + t;
        s_b[t] = (r < Nv) ? batch_idx[r] : -1;
    }

    int wid = t >> 5, lane = t & 31;
    int mb = (wid >> 1) * 32;
    int nb = (wid & 1) * 32;
    int a_row = lane & 15;
    int a_koff = (lane >> 4) << 3;
    int b_n = (lane & 7) + ((lane >> 4) << 3);
    int b_koff = ((lane >> 3) & 1) << 3;

    float acc[2][4][4];
#pragma unroll
    for (int i = 0; i < 2; i++)
#pragma unroll
        for (int j = 0; j < 4; j++)
#pragma unroll
            for (int q = 0; q < 4; q++) acc[i][j][q] = 0.f;

    for (int k0 = 0; k0 < 256; k0 += 64) {
        __syncthreads();
#pragma unroll
        for (int e4 = t; e4 < 2048; e4 += 256) {
            int r = e4 >> 4, cg = e4 & 15;
            int row = row0 + r;
            float4 v = make_float4(0.f, 0.f, 0.f, 0.f);
            if (row < Nv) v = *(const float4*)&feats[(size_t)row * 256 + k0 + cg * 4];
            __half2 h0 = __floats2half2_rn(v.x, v.y);
            __half2 h1 = __floats2half2_rn(v.z, v.w);
            uint2 u;
            u.x = *(uint32_t*)&h0;
            u.y = *(uint32_t*)&h1;
            *(uint2*)&Ah[r * 72 + cg * 4] = u;
        }
#pragma unroll
        for (int e4 = t; e4 < 512; e4 += 256) {
            int d = e4 >> 3, q = e4 & 7;
            *(uint4*)&Wh[d * 72 + q * 8] = *(const uint4*)&g_W1h[d * 256 + k0 + q * 8];
        }
        __syncthreads();

#pragma unroll
        for (int ks = 0; ks < 4; ks++) {
            int kc = ks * 16;
            uint32_t af0[4], af1[4], bf0[4], bf1[4];
            ldsm_x4(af0, smem_u32(&Ah[(mb + a_row) * 72 + kc + a_koff]));
            ldsm_x4(af1, smem_u32(&Ah[(mb + 16 + a_row) * 72 + kc + a_koff]));
            ldsm_x4(bf0, smem_u32(&Wh[(nb + b_n) * 72 + kc + b_koff]));
            ldsm_x4(bf1, smem_u32(&Wh[(nb + 16 + b_n) * 72 + kc + b_koff]));
            mma_f16(acc[0][0], af0, bf0[0], bf0[1]);
            mma_f16(acc[0][1], af0, bf0[2], bf0[3]);
            mma_f16(acc[0][2], af0, bf1[0], bf1[1]);
            mma_f16(acc[0][3], af0, bf1[2], bf1[3]);
            mma_f16(acc[1][0], af1, bf0[0], bf0[1]);
            mma_f16(acc[1][1], af1, bf0[2], bf0[3]);
            mma_f16(acc[1][2], af1, bf1[0], bf1[1]);
            mma_f16(acc[1][3], af1, bf1[2], bf1[3]);
        }
    }

    __syncthreads();
    int g = lane >> 2, tg = lane & 3;
#pragma unroll
    for (int mi = 0; mi < 2; mi++) {
        int row = mb + mi * 16 + g;
#pragma unroll
        for (int nj = 0; nj < 4; nj++) {
            int col = nb + nj * 8 + tg * 2;
            *(float2*)&Cs[row * 68 + col]       = make_float2(acc[mi][nj][0], acc[mi][nj][1]);
            *(float2*)&Cs[(row + 8) * 68 + col] = make_float2(acc[mi][nj][2], acc[mi][nj][3]);
        }
    }
    __syncthreads();

#pragma unroll
    for (int e4 = t; e4 < 2048; e4 += 256) {
        int r = e4 >> 4, cg = e4 & 15;
        int row = row0 + r;
        if (row < Nv)
            *(float4*)&g_x1[(size_t)row * 64 + cg * 4] = *(const float4*)&Cs[r * 68 + cg * 4];
    }

    int b0 = s_b[0];
    bool fast;
    if (s_b[127] == b0) fast = true;
    else if (row0 + 127 >= Nv) {
        int lastr = Nv - 1 - row0;
        fast = (lastr >= 0 && s_b[lastr] == b0);
    } else fast = false;

    if (fast) {
        int col = t & 63, rg = t >> 6;
        float s = 0.f, q = 0.f;
#pragma unroll 8
        for (int r = rg * 32; r < rg * 32 + 32; r++) {
            float v = Cs[r * 68 + col];
            s += v; q += v * v;
        }
        sred[rg * 64 + col] = s;
        qred[rg * 64 + col] = q;
        __syncthreads();
        if (t < 64) {
            float v = sred[t] + sred[64 + t] + sred[128 + t] + sred[192 + t];
            atomicAdd(&gsum[b0 * 64 + t], v);
        } else if (t < 128) {
            int c = t - 64;
            float v = qred[c] + qred[64 + c] + qred[128 + c] + qred[192 + c];
            atomicAdd(&gsq[b0 * 64 + c], v);
        }
    } else {
        for (int e = t; e < 8192; e += 256) {
            int r = e >> 6, c = e & 63;
            if (row0 + r < Nv) {
                float v = Cs[r * 68 + c];
                int b = s_b[r];
                atomicAdd(&gsum[b * 64 + c], v);
                atomicAdd(&gsq[b * 64 + c], v * v);
            }
        }
    }
}

// ---------------- norm + relu -> fp16 (fused finalize) -----------------------
__global__ void __launch_bounds__(256) norm_f16_kernel(const float* __restrict__ x,
                                                       __half* __restrict__ oh,
                                                       const int* __restrict__ batch_idx,
                                                       const float* __restrict__ sumArr,
                                                       const float* __restrict__ sqArr) {
    __shared__ float s_m[Bb * 64], s_i[Bb * 64];
    int t = threadIdx.x;
    for (int i = t; i < Bb * 64; i += 256) {
        float cnt = (float)g_cnt[i >> 6];
        float mean = sumArr[i] / cnt;
        float var = sqArr[i] / cnt - mean * mean;
        s_m[i] = mean;
        s_i[i] = rsqrtf(fmaxf(var, 0.f) + EPSf);
    }
    __syncthreads();

    long long total = (long long)Nv * 16;
    long long i = (long long)blockIdx.x * blockDim.x + t;
    long long stride = (long long)gridDim.x * blockDim.x;
    for (; i < total; i += stride) {
        int row = (int)(i >> 4);
        int cg = (int)(i & 15);
        int b = batch_idx[row];
        float4 v = ((const float4*)x)[i];
        float4 m = ((const float4*)s_m)[b * 16 + cg];
        float4 s = ((const float4*)s_i)[b * 16 + cg];
        __half2 h0 = __floats2half2_rn(fmaxf((v.x - m.x) * s.x, 0.f),
                                       fmaxf((v.y - m.y) * s.y, 0.f));
        __half2 h1 = __floats2half2_rn(fmaxf((v.z - m.z) * s.z, 0.f),
                                       fmaxf((v.w - m.w) * s.w, 0.f));
        uint2 u;
        u.x = *(uint32_t*)&h0;
        u.y = *(uint32_t*)&h1;
        *(uint2*)&oh[(size_t)row * 64 + cg * 4] = u;
    }
}

// ---------------- conv2: persistent pipelined fp16 single-A gather-GEMM-scatter
__global__ void __launch_bounds__(256, 2) conv2_mma_kernel(const int* __restrict__ in_idx,
                                                           const int* __restrict__ out_idx) {
    extern __shared__ __align__(16) char sm2[];
    __half* Wh = (__half*)(sm2 + 36864);
    __shared__ int s_in[2][128], s_out[2][128];

    int t = threadIdx.x;
    int per = (C2_TILES + C2_GRID - 1) / C2_GRID;   // 72
    int start = blockIdx.x * per;
    int end = min(start + per, C2_TILES);
    if (start >= end) return;

    int wid = t >> 5, lane = t & 31;
    int mb = (wid >> 1) * 32;
    int nb = (wid & 1) * 32;
    int a_row = lane & 15;
    int a_koff = (lane >> 4) << 3;
    int b_n = (lane & 7) + ((lane >> 4) << 3);
    int b_koff = ((lane >> 3) & 1) << 3;
    int g = lane >> 2, tg = lane & 3;

    int cur_k = -1;

    {
        int k0 = start / C2_TPK;
        int m0 = (start % C2_TPK) * 128;
        if (t < 128) {
            int p = m0 + t;
            bool v = (p < Mm);
            s_in[0][t]  = v ? in_idx[(size_t)k0 * Mm + p] : -1;
            s_out[0][t] = v ? out_idx[(size_t)k0 * Mm + p] : -1;
        }
    }
    __syncthreads();
    {
        char* base = sm2;
#pragma unroll
        for (int e = t; e < 1024; e += 256) {
            int r = e >> 3, q = e & 7;
            int src = s_in[0][r];
            bool v = (src >= 0);
            size_t off = (size_t)(v ? src : 0) * 64 + q * 8;
            cp16(smem_u32(base + r * 144 + q * 16), g_x1h + off, v ? 16 : 0);
        }
        CP_COMMIT();
    }

    for (int i = start; i < end; i++) {
        int s = (i - start) & 1;
        int ns = s ^ 1;
        int k = i / C2_TPK;

        int ri = -1, ro = -1;
        bool have_next = (i + 1 < end);
        if (have_next && t < 128) {
            int nk = (i + 1) / C2_TPK;
            int m0 = ((i + 1) % C2_TPK) * 128;
            int p = m0 + t;
            if (p < Mm) {
                ri = in_idx[(size_t)nk * Mm + p];
                ro = out_idx[(size_t)nk * Mm + p];
            }
        }

        CP_WAIT0();
        __syncthreads();

        if (have_next && t < 128) { s_in[ns][t] = ri; s_out[ns][t] = ro; }
        if (k != cur_k) {
            const __half* Wkh = g_W2h + (size_t)k * 4096;
#pragma unroll
            for (int e4 = t; e4 < 512; e4 += 256) {
                int d = e4 >> 3, q = e4 & 7;
                *(uint4*)&Wh[d * 72 + q * 8] = *(const uint4*)&Wkh[d * 64 + q * 8];
            }
            cur_k = k;
        }
        __syncthreads();

        if (have_next) {
            char* base = sm2 + ns * 18432;
#pragma unroll
            for (int e = t; e < 1024; e += 256) {
                int r = e >> 3, q = e & 7;
                int src = s_in[ns][r];
                bool v = (src >= 0);
                size_t off = (size_t)(v ? src : 0) * 64 + q * 8;
                cp16(smem_u32(base + r * 144 + q * 16), g_x1h + off, v ? 16 : 0);
            }
            CP_COMMIT();
        }

        const __half* A = (const __half*)(sm2 + s * 18432);

        float acc[2][4][4];
#pragma unroll
        for (int ii = 0; ii < 2; ii++)
#pragma unroll
            for (int j = 0; j < 4; j++)
#pragma unroll
                for (int q = 0; q < 4; q++) acc[ii][j][q] = 0.f;

#pragma unroll
        for (int ks = 0; ks < 4; ks++) {
            int k0 = ks * 16;
            uint32_t af0[4], af1[4], bf0[4], bf1[4];
            ldsm_x4(af0, smem_u32(&A[(mb + a_row) * 72 + k0 + a_koff]));
            ldsm_x4(af1, smem_u32(&A[(mb + 16 + a_row) * 72 + k0 + a_koff]));
            ldsm_x4(bf0, smem_u32(&Wh[(nb + b_n) * 72 + k0 + b_koff]));
            ldsm_x4(bf1, smem_u32(&Wh[(nb + 16 + b_n) * 72 + k0 + b_koff]));
            mma_f16(acc[0][0], af0, bf0[0], bf0[1]);
            mma_f16(acc[0][1], af0, bf0[2], bf0[3]);
            mma_f16(acc[0][2], af0, bf1[0], bf1[1]);
            mma_f16(acc[0][3], af0, bf1[2], bf1[3]);
            mma_f16(acc[1][0], af1, bf0[0], bf0[1]);
            mma_f16(acc[1][1], af1, bf0[2], bf0[3]);
            mma_f16(acc[1][2], af1, bf1[0], bf1[1]);
            mma_f16(acc[1][3], af1, bf1[2], bf1[3]);
        }

#pragma unroll
        for (int mi = 0; mi < 2; mi++) {
            int row = mb + mi * 16 + g;
            int dst0 = s_out[s][row];
            int dst1 = s_out[s][row + 8];
#pragma unroll
            for (int nj = 0; nj < 4; nj++) {
                int col = nb + nj * 8 + tg * 2;
                if (dst0 >= 0)
                    red_v2(g_x2 + (size_t)dst0 * 64 + col, acc[mi][nj][0], acc[mi][nj][1]);
                if (dst1 >= 0)
                    red_v2(g_x2 + (size_t)dst1 * 64 + col, acc[mi][nj][2], acc[mi][nj][3]);
            }
        }
    }
}

// ---------------- stats2 ------------------------------------------------------
__global__ void __launch_bounds__(256) stats2_kernel(const float* __restrict__ x,
                                                     const int* __restrict__ batch_idx,
                                                     float* __restrict__ gsum,
                                                     float* __restrict__ gsq) {
    __shared__ float sm[2048];
    int t = threadIdx.x;
    int r0 = blockIdx.x * 128;
    int r1 = min(r0 + 128, Nv);
    int cg = t & 15, rg = t >> 4;
    int b0 = batch_idx[r0], b1 = batch_idx[r1 - 1];

    if (b0 == b1) {
        float4 s = make_float4(0.f, 0.f, 0.f, 0.f);
        float4 q = make_float4(0.f, 0.f, 0.f, 0.f);
#pragma unroll 4
        for (int r = r0 + rg; r < r1; r += 16) {
            float4 v = *(const float4*)&x[(size_t)r * 64 + cg * 4];
            s.x += v.x; s.y += v.y; s.z += v.z; s.w += v.w;
            q.x += v.x * v.x; q.y += v.y * v.y; q.z += v.z * v.z; q.w += v.w * v.w;
        }
        *(float4*)&sm[rg * 64 + cg * 4]        = s;
        *(float4*)&sm[1024 + rg * 64 + cg * 4] = q;
        __syncthreads();
        if (t < 64) {
            float v = 0.f;
#pragma unroll
            for (int u = 0; u < 16; u++) v += sm[u * 64 + t];
            atomicAdd(&gsum[b0 * 64 + t], v);
        } else if (t < 128) {
            int c = t - 64;
            float v = 0.f;
#pragma unroll
            for (int u = 0; u < 16; u++) v += sm[1024 + u * 64 + c];
            atomicAdd(&gsq[b0 * 64 + c], v);
        }
    } else {
        for (int i = t; i < 512; i += 256) sm[i] = 0.f;
        __syncthreads();
        for (int r = r0 + rg; r < r1; r += 16) {
            int b = batch_idx[r];
            float4 v = *(const float4*)&x[(size_t)r * 64 + cg * 4];
            atomicAdd(&sm[b * 64 + cg * 4], v.x);
            atomicAdd(&sm[b * 64 + cg * 4 + 1], v.y);
            atomicAdd(&sm[b * 64 + cg * 4 + 2], v.z);
            atomicAdd(&sm[b * 64 + cg * 4 + 3], v.w);
            atomicAdd(&sm[256 + b * 64 + cg * 4], v.x * v.x);
            atomicAdd(&sm[256 + b * 64 + cg * 4 + 1], v.y * v.y);
            atomicAdd(&sm[256 + b * 64 + cg * 4 + 2], v.z * v.z);
            atomicAdd(&sm[256 + b * 64 + cg * 4 + 3], v.w * v.w);
        }
        __syncthreads();
        if (t < 256) {
            if (sm[t] != 0.f)       atomicAdd(&gsum[t], sm[t]);
            if (sm[256 + t] != 0.f) atomicAdd(&gsq[t], sm[256 + t]);
        }
    }
}

// ---------------- conv3: mma.sync fp16 single-A -> fp16 x3 + stats3 ----------
__global__ void __launch_bounds__(256, 2) conv3_mma_kernel(const int* __restrict__ batch_idx,
                                                           float* __restrict__ gsum,
                                                           float* __restrict__ gsq) {
    extern __shared__ __align__(16) char sm3[];
    __half* Ah = (__half*)sm3;
    __half* Wh = (__half*)(sm3 + 18432);
    float* Cs = (float*)sm3;
    __shared__ int s_b[128];
    __shared__ float sred[256], qred[256];

    int t = threadIdx.x;
    int row0 = blockIdx.x * 128;
    int col0 = blockIdx.y * 64;

    if (t < 128) {
        int r = row0 + t;
        s_b[t] = (r < Nv) ? batch_idx[r] : -1;
    }

#pragma unroll
    for (int e = t; e < 1024; e += 256) {
        int r = e >> 3, q = e & 7;
        int row = row0 + r;
        uint4 vh = make_uint4(0u, 0u, 0u, 0u);
        if (row < Nv) vh = *(const uint4*)&g_x2h[(size_t)row * 64 + q * 8];
        *(uint4*)&Ah[r * 72 + q * 8] = vh;
    }
#pragma unroll
    for (int e4 = t; e4 < 512; e4 += 256) {
        int n = e4 >> 3, q = e4 & 7;
        *(uint4*)&Wh[n * 72 + q * 8] = *(const uint4*)&g_W3h[(col0 + n) * 64 + q * 8];
    }
    __syncthreads();

    int wid = t >> 5, lane = t & 31;
    int mb = (wid >> 1) * 32;
    int nb = (wid & 1) * 32;

    float acc[2][4][4];
#pragma unroll
    for (int i = 0; i < 2; i++)
#pragma unroll
        for (int j = 0; j < 4; j++)
#pragma unroll
            for (int q = 0; q < 4; q++) acc[i][j][q] = 0.f;

    int a_row = lane & 15;
    int a_koff = (lane >> 4) << 3;
    int b_n = (lane & 7) + ((lane >> 4) << 3);
    int b_koff = ((lane >> 3) & 1) << 3;

#pragma unroll
    for (int ks = 0; ks < 4; ks++) {
        int k0 = ks * 16;
        uint32_t af0[4], af1[4], bf0[4], bf1[4];
        ldsm_x4(af0, smem_u32(&Ah[(mb + a_row) * 72 + k0 + a_koff]));
        ldsm_x4(af1, smem_u32(&Ah[(mb + 16 + a_row) * 72 + k0 + a_koff]));
        ldsm_x4(bf0, smem_u32(&Wh[(nb + b_n) * 72 + k0 + b_koff]));
        ldsm_x4(bf1, smem_u32(&Wh[(nb + 16 + b_n) * 72 + k0 + b_koff]));
        mma_f16(acc[0][0], af0, bf0[0], bf0[1]);
        mma_f16(acc[0][1], af0, bf0[2], bf0[3]);
        mma_f16(acc[0][2], af0, bf1[0], bf1[1]);
        mma_f16(acc[0][3], af0, bf1[2], bf1[3]);
        mma_f16(acc[1][0], af1, bf0[0], bf0[1]);
        mma_f16(acc[1][1], af1, bf0[2], bf0[3]);
        mma_f16(acc[1][2], af1, bf1[0], bf1[1]);
        mma_f16(acc[1][3], af1, bf1[2], bf1[3]);
    }

    __syncthreads();
    int g = lane >> 2, tg = lane & 3;
#pragma unroll
    for (int mi = 0; mi < 2; mi++) {
        int row = mb + mi * 16 + g;
#pragma unroll
        for (int nj = 0; nj < 4; nj++) {
            int col = nb + nj * 8 + tg * 2;
            *(float2*)&Cs[row * 68 + col]       = make_float2(acc[mi][nj][0], acc[mi][nj][1]);
            *(float2*)&Cs[(row + 8) * 68 + col] = make_float2(acc[mi][nj][2], acc[mi][nj][3]);
        }
    }
    __syncthreads();

#pragma unroll
    for (int e4 = t; e4 < 2048; e4 += 256) {
        int r = e4 >> 4, cg = e4 & 15;
        int row = row0 + r;
        if (row < Nv) {
            float4 v = *(const float4*)&Cs[r * 68 + cg * 4];
            __half2 h0 = __floats2half2_rn(v.x, v.y);
            __half2 h1 = __floats2half2_rn(v.z, v.w);
            uint2 u;
            u.x = *(uint32_t*)&h0;
            u.y = *(uint32_t*)&h1;
            *(uint2*)&g_x3h[(size_t)row * 256 + col0 + cg * 4] = u;
        }
    }

    int b0 = s_b[0];
    bool fast;
    if (s_b[127] == b0) fast = true;
    else if (row0 + 127 >= Nv) {
        int lastr = Nv - 1 - row0;
        fast = (lastr >= 0 && s_b[lastr] == b0);
    } else fast = false;

    if (fast) {
        int col = t & 63, rg = t >> 6;
        float s = 0.f, q = 0.f;
#pragma unroll 8
        for (int r = rg * 32; r < rg * 32 + 32; r++) {
            float v = Cs[r * 68 + col];
            s += v; q += v * v;
        }
        sred[rg * 64 + col] = s;
        qred[rg * 64 + col] = q;
        __syncthreads();
        if (t < 64) {
            float v = sred[t] + sred[64 + t] + sred[128 + t] + sred[192 + t];
            atomicAdd(&gsum[b0 * 256 + col0 + t], v);
        } else if (t < 128) {
            int c = t - 64;
            float v = qred[c] + qred[64 + c] + qred[128 + c] + qred[192 + c];
            atomicAdd(&gsq[b0 * 256 + col0 + c], v);
        }
    } else {
        for (int e = t; e < 8192; e += 256) {
            int r = e >> 6, c = e & 63;
            if (row0 + r < Nv) {
                float v = Cs[r * 68 + c];
                int b = s_b[r];
                atomicAdd(&gsum[b * 256 + col0 + c], v);
                atomicAdd(&gsq[b * 256 + col0 + c], v * v);
            }
        }
    }
}

// ---------------- final: fused finalize3 + normalize + residual + relu -------
__global__ void __launch_bounds__(256) final_kernel(float* __restrict__ y,
                                                    const float* __restrict__ feats,
                                                    const int* __restrict__ batch_idx,
                                                    const float* __restrict__ sumArr,
                                                    const float* __restrict__ sqArr) {
    __shared__ float s_m[Bb * 256], s_i[Bb * 256];
    int t = threadIdx.x;
    for (int i = t; i < Bb * 256; i += 256) {
        float cnt = (float)g_cnt[i >> 8];
        float mean = sumArr[i] / cnt;
        float var = sqArr[i] / cnt - mean * mean;
        s_m[i] = mean;
        s_i[i] = rsqrtf(fmaxf(var, 0.f) + EPSf);
    }
    __syncthreads();

    const int C4 = 64;
    long long total = (long long)Nv * C4;
    long long i = (long long)blockIdx.x * blockDim.x + t;
    long long stride = (long long)gridDim.x * blockDim.x;
    for (; i < total; i += stride) {
        int row = (int)(i / C4);
        int cg = (int)(i % C4);
        int b = batch_idx[row];
        uint2 u = *(const uint2*)&g_x3h[(size_t)row * 256 + cg * 4];
        __half2 p0 = *(__half2*)&u.x;
        __half2 p1 = *(__half2*)&u.y;
        float2 f0 = __half22float2(p0);
        float2 f1 = __half22float2(p1);
        float4 f = ((const float4*)feats)[i];
        float4 m = ((const float4*)s_m)[b * C4 + cg];
        float4 sv = ((const float4*)s_i)[b * C4 + cg];
        float4 v;
        v.x = fmaxf((f0.x - m.x) * sv.x + f.x, 0.f);
        v.y = fmaxf((f0.y - m.y) * sv.y + f.y, 0.f);
        v.z = fmaxf((f1.x - m.z) * sv.z + f.z, 0.f);
        v.w = fmaxf((f1.y - m.w) * sv.w + f.w, 0.f);
        ((float4*)y)[i] = v;
    }
}

// ---------------- launch -----------------------------------------------------
extern "C" void kernel_launch(void* const* d_in, const int* in_sizes, int n_in,
                              void* d_out, int out_size) {
    const float* feats     = (const float*)d_in[0];
    const float* W1        = (const float*)d_in[1];
    const float* W2        = (const float*)d_in[2];
    const float* W3        = (const float*)d_in[3];
    const int*   in_idx    = (const int*)d_in[4];
    const int*   out_idx   = (const int*)d_in[5];
    const int*   batch_idx = (const int*)d_in[6];
    float* out = (float*)d_out;

    float *p_x1, *p_x2, *p_sum1, *p_sq1, *p_sum2, *p_sq2, *p_sum3, *p_sq3;
    __half *p_x1h, *p_x2h;
    cudaGetSymbolAddress((void**)&p_x1, g_x1);
    cudaGetSymbolAddress((void**)&p_x2, g_x2);
    cudaGetSymbolAddress((void**)&p_x1h, g_x1h);
    cudaGetSymbolAddress((void**)&p_x2h, g_x2h);
    cudaGetSymbolAddress((void**)&p_sum1, g_sum1);
    cudaGetSymbolAddress((void**)&p_sq1, g_sq1);
    cudaGetSymbolAddress((void**)&p_sum2, g_sum2);
    cudaGetSymbolAddress((void**)&p_sq2, g_sq2);
    cudaGetSymbolAddress((void**)&p_sum3, g_sum3);
    cudaGetSymbolAddress((void**)&p_sq3, g_sq3);

    const int smem1 = 36864;   // Ah + Wh (27648), Cs overlay 34816
    const int smem2 = 46080;   // 2 A stages (36864) + Wh (9216)
    const int smem3 = 36864;   // Ah + Wh (27648), Cs overlay 34816
    cudaFuncSetAttribute(conv1_mma_kernel, cudaFuncAttributeMaxDynamicSharedMemorySize, smem1);
    cudaFuncSetAttribute(conv2_mma_kernel, cudaFuncAttributeMaxDynamicSharedMemorySize, smem2);
    cudaFuncSetAttribute(conv3_mma_kernel, cudaFuncAttributeMaxDynamicSharedMemorySize, smem3);

    small_zero_kernel<<<1, 256>>>();
    setup_kernel<<<2048, 256>>>(W1, W2, W3, batch_idx);

    // conv1 (tensor fp16 single-term) + fused stats1
    conv1_mma_kernel<<<(Nv + 127) / 128, 256, smem1>>>(feats, batch_idx, p_sum1, p_sq1);

    // norm1 + relu -> fp16 (finalize fused)
    norm_f16_kernel<<<4096, 256>>>(p_x1, p_x1h, batch_idx, p_sum1, p_sq1);

    // conv2: persistent pipelined fp16 single-A, register-direct scatter
    conv2_mma_kernel<<<C2_GRID, 256, smem2>>>(in_idx, out_idx);
    stats2_kernel<<<(Nv + 127) / 128, 256>>>(p_x2, batch_idx, p_sum2, p_sq2);

    // norm2 + relu -> fp16 (finalize fused)
    norm_f16_kernel<<<4096, 256>>>(p_x2, p_x2h, batch_idx, p_sum2, p_sq2);

    // conv3 (tensor fp16 single-A) -> fp16 x3 + fused stats3
    dim3 g3((Nv + 127) / 128, 4);
    conv3_mma_kernel<<<g3, 256, smem3>>>(batch_idx, p_sum3, p_sq3);

    // finalize3 fused + normalize + residual + relu
    final_kernel<<<4096, 256>>>(out, feats, batch_idx, p_sum3, p_sq3);
}